// round 7
// baseline (speedup 1.0000x reference)
#include <cuda_runtime.h>
#include <cuda_bf16.h>
#include <cstdint>
#include <cstdio>

// ---------------------------------------------------------------------------
// EdgeVGAE encoder, algebraically collapsed:
//   S_l = segment_sum(leaky(edge_attr @ W1_l + b1_l), dst)   (edge pass, l=1,2)
//   h1  = leaky(deg*(x @ n1Wx + c1) + S1 @ M1)
//   h2  = leaky(deg*(h1 @ n2Wh + c2) + S2 @ M2)
//   mu|lv = h2 @ [muW|lvW] + [mub|lvb]
// R7: edges counting-sorted by dst; edge-MMA epilogue merges dst-runs in
// warp-private SMEM -> 12x fewer red.global ops (the R6 bottleneck).
// ---------------------------------------------------------------------------

typedef unsigned long long u64;

#define NMAX 50048
#define EMAX 655360

__device__ float g_S1[NMAX * 128];
__device__ float g_S2[NMAX * 128];
__device__ float g_h1[NMAX * 128];
__device__ float g_h2[NMAX * 128];
__device__ float g_deg[NMAX];
__device__ float g_B1[256 * 128];
__device__ float g_B2[256 * 128];
__device__ float g_c1[128];
__device__ float g_c2[128];
__device__ float g_B3[128 * 128];
__device__ float g_b3[128];
__device__ __nv_bfloat16 g_Bth[256 * 64];
__device__ __nv_bfloat16 g_Btl[256 * 64];
__device__ float g_biascat[256];
__device__ int g_cnt[NMAX];
__device__ int g_off[NMAX];
__device__ int g_cur[NMAX];
__device__ int g_aux[128];
__device__ int g_perm[EMAX];
__device__ int g_sdst[EMAX];

// ============================ helpers ======================================
__device__ __forceinline__ uint32_t smem_u32(const void* p) {
    uint32_t a;
    asm("{ .reg .u64 t; cvta.to.shared.u64 t, %1; cvt.u32.u64 %0, t; }" : "=r"(a) : "l"(p));
    return a;
}
__device__ __forceinline__ void ffma2(u64& d, u64 a, u64 b) {
    asm("fma.rn.f32x2 %0, %1, %2, %0;" : "+l"(d) : "l"(a), "l"(b));
}
__device__ __forceinline__ u64 pack2(float x, float y) {
    u64 r;
    asm("mov.b64 %0, {%1, %2};" : "=l"(r) : "f"(x), "f"(y));
    return r;
}
__device__ __forceinline__ float2 unpack2(u64 v) {
    float2 r;
    asm("mov.b64 {%0, %1}, %2;" : "=f"(r.x), "=f"(r.y) : "l"(v));
    return r;
}
__device__ __forceinline__ float lk(float v) { return fmaxf(v, 0.15f * v); }
__device__ __forceinline__ void red4(float* p, float a, float b, float c, float d) {
    asm volatile("red.global.add.v4.f32 [%0], {%1, %2, %3, %4};"
                 :: "l"((u64)(uintptr_t)p), "f"(a), "f"(b), "f"(c), "f"(d) : "memory");
}

// mma.sync m16n8k16 bf16 -> f32, accumulate in place
__device__ __forceinline__ void mma16816(float* c, const uint32_t* a,
                                         uint32_t b0, uint32_t b1) {
    asm volatile(
        "mma.sync.aligned.m16n8k16.row.col.f32.bf16.bf16.f32 "
        "{%0,%1,%2,%3}, {%4,%5,%6,%7}, {%8,%9}, {%0,%1,%2,%3};"
        : "+f"(c[0]), "+f"(c[1]), "+f"(c[2]), "+f"(c[3])
        : "r"(a[0]), "r"(a[1]), "r"(a[2]), "r"(a[3]), "r"(b0), "r"(b1));
}
__device__ __forceinline__ void ldsm_x4(uint32_t* r, uint32_t addr) {
    asm volatile("ldmatrix.sync.aligned.m8n8.x4.shared.b16 {%0,%1,%2,%3}, [%4];"
                 : "=r"(r[0]), "=r"(r[1]), "=r"(r[2]), "=r"(r[3]) : "r"(addr));
}

// ======================= merged precompute =================================
__global__ void prep_all(const float* __restrict__ e1W2, const float* __restrict__ e1b2,
                         const float* __restrict__ n1W,  const float* __restrict__ n1b,
                         const float* __restrict__ e2W2, const float* __restrict__ e2b2,
                         const float* __restrict__ n2W,  const float* __restrict__ n2b,
                         const float* __restrict__ muW,  const float* __restrict__ mub,
                         const float* __restrict__ lvW,  const float* __restrict__ lvb,
                         const float* __restrict__ e1W1, const float* __restrict__ e1b1,
                         const float* __restrict__ e2W1, const float* __restrict__ e2b1,
                         float* __restrict__ B1, float* __restrict__ c1,
                         float* __restrict__ B2, float* __restrict__ c2,
                         float* __restrict__ B3, float* __restrict__ b3,
                         __nv_bfloat16* __restrict__ bth, __nv_bfloat16* __restrict__ btl,
                         float* __restrict__ bias) {
    const int task = blockIdx.y, bx = blockIdx.x, tid = threadIdx.x;
    if (task <= 1) {
        const float* eW2 = task ? e2W2 : e1W2;
        const float* eb2 = task ? e2b2 : e1b2;
        const float* nW  = task ? n2W  : n1W;
        const float* nb  = task ? n2b  : n1b;
        float* Bcat = task ? B2 : B1;
        float* c = task ? c2 : c1;
        int k = bx, j = tid;
        Bcat[k * 128 + j] = nW[k * 128 + j];
        float acc = 0.f;
        #pragma unroll 4
        for (int t = 0; t < 128; t++) acc += eW2[k * 128 + t] * nW[(128 + t) * 128 + j];
        Bcat[(128 + k) * 128 + j] = acc;
        if (k == 0) {
            float cc = nb[j];
            #pragma unroll 4
            for (int t = 0; t < 128; t++) cc += eb2[t] * nW[(128 + t) * 128 + j];
            c[j] = cc;
        }
    } else if (task == 2) {
        int k = bx, j = tid;
        B3[k * 128 + j] = (j < 64) ? muW[k * 64 + j] : lvW[k * 64 + (j - 64)];
        if (k == 0) b3[j] = (j < 64) ? mub[j] : lvb[j - 64];
    } else {
        int k = tid & 63, half = tid >> 6;
        int n = bx + half * 128;
        float w = (n < 128) ? e1W1[k * 128 + n] : e2W1[k * 128 + (n - 128)];
        __nv_bfloat16 h = __float2bfloat16(w);
        float r = w - __bfloat162float(h);
        bth[n * 64 + k] = h;
        btl[n * 64 + k] = __float2bfloat16(r);
        if (k == 0) bias[n] = (n < 128) ? e1b1[n] : e2b1[n - 128];
    }
}

// ======================= counting sort by dst ==============================
__global__ void hist_kernel(const int* __restrict__ dst, int* __restrict__ cnt, int E) {
    int e = blockIdx.x * blockDim.x + threadIdx.x;
    if (e < E) atomicAdd(&cnt[dst[e]], 1);
}

#define SCAN_B 512
__global__ void scan_part(const int* __restrict__ cnt, int* __restrict__ off,
                          int* __restrict__ aux, int n) {
    __shared__ int sm[SCAN_B];
    int i = blockIdx.x * SCAN_B + threadIdx.x;
    int v = (i < n) ? cnt[i] : 0;
    sm[threadIdx.x] = v;
    __syncthreads();
    for (int s = 1; s < SCAN_B; s <<= 1) {
        int t = (threadIdx.x >= s) ? sm[threadIdx.x - s] : 0;
        __syncthreads();
        sm[threadIdx.x] += t;
        __syncthreads();
    }
    if (i < n) off[i] = sm[threadIdx.x] - v;  // exclusive
    if (threadIdx.x == SCAN_B - 1) aux[blockIdx.x] = sm[SCAN_B - 1];
}
__global__ void scan_aux(int* __restrict__ aux, int nb) {
    __shared__ int sm[128];
    int v = (threadIdx.x < nb) ? aux[threadIdx.x] : 0;
    sm[threadIdx.x] = v;
    __syncthreads();
    for (int s = 1; s < 128; s <<= 1) {
        int t = (threadIdx.x >= s) ? sm[threadIdx.x - s] : 0;
        __syncthreads();
        sm[threadIdx.x] += t;
        __syncthreads();
    }
    if (threadIdx.x < nb) aux[threadIdx.x] = sm[threadIdx.x] - v;
}
__global__ void scan_add(const int* __restrict__ cnt, int* __restrict__ off,
                         const int* __restrict__ aux, int* __restrict__ cur,
                         float* __restrict__ deg, int n) {
    int i = blockIdx.x * SCAN_B + threadIdx.x;
    if (i < n) {
        int o = off[i] + aux[blockIdx.x];
        off[i] = o;
        cur[i] = o;
        deg[i] = (float)cnt[i];
    }
}
__global__ void scatter_kernel(const int* __restrict__ dst, int* __restrict__ cur,
                               int* __restrict__ perm, int* __restrict__ sdst, int E) {
    int e = blockIdx.x * blockDim.x + threadIdx.x;
    if (e < E) {
        int d = dst[e];
        int p = atomicAdd(&cur[d], 1);
        perm[p] = e;
        sdst[p] = d;
    }
}

// ======================= mma.sync edge pass (sorted) =======================
// Tile: 128 sorted edges (M) x 256 cols (N = S1|S2) x K=64, split-bf16.
// Warp w owns cols [w*32, w*32+32). B frags register-resident; A via
// ldmatrix.x4. Epilogue: bias+leaky -> warp-private SMEM (pitch 40), then
// dst-run merge -> one red4 per (run, 4 cols).
#define APITCH 144
#define RPITCH 40
#define SM_A 0
#define SM_RES 36864
#define SM_BIAS 200704
#define SM_SDST 201728
#define EDGE_SMEM 202240

__global__ __launch_bounds__(256, 1)
void edge_mma_kernel(const float* __restrict__ ea,
                     const int* __restrict__ perm, const int* __restrict__ sdst,
                     const __nv_bfloat16* __restrict__ Bth,
                     const __nv_bfloat16* __restrict__ Btl,
                     const float* __restrict__ biascat,
                     float* __restrict__ S1, float* __restrict__ S2,
                     int E, int ntiles) {
    extern __shared__ __align__(16) char smem[];
    char* sAh = smem + SM_A;
    char* sAl = smem + SM_A + 128 * APITCH;
    float* sBias = (float*)(smem + SM_BIAS);
    int* sDst = (int*)(smem + SM_SDST);

    const int tid = threadIdx.x, wid = tid >> 5, lane = tid & 31;
    const int g = lane >> 2, q = lane & 3;
    const int n0 = wid * 32;

    sBias[tid] = biascat[tid];

    // ---- B fragments in registers (once) ----
    uint32_t bh[4][4][2], bl[4][4][2];
    {
        const uint32_t* BH = (const uint32_t*)Bth;
        const uint32_t* BL = (const uint32_t*)Btl;
        #pragma unroll
        for (int nt = 0; nt < 4; nt++) {
            const int n = n0 + nt * 8 + g;
            #pragma unroll
            for (int kt = 0; kt < 4; kt++) {
                const int base = n * 32 + kt * 8 + q;
                bh[nt][kt][0] = BH[base];
                bh[nt][kt][1] = BH[base + 4];
                bl[nt][kt][0] = BL[base];
                bl[nt][kt][1] = BL[base + 4];
            }
        }
    }

    const int rowoff = (lane & 7) + ((lane >> 3) & 1) * 8;
    const int koff = (lane >> 4) * 16;
    const uint32_t sAh_u = smem_u32(sAh);
    const uint32_t sAl_u = smem_u32(sAl);
    const uint32_t lmBase = (uint32_t)(rowoff * APITCH + koff);
    float* resW = (float*)(smem + SM_RES) + wid * 128 * RPITCH;

    for (int tile = blockIdx.x; tile < ntiles; tile += gridDim.x) {
        const int e0 = tile * 128;
        // ---- stage A tile (sorted gather, hi/lo split) ----
        {
            const int row = tid >> 1, hf = tid & 1;
            const int ge = e0 + row;
            uint32_t* ah = (uint32_t*)(sAh + row * APITCH + hf * 64);
            uint32_t* al = (uint32_t*)(sAl + row * APITCH + hf * 64);
            if (ge < E) {
                const int pe = perm[ge];
                const float4* src = (const float4*)(ea + (size_t)pe * 64 + hf * 32);
                #pragma unroll
                for (int j = 0; j < 8; j++) {
                    float4 v = src[j];
                    __nv_bfloat162 h0 = __floats2bfloat162_rn(v.x, v.y);
                    __nv_bfloat162 h1 = __floats2bfloat162_rn(v.z, v.w);
                    __nv_bfloat162 l0 = __floats2bfloat162_rn(v.x - __low2float(h0),
                                                              v.y - __high2float(h0));
                    __nv_bfloat162 l1 = __floats2bfloat162_rn(v.z - __low2float(h1),
                                                              v.w - __high2float(h1));
                    ah[j * 2]     = *(uint32_t*)&h0;
                    ah[j * 2 + 1] = *(uint32_t*)&h1;
                    al[j * 2]     = *(uint32_t*)&l0;
                    al[j * 2 + 1] = *(uint32_t*)&l1;
                }
                if (hf == 0) sDst[row] = sdst[ge];
            } else {
                #pragma unroll
                for (int j = 0; j < 16; j++) { ah[j] = 0u; al[j] = 0u; }
                if (hf == 0) sDst[row] = -1;
            }
        }
        __syncthreads();

        // ---- mainloop ----
        float acc[8][4][4];
        #pragma unroll
        for (int mt = 0; mt < 8; mt++)
            #pragma unroll
            for (int nt = 0; nt < 4; nt++)
                #pragma unroll
                for (int i = 0; i < 4; i++) acc[mt][nt][i] = 0.f;

        #pragma unroll
        for (int mt = 0; mt < 8; mt++) {
            const uint32_t mtOff = (uint32_t)(mt * 16 * APITCH) + lmBase;
            #pragma unroll
            for (int kt = 0; kt < 4; kt++) {
                uint32_t ah4[4], al4[4];
                ldsm_x4(ah4, sAh_u + mtOff + kt * 32);
                ldsm_x4(al4, sAl_u + mtOff + kt * 32);
                #pragma unroll
                for (int nt = 0; nt < 4; nt++) {
                    mma16816(acc[mt][nt], ah4, bh[nt][kt][0], bh[nt][kt][1]);
                    mma16816(acc[mt][nt], al4, bh[nt][kt][0], bh[nt][kt][1]);
                    mma16816(acc[mt][nt], ah4, bl[nt][kt][0], bl[nt][kt][1]);
                }
            }
        }

        // ---- epilogue: bias+leaky -> warp-private smem ----
        #pragma unroll
        for (int mt = 0; mt < 8; mt++) {
            #pragma unroll
            for (int nt = 0; nt < 4; nt++) {
                float* c = acc[mt][nt];
                const int col = nt * 8 + q * 2;
                const float b0 = sBias[n0 + col], b1 = sBias[n0 + col + 1];
                float2 lo = make_float2(lk(c[0] + b0), lk(c[1] + b1));
                float2 hi = make_float2(lk(c[2] + b0), lk(c[3] + b1));
                *(float2*)&resW[(mt * 16 + g) * RPITCH + col] = lo;
                *(float2*)&resW[(mt * 16 + g + 8) * RPITCH + col] = hi;
            }
        }
        __syncwarp();

        // ---- dst-run merge + single red4 per (run, 4 cols) ----
        {
            float* Sbase = (n0 < 128) ? S1 : S2;
            const int cbase = (n0 < 128) ? n0 : n0 - 128;
            int r = 0;
            while (r < 128) {
                const int d = sDst[r];
                int re = r + 1;
                while (re < 128 && sDst[re] == d) re++;
                if (d >= 0 && lane < 8) {
                    float4 a = make_float4(0.f, 0.f, 0.f, 0.f);
                    for (int rr = r; rr < re; rr++) {
                        float4 t = *(const float4*)&resW[rr * RPITCH + lane * 4];
                        a.x += t.x; a.y += t.y; a.z += t.z; a.w += t.w;
                    }
                    red4(&Sbase[(size_t)d * 128 + cbase + lane * 4], a.x, a.y, a.z, a.w);
                }
                r = re;
            }
        }
        __syncthreads();
    }
}

// ======================= node GEMMs (fp32, known-good) =====================
template <int KTOT, bool SECOND, bool DOLEAKY, bool SPLIT>
__global__ __launch_bounds__(256) void node_gemm(
    const float* __restrict__ A1, const float* __restrict__ A2,
    const float* __restrict__ B, const float* __restrict__ bias,
    const float* __restrict__ deg, float* __restrict__ out, int N) {
    extern __shared__ float sm[];
    float* shB = sm;             // [64][128]
    float* shA = sm + 64 * 128;  // [64][64]

    const int tid = threadIdx.x, wid = tid >> 5, lane = tid & 31;
    const int j0 = lane * 4;
    const int row0 = blockIdx.x * 64;

    float degv[8];
    #pragma unroll
    for (int r = 0; r < 8; r++) {
        int row = row0 + wid * 8 + r;
        degv[r] = (SECOND && row < N) ? deg[row] : 1.f;
    }
    float4 bv = *(const float4*)&bias[j0];
    u64 acc[8][2];
    #pragma unroll
    for (int r = 0; r < 8; r++) {
        acc[r][0] = pack2(degv[r] * bv.x, degv[r] * bv.y);
        acc[r][1] = pack2(degv[r] * bv.z, degv[r] * bv.w);
    }

    for (int kc = 0; kc < KTOT; kc += 64) {
        __syncthreads();
        for (int i = tid; i < 2048; i += 256)
            *(float4*)&shB[i * 4] = *(const float4*)&B[(size_t)kc * 128 + i * 4];
        for (int i = tid; i < 1024; i += 256) {
            int rr = i & 63, kq = i >> 6;
            int k4g = kc + kq * 4;
            int row = row0 + rr;
            float4 v = make_float4(0.f, 0.f, 0.f, 0.f);
            if (row < N) {
                if (!SECOND || k4g < 128) {
                    v = *(const float4*)&A1[(size_t)row * 128 + k4g];
                    if (SECOND) {
                        float dg = deg[row];
                        v.x *= dg; v.y *= dg; v.z *= dg; v.w *= dg;
                    }
                } else {
                    v = *(const float4*)&A2[(size_t)row * 128 + (k4g - 128)];
                }
            }
            int k4 = kq * 4;
            shA[(k4 + 0) * 64 + rr] = v.x;
            shA[(k4 + 1) * 64 + rr] = v.y;
            shA[(k4 + 2) * 64 + rr] = v.z;
            shA[(k4 + 3) * 64 + rr] = v.w;
        }
        __syncthreads();

        const float* aBase = shA + wid * 8;
        #pragma unroll 8
        for (int kk = 0; kk < 64; kk++) {
            float4 a03 = *(const float4*)(aBase + kk * 64);
            float4 a47 = *(const float4*)(aBase + kk * 64 + 4);
            ulonglong2 w = *(const ulonglong2*)&shB[kk * 128 + j0];
            float a[8] = {a03.x, a03.y, a03.z, a03.w, a47.x, a47.y, a47.z, a47.w};
            #pragma unroll
            for (int r = 0; r < 8; r++) {
                u64 ad = pack2(a[r], a[r]);
                ffma2(acc[r][0], ad, w.x);
                ffma2(acc[r][1], ad, w.y);
            }
        }
    }

    #pragma unroll
    for (int r = 0; r < 8; r++) {
        int row = row0 + wid * 8 + r;
        if (row >= N) continue;
        float2 p0 = unpack2(acc[r][0]), p1 = unpack2(acc[r][1]);
        float4 v = make_float4(p0.x, p0.y, p1.x, p1.y);
        if (DOLEAKY) { v.x = lk(v.x); v.y = lk(v.y); v.z = lk(v.z); v.w = lk(v.w); }
        if (!SPLIT) {
            *(float4*)&out[(size_t)row * 128 + j0] = v;
        } else {
            if (j0 < 64)
                *(float4*)&out[(size_t)row * 64 + j0] = v;
            else
                *(float4*)&out[(size_t)N * 64 + (size_t)row * 64 + (j0 - 64)] = v;
        }
    }
}

// ---------------------------------------------------------------------------
extern "C" void kernel_launch(void* const* d_in, const int* in_sizes, int n_in,
                              void* d_out, int out_size) {
    const float* x    = (const float*)d_in[0];
    const int*   ei   = (const int*)d_in[1];
    const float* ea   = (const float*)d_in[2];
    const float* e1W1 = (const float*)d_in[3];
    const float* e1b1 = (const float*)d_in[4];
    const float* e1W2 = (const float*)d_in[5];
    const float* e1b2 = (const float*)d_in[6];
    const float* n1W  = (const float*)d_in[7];
    const float* n1b  = (const float*)d_in[8];
    const float* e2W1 = (const float*)d_in[9];
    const float* e2b1 = (const float*)d_in[10];
    const float* e2W2 = (const float*)d_in[11];
    const float* e2b2 = (const float*)d_in[12];
    const float* n2W  = (const float*)d_in[13];
    const float* n2b  = (const float*)d_in[14];
    const float* muW  = (const float*)d_in[15];
    const float* mub  = (const float*)d_in[16];
    const float* lvW  = (const float*)d_in[17];
    const float* lvb  = (const float*)d_in[18];

    const int N = in_sizes[0] / 128;  // 50000
    const int E = in_sizes[2] / 64;   // 640000
    const int* dst = ei + E;          // edge_index row 1

    float *S1, *S2, *h1, *h2, *dg, *B1, *B2, *c1, *c2, *B3, *b3, *biascat;
    __nv_bfloat16 *Bth, *Btl;
    int *cnt, *off, *cur, *aux, *perm, *sdst;
    cudaGetSymbolAddress((void**)&S1, g_S1);
    cudaGetSymbolAddress((void**)&S2, g_S2);
    cudaGetSymbolAddress((void**)&h1, g_h1);
    cudaGetSymbolAddress((void**)&h2, g_h2);
    cudaGetSymbolAddress((void**)&dg, g_deg);
    cudaGetSymbolAddress((void**)&B1, g_B1);
    cudaGetSymbolAddress((void**)&B2, g_B2);
    cudaGetSymbolAddress((void**)&c1, g_c1);
    cudaGetSymbolAddress((void**)&c2, g_c2);
    cudaGetSymbolAddress((void**)&B3, g_B3);
    cudaGetSymbolAddress((void**)&b3, g_b3);
    cudaGetSymbolAddress((void**)&Bth, g_Bth);
    cudaGetSymbolAddress((void**)&Btl, g_Btl);
    cudaGetSymbolAddress((void**)&biascat, g_biascat);
    cudaGetSymbolAddress((void**)&cnt, g_cnt);
    cudaGetSymbolAddress((void**)&off, g_off);
    cudaGetSymbolAddress((void**)&cur, g_cur);
    cudaGetSymbolAddress((void**)&aux, g_aux);
    cudaGetSymbolAddress((void**)&perm, g_perm);
    cudaGetSymbolAddress((void**)&sdst, g_sdst);

    cudaMemsetAsync(S1, 0, (size_t)N * 128 * sizeof(float));
    cudaMemsetAsync(S2, 0, (size_t)N * 128 * sizeof(float));
    cudaMemsetAsync(cnt, 0, (size_t)N * sizeof(int));

    prep_all<<<dim3(128, 4), 128>>>(e1W2, e1b2, n1W, n1b,
                                    e2W2, e2b2, n2W, n2b,
                                    muW, mub, lvW, lvb,
                                    e1W1, e1b1, e2W1, e2b1,
                                    B1, c1, B2, c2, B3, b3, Bth, Btl, biascat);

    // ---- counting sort of edges by dst (also produces deg) ----
    const int nsb = (N + SCAN_B - 1) / SCAN_B;  // 98
    hist_kernel<<<(E + 255) / 256, 256>>>(dst, cnt, E);
    scan_part<<<nsb, SCAN_B>>>(cnt, off, aux, N);
    scan_aux<<<1, 128>>>(aux, nsb);
    scan_add<<<nsb, SCAN_B>>>(cnt, off, aux, cur, dg, N);
    scatter_kernel<<<(E + 255) / 256, 256>>>(dst, cur, perm, sdst, E);

    // ---- sorted edge MMA pass ----
    cudaFuncSetAttribute(edge_mma_kernel, cudaFuncAttributeMaxDynamicSharedMemorySize,
                         EDGE_SMEM);
    int ntiles = (E + 127) / 128;
    int egrid = ntiles < 148 ? ntiles : 148;
    edge_mma_kernel<<<egrid, 256, EDGE_SMEM>>>(ea, perm, sdst, Bth, Btl, biascat,
                                               S1, S2, E, ntiles);

    const int NODE_SMEM = (64 * 128 + 64 * 64) * 4;  // 49152 B
    int nblk = (N + 63) / 64;
    cudaFuncSetAttribute(node_gemm<256, true, true, false>,
                         cudaFuncAttributeMaxDynamicSharedMemorySize, NODE_SMEM);
    cudaFuncSetAttribute(node_gemm<128, false, false, true>,
                         cudaFuncAttributeMaxDynamicSharedMemorySize, NODE_SMEM);

    node_gemm<256, true, true, false><<<nblk, 256, NODE_SMEM>>>(x,  S1, B1, c1, dg, h1, N);
    node_gemm<256, true, true, false><<<nblk, 256, NODE_SMEM>>>(h1, S2, B2, c2, dg, h2, N);
    node_gemm<128, false, false, true><<<nblk, 256, NODE_SMEM>>>(h2, nullptr, B3, b3, nullptr,
                                                                 (float*)d_out, N);
}

// round 8
// speedup vs baseline: 1.1839x; 1.1839x over previous
#include <cuda_runtime.h>
#include <cuda_bf16.h>
#include <cstdint>
#include <cstdio>

// ---------------------------------------------------------------------------
// EdgeVGAE encoder, algebraically collapsed:
//   S_l = segment_sum(leaky(edge_attr @ W1_l + b1_l), dst)   (edge pass, l=1,2)
//   h1  = leaky(deg*(x @ n1Wx + c1) + S1 @ M1)
//   h2  = leaky(deg*(h1 @ n2Wh + c2) + S2 @ M2)
//   mu|lv = h2 @ [muW|lvW] + [mub|lvb]
// R8: R7's dst-sorted merge, but run boundaries found via parallel ballot
// compaction (R7's serial per-row scan was the regression: ~4K cyc/tile/warp).
// ---------------------------------------------------------------------------

typedef unsigned long long u64;

#define NMAX 50048
#define EMAX 655360

__device__ float g_S1[NMAX * 128];
__device__ float g_S2[NMAX * 128];
__device__ float g_h1[NMAX * 128];
__device__ float g_h2[NMAX * 128];
__device__ float g_deg[NMAX];
__device__ float g_B1[256 * 128];
__device__ float g_B2[256 * 128];
__device__ float g_c1[128];
__device__ float g_c2[128];
__device__ float g_B3[128 * 128];
__device__ float g_b3[128];
__device__ __nv_bfloat16 g_Bth[256 * 64];
__device__ __nv_bfloat16 g_Btl[256 * 64];
__device__ float g_biascat[256];
__device__ int g_cnt[NMAX];
__device__ int g_off[NMAX];
__device__ int g_cur[NMAX];
__device__ int g_aux[128];
__device__ int g_perm[EMAX];
__device__ int g_sdst[EMAX];

// ============================ helpers ======================================
__device__ __forceinline__ uint32_t smem_u32(const void* p) {
    uint32_t a;
    asm("{ .reg .u64 t; cvta.to.shared.u64 t, %1; cvt.u32.u64 %0, t; }" : "=r"(a) : "l"(p));
    return a;
}
__device__ __forceinline__ void ffma2(u64& d, u64 a, u64 b) {
    asm("fma.rn.f32x2 %0, %1, %2, %0;" : "+l"(d) : "l"(a), "l"(b));
}
__device__ __forceinline__ u64 pack2(float x, float y) {
    u64 r;
    asm("mov.b64 %0, {%1, %2};" : "=l"(r) : "f"(x), "f"(y));
    return r;
}
__device__ __forceinline__ float2 unpack2(u64 v) {
    float2 r;
    asm("mov.b64 {%0, %1}, %2;" : "=f"(r.x), "=f"(r.y) : "l"(v));
    return r;
}
__device__ __forceinline__ float lk(float v) { return fmaxf(v, 0.15f * v); }
__device__ __forceinline__ void red4(float* p, float a, float b, float c, float d) {
    asm volatile("red.global.add.v4.f32 [%0], {%1, %2, %3, %4};"
                 :: "l"((u64)(uintptr_t)p), "f"(a), "f"(b), "f"(c), "f"(d) : "memory");
}

// mma.sync m16n8k16 bf16 -> f32, accumulate in place
__device__ __forceinline__ void mma16816(float* c, const uint32_t* a,
                                         uint32_t b0, uint32_t b1) {
    asm volatile(
        "mma.sync.aligned.m16n8k16.row.col.f32.bf16.bf16.f32 "
        "{%0,%1,%2,%3}, {%4,%5,%6,%7}, {%8,%9}, {%0,%1,%2,%3};"
        : "+f"(c[0]), "+f"(c[1]), "+f"(c[2]), "+f"(c[3])
        : "r"(a[0]), "r"(a[1]), "r"(a[2]), "r"(a[3]), "r"(b0), "r"(b1));
}
__device__ __forceinline__ void ldsm_x4(uint32_t* r, uint32_t addr) {
    asm volatile("ldmatrix.sync.aligned.m8n8.x4.shared.b16 {%0,%1,%2,%3}, [%4];"
                 : "=r"(r[0]), "=r"(r[1]), "=r"(r[2]), "=r"(r[3]) : "r"(addr));
}

// ======================= merged precompute =================================
__global__ void prep_all(const float* __restrict__ e1W2, const float* __restrict__ e1b2,
                         const float* __restrict__ n1W,  const float* __restrict__ n1b,
                         const float* __restrict__ e2W2, const float* __restrict__ e2b2,
                         const float* __restrict__ n2W,  const float* __restrict__ n2b,
                         const float* __restrict__ muW,  const float* __restrict__ mub,
                         const float* __restrict__ lvW,  const float* __restrict__ lvb,
                         const float* __restrict__ e1W1, const float* __restrict__ e1b1,
                         const float* __restrict__ e2W1, const float* __restrict__ e2b1,
                         float* __restrict__ B1, float* __restrict__ c1,
                         float* __restrict__ B2, float* __restrict__ c2,
                         float* __restrict__ B3, float* __restrict__ b3,
                         __nv_bfloat16* __restrict__ bth, __nv_bfloat16* __restrict__ btl,
                         float* __restrict__ bias) {
    const int task = blockIdx.y, bx = blockIdx.x, tid = threadIdx.x;
    if (task <= 1) {
        const float* eW2 = task ? e2W2 : e1W2;
        const float* eb2 = task ? e2b2 : e1b2;
        const float* nW  = task ? n2W  : n1W;
        const float* nb  = task ? n2b  : n1b;
        float* Bcat = task ? B2 : B1;
        float* c = task ? c2 : c1;
        int k = bx, j = tid;
        Bcat[k * 128 + j] = nW[k * 128 + j];
        float acc = 0.f;
        #pragma unroll 4
        for (int t = 0; t < 128; t++) acc += eW2[k * 128 + t] * nW[(128 + t) * 128 + j];
        Bcat[(128 + k) * 128 + j] = acc;
        if (k == 0) {
            float cc = nb[j];
            #pragma unroll 4
            for (int t = 0; t < 128; t++) cc += eb2[t] * nW[(128 + t) * 128 + j];
            c[j] = cc;
        }
    } else if (task == 2) {
        int k = bx, j = tid;
        B3[k * 128 + j] = (j < 64) ? muW[k * 64 + j] : lvW[k * 64 + (j - 64)];
        if (k == 0) b3[j] = (j < 64) ? mub[j] : lvb[j - 64];
    } else {
        int k = tid & 63, half = tid >> 6;
        int n = bx + half * 128;
        float w = (n < 128) ? e1W1[k * 128 + n] : e2W1[k * 128 + (n - 128)];
        __nv_bfloat16 h = __float2bfloat16(w);
        float r = w - __bfloat162float(h);
        bth[n * 64 + k] = h;
        btl[n * 64 + k] = __float2bfloat16(r);
        if (k == 0) bias[n] = (n < 128) ? e1b1[n] : e2b1[n - 128];
    }
}

// ======================= counting sort by dst ==============================
__global__ void hist_kernel(const int* __restrict__ dst, int* __restrict__ cnt, int E) {
    int e = blockIdx.x * blockDim.x + threadIdx.x;
    if (e < E) atomicAdd(&cnt[dst[e]], 1);
}

#define SCAN_B 512
__global__ void scan_part(const int* __restrict__ cnt, int* __restrict__ off,
                          int* __restrict__ aux, int n) {
    __shared__ int sm[SCAN_B];
    int i = blockIdx.x * SCAN_B + threadIdx.x;
    int v = (i < n) ? cnt[i] : 0;
    sm[threadIdx.x] = v;
    __syncthreads();
    for (int s = 1; s < SCAN_B; s <<= 1) {
        int t = (threadIdx.x >= s) ? sm[threadIdx.x - s] : 0;
        __syncthreads();
        sm[threadIdx.x] += t;
        __syncthreads();
    }
    if (i < n) off[i] = sm[threadIdx.x] - v;  // exclusive
    if (threadIdx.x == SCAN_B - 1) aux[blockIdx.x] = sm[SCAN_B - 1];
}
__global__ void scan_aux(int* __restrict__ aux, int nb) {
    __shared__ int sm[128];
    int v = (threadIdx.x < nb) ? aux[threadIdx.x] : 0;
    sm[threadIdx.x] = v;
    __syncthreads();
    for (int s = 1; s < 128; s <<= 1) {
        int t = (threadIdx.x >= s) ? sm[threadIdx.x - s] : 0;
        __syncthreads();
        sm[threadIdx.x] += t;
        __syncthreads();
    }
    if (threadIdx.x < nb) aux[threadIdx.x] = sm[threadIdx.x] - v;
}
__global__ void scan_add(const int* __restrict__ cnt, int* __restrict__ off,
                         const int* __restrict__ aux, int* __restrict__ cur,
                         float* __restrict__ deg, int n) {
    int i = blockIdx.x * SCAN_B + threadIdx.x;
    if (i < n) {
        int o = off[i] + aux[blockIdx.x];
        off[i] = o;
        cur[i] = o;
        deg[i] = (float)cnt[i];
    }
}
__global__ void scatter_kernel(const int* __restrict__ dst, int* __restrict__ cur,
                               int* __restrict__ perm, int* __restrict__ sdst, int E) {
    int e = blockIdx.x * blockDim.x + threadIdx.x;
    if (e < E) {
        int d = dst[e];
        int p = atomicAdd(&cur[d], 1);
        perm[p] = e;
        sdst[p] = d;
    }
}

// ======================= mma.sync edge pass (sorted) =======================
// Tile: 128 sorted edges (M) x 256 cols (N = S1|S2) x K=64, split-bf16.
// Warp w owns cols [w*32, w*32+32). B frags register-resident; A via
// ldmatrix.x4. Run boundaries via ballot compaction; epilogue merges each
// dst-run in warp-private SMEM -> one red4 per (run, 4 cols).
#define APITCH 144
#define RPITCH 40
#define SM_A 0
#define SM_RES 36864
#define SM_BIAS 200704
#define SM_SDST 201728
#define SM_MASK 202240     // 4 u32 ballot masks
#define SM_NRUN 202256     // 1 int
#define SM_RUNS 202272     // 132 ints
#define EDGE_SMEM 202816

__global__ __launch_bounds__(256, 1)
void edge_mma_kernel(const float* __restrict__ ea,
                     const int* __restrict__ perm, const int* __restrict__ sdst,
                     const __nv_bfloat16* __restrict__ Bth,
                     const __nv_bfloat16* __restrict__ Btl,
                     const float* __restrict__ biascat,
                     float* __restrict__ S1, float* __restrict__ S2,
                     int E, int ntiles) {
    extern __shared__ __align__(16) char smem[];
    char* sAh = smem + SM_A;
    char* sAl = smem + SM_A + 128 * APITCH;
    float* sBias = (float*)(smem + SM_BIAS);
    int* sDst = (int*)(smem + SM_SDST);
    unsigned* sMask = (unsigned*)(smem + SM_MASK);
    int* sNRuns = (int*)(smem + SM_NRUN);
    int* sRunStart = (int*)(smem + SM_RUNS);

    const int tid = threadIdx.x, wid = tid >> 5, lane = tid & 31;
    const int g = lane >> 2, q = lane & 3;
    const int n0 = wid * 32;

    sBias[tid] = biascat[tid];

    // ---- B fragments in registers (once) ----
    uint32_t bh[4][4][2], bl[4][4][2];
    {
        const uint32_t* BH = (const uint32_t*)Bth;
        const uint32_t* BL = (const uint32_t*)Btl;
        #pragma unroll
        for (int nt = 0; nt < 4; nt++) {
            const int n = n0 + nt * 8 + g;
            #pragma unroll
            for (int kt = 0; kt < 4; kt++) {
                const int base = n * 32 + kt * 8 + q;
                bh[nt][kt][0] = BH[base];
                bh[nt][kt][1] = BH[base + 4];
                bl[nt][kt][0] = BL[base];
                bl[nt][kt][1] = BL[base + 4];
            }
        }
    }

    const int rowoff = (lane & 7) + ((lane >> 3) & 1) * 8;
    const int koff = (lane >> 4) * 16;
    const uint32_t sAh_u = smem_u32(sAh);
    const uint32_t sAl_u = smem_u32(sAl);
    const uint32_t lmBase = (uint32_t)(rowoff * APITCH + koff);
    float* resW = (float*)(smem + SM_RES) + wid * 128 * RPITCH;

    for (int tile = blockIdx.x; tile < ntiles; tile += gridDim.x) {
        const int e0 = tile * 128;
        // ---- stage A tile (sorted gather, hi/lo split) ----
        {
            const int row = tid >> 1, hf = tid & 1;
            const int ge = e0 + row;
            uint32_t* ah = (uint32_t*)(sAh + row * APITCH + hf * 64);
            uint32_t* al = (uint32_t*)(sAl + row * APITCH + hf * 64);
            if (ge < E) {
                const int pe = perm[ge];
                const float4* src = (const float4*)(ea + (size_t)pe * 64 + hf * 32);
                #pragma unroll
                for (int j = 0; j < 8; j++) {
                    float4 v = src[j];
                    __nv_bfloat162 h0 = __floats2bfloat162_rn(v.x, v.y);
                    __nv_bfloat162 h1 = __floats2bfloat162_rn(v.z, v.w);
                    __nv_bfloat162 l0 = __floats2bfloat162_rn(v.x - __low2float(h0),
                                                              v.y - __high2float(h0));
                    __nv_bfloat162 l1 = __floats2bfloat162_rn(v.z - __low2float(h1),
                                                              v.w - __high2float(h1));
                    ah[j * 2]     = *(uint32_t*)&h0;
                    ah[j * 2 + 1] = *(uint32_t*)&h1;
                    al[j * 2]     = *(uint32_t*)&l0;
                    al[j * 2 + 1] = *(uint32_t*)&l1;
                }
                if (hf == 0) sDst[row] = sdst[ge];
            } else {
                #pragma unroll
                for (int j = 0; j < 16; j++) { ah[j] = 0u; al[j] = 0u; }
                if (hf == 0) sDst[row] = -1;
            }
        }
        __syncthreads();

        // ---- parallel run-boundary detection (ballot compaction) ----
        if (tid < 128) {
            int head = (tid == 0) || (sDst[tid] != sDst[tid - 1]);
            unsigned b = __ballot_sync(0xffffffffu, head);
            if (lane == 0) sMask[tid >> 5] = b;
        }
        __syncthreads();
        if (tid < 128) {
            const int chunk = tid >> 5;
            unsigned b = sMask[chunk];
            int off = 0;
            #pragma unroll
            for (int c = 0; c < 4; c++) off += (c < chunk) ? __popc(sMask[c]) : 0;
            if ((b >> lane) & 1u) {
                int rank = off + __popc(b & ((1u << lane) - 1u));
                sRunStart[rank] = tid;
            }
            if (tid == 0) {
                int R = __popc(sMask[0]) + __popc(sMask[1]) +
                        __popc(sMask[2]) + __popc(sMask[3]);
                *sNRuns = R;
                sRunStart[R] = 128;
            }
        }
        __syncthreads();

        // ---- mainloop ----
        float acc[8][4][4];
        #pragma unroll
        for (int mt = 0; mt < 8; mt++)
            #pragma unroll
            for (int nt = 0; nt < 4; nt++)
                #pragma unroll
                for (int i = 0; i < 4; i++) acc[mt][nt][i] = 0.f;

        #pragma unroll
        for (int mt = 0; mt < 8; mt++) {
            const uint32_t mtOff = (uint32_t)(mt * 16 * APITCH) + lmBase;
            #pragma unroll
            for (int kt = 0; kt < 4; kt++) {
                uint32_t ah4[4], al4[4];
                ldsm_x4(ah4, sAh_u + mtOff + kt * 32);
                ldsm_x4(al4, sAl_u + mtOff + kt * 32);
                #pragma unroll
                for (int nt = 0; nt < 4; nt++) {
                    mma16816(acc[mt][nt], ah4, bh[nt][kt][0], bh[nt][kt][1]);
                    mma16816(acc[mt][nt], al4, bh[nt][kt][0], bh[nt][kt][1]);
                    mma16816(acc[mt][nt], ah4, bl[nt][kt][0], bl[nt][kt][1]);
                }
            }
        }

        // ---- epilogue: bias+leaky -> warp-private smem ----
        #pragma unroll
        for (int mt = 0; mt < 8; mt++) {
            #pragma unroll
            for (int nt = 0; nt < 4; nt++) {
                float* c = acc[mt][nt];
                const int col = nt * 8 + q * 2;
                const float b0 = sBias[n0 + col], b1 = sBias[n0 + col + 1];
                float2 lo = make_float2(lk(c[0] + b0), lk(c[1] + b1));
                float2 hi = make_float2(lk(c[2] + b0), lk(c[3] + b1));
                *(float2*)&resW[(mt * 16 + g) * RPITCH + col] = lo;
                *(float2*)&resW[(mt * 16 + g + 8) * RPITCH + col] = hi;
            }
        }
        __syncwarp();

        // ---- uniform run loop: accumulate + single red4 per (run, 4 cols) ----
        {
            const int R = *sNRuns;
            float* Sbase = (n0 < 128) ? S1 : S2;
            const int cbase = (n0 < 128) ? n0 : n0 - 128;
            for (int j = 0; j < R; j++) {
                const int st = sRunStart[j], en = sRunStart[j + 1];
                const int d = sDst[st];
                if (d >= 0 && lane < 8) {
                    float4 a = make_float4(0.f, 0.f, 0.f, 0.f);
                    for (int rr = st; rr < en; rr++) {
                        float4 t = *(const float4*)&resW[rr * RPITCH + lane * 4];
                        a.x += t.x; a.y += t.y; a.z += t.z; a.w += t.w;
                    }
                    red4(&Sbase[(size_t)d * 128 + cbase + lane * 4], a.x, a.y, a.z, a.w);
                }
            }
        }
        __syncthreads();
    }
}

// ======================= node GEMMs (fp32, known-good) =====================
template <int KTOT, bool SECOND, bool DOLEAKY, bool SPLIT>
__global__ __launch_bounds__(256) void node_gemm(
    const float* __restrict__ A1, const float* __restrict__ A2,
    const float* __restrict__ B, const float* __restrict__ bias,
    const float* __restrict__ deg, float* __restrict__ out, int N) {
    extern __shared__ float sm[];
    float* shB = sm;             // [64][128]
    float* shA = sm + 64 * 128;  // [64][64]

    const int tid = threadIdx.x, wid = tid >> 5, lane = tid & 31;
    const int j0 = lane * 4;
    const int row0 = blockIdx.x * 64;

    float degv[8];
    #pragma unroll
    for (int r = 0; r < 8; r++) {
        int row = row0 + wid * 8 + r;
        degv[r] = (SECOND && row < N) ? deg[row] : 1.f;
    }
    float4 bv = *(const float4*)&bias[j0];
    u64 acc[8][2];
    #pragma unroll
    for (int r = 0; r < 8; r++) {
        acc[r][0] = pack2(degv[r] * bv.x, degv[r] * bv.y);
        acc[r][1] = pack2(degv[r] * bv.z, degv[r] * bv.w);
    }

    for (int kc = 0; kc < KTOT; kc += 64) {
        __syncthreads();
        for (int i = tid; i < 2048; i += 256)
            *(float4*)&shB[i * 4] = *(const float4*)&B[(size_t)kc * 128 + i * 4];
        for (int i = tid; i < 1024; i += 256) {
            int rr = i & 63, kq = i >> 6;
            int k4g = kc + kq * 4;
            int row = row0 + rr;
            float4 v = make_float4(0.f, 0.f, 0.f, 0.f);
            if (row < N) {
                if (!SECOND || k4g < 128) {
                    v = *(const float4*)&A1[(size_t)row * 128 + k4g];
                    if (SECOND) {
                        float dg = deg[row];
                        v.x *= dg; v.y *= dg; v.z *= dg; v.w *= dg;
                    }
                } else {
                    v = *(const float4*)&A2[(size_t)row * 128 + (k4g - 128)];
                }
            }
            int k4 = kq * 4;
            shA[(k4 + 0) * 64 + rr] = v.x;
            shA[(k4 + 1) * 64 + rr] = v.y;
            shA[(k4 + 2) * 64 + rr] = v.z;
            shA[(k4 + 3) * 64 + rr] = v.w;
        }
        __syncthreads();

        const float* aBase = shA + wid * 8;
        #pragma unroll 8
        for (int kk = 0; kk < 64; kk++) {
            float4 a03 = *(const float4*)(aBase + kk * 64);
            float4 a47 = *(const float4*)(aBase + kk * 64 + 4);
            ulonglong2 w = *(const ulonglong2*)&shB[kk * 128 + j0];
            float a[8] = {a03.x, a03.y, a03.z, a03.w, a47.x, a47.y, a47.z, a47.w};
            #pragma unroll
            for (int r = 0; r < 8; r++) {
                u64 ad = pack2(a[r], a[r]);
                ffma2(acc[r][0], ad, w.x);
                ffma2(acc[r][1], ad, w.y);
            }
        }
    }

    #pragma unroll
    for (int r = 0; r < 8; r++) {
        int row = row0 + wid * 8 + r;
        if (row >= N) continue;
        float2 p0 = unpack2(acc[r][0]), p1 = unpack2(acc[r][1]);
        float4 v = make_float4(p0.x, p0.y, p1.x, p1.y);
        if (DOLEAKY) { v.x = lk(v.x); v.y = lk(v.y); v.z = lk(v.z); v.w = lk(v.w); }
        if (!SPLIT) {
            *(float4*)&out[(size_t)row * 128 + j0] = v;
        } else {
            if (j0 < 64)
                *(float4*)&out[(size_t)row * 64 + j0] = v;
            else
                *(float4*)&out[(size_t)N * 64 + (size_t)row * 64 + (j0 - 64)] = v;
        }
    }
}

// ---------------------------------------------------------------------------
extern "C" void kernel_launch(void* const* d_in, const int* in_sizes, int n_in,
                              void* d_out, int out_size) {
    const float* x    = (const float*)d_in[0];
    const int*   ei   = (const int*)d_in[1];
    const float* ea   = (const float*)d_in[2];
    const float* e1W1 = (const float*)d_in[3];
    const float* e1b1 = (const float*)d_in[4];
    const float* e1W2 = (const float*)d_in[5];
    const float* e1b2 = (const float*)d_in[6];
    const float* n1W  = (const float*)d_in[7];
    const float* n1b  = (const float*)d_in[8];
    const float* e2W1 = (const float*)d_in[9];
    const float* e2b1 = (const float*)d_in[10];
    const float* e2W2 = (const float*)d_in[11];
    const float* e2b2 = (const float*)d_in[12];
    const float* n2W  = (const float*)d_in[13];
    const float* n2b  = (const float*)d_in[14];
    const float* muW  = (const float*)d_in[15];
    const float* mub  = (const float*)d_in[16];
    const float* lvW  = (const float*)d_in[17];
    const float* lvb  = (const float*)d_in[18];

    const int N = in_sizes[0] / 128;  // 50000
    const int E = in_sizes[2] / 64;   // 640000
    const int* dst = ei + E;          // edge_index row 1

    float *S1, *S2, *h1, *h2, *dg, *B1, *B2, *c1, *c2, *B3, *b3, *biascat;
    __nv_bfloat16 *Bth, *Btl;
    int *cnt, *off, *cur, *aux, *perm, *sdst;
    cudaGetSymbolAddress((void**)&S1, g_S1);
    cudaGetSymbolAddress((void**)&S2, g_S2);
    cudaGetSymbolAddress((void**)&h1, g_h1);
    cudaGetSymbolAddress((void**)&h2, g_h2);
    cudaGetSymbolAddress((void**)&dg, g_deg);
    cudaGetSymbolAddress((void**)&B1, g_B1);
    cudaGetSymbolAddress((void**)&B2, g_B2);
    cudaGetSymbolAddress((void**)&c1, g_c1);
    cudaGetSymbolAddress((void**)&c2, g_c2);
    cudaGetSymbolAddress((void**)&B3, g_B3);
    cudaGetSymbolAddress((void**)&b3, g_b3);
    cudaGetSymbolAddress((void**)&Bth, g_Bth);
    cudaGetSymbolAddress((void**)&Btl, g_Btl);
    cudaGetSymbolAddress((void**)&biascat, g_biascat);
    cudaGetSymbolAddress((void**)&cnt, g_cnt);
    cudaGetSymbolAddress((void**)&off, g_off);
    cudaGetSymbolAddress((void**)&cur, g_cur);
    cudaGetSymbolAddress((void**)&aux, g_aux);
    cudaGetSymbolAddress((void**)&perm, g_perm);
    cudaGetSymbolAddress((void**)&sdst, g_sdst);

    cudaMemsetAsync(S1, 0, (size_t)N * 128 * sizeof(float));
    cudaMemsetAsync(S2, 0, (size_t)N * 128 * sizeof(float));
    cudaMemsetAsync(cnt, 0, (size_t)N * sizeof(int));

    prep_all<<<dim3(128, 4), 128>>>(e1W2, e1b2, n1W, n1b,
                                    e2W2, e2b2, n2W, n2b,
                                    muW, mub, lvW, lvb,
                                    e1W1, e1b1, e2W1, e2b1,
                                    B1, c1, B2, c2, B3, b3, Bth, Btl, biascat);

    // ---- counting sort of edges by dst (also produces deg) ----
    const int nsb = (N + SCAN_B - 1) / SCAN_B;  // 98
    hist_kernel<<<(E + 255) / 256, 256>>>(dst, cnt, E);
    scan_part<<<nsb, SCAN_B>>>(cnt, off, aux, N);
    scan_aux<<<1, 128>>>(aux, nsb);
    scan_add<<<nsb, SCAN_B>>>(cnt, off, aux, cur, dg, N);
    scatter_kernel<<<(E + 255) / 256, 256>>>(dst, cur, perm, sdst, E);

    // ---- sorted edge MMA pass ----
    cudaFuncSetAttribute(edge_mma_kernel, cudaFuncAttributeMaxDynamicSharedMemorySize,
                         EDGE_SMEM);
    int ntiles = (E + 127) / 128;
    int egrid = ntiles < 148 ? ntiles : 148;
    edge_mma_kernel<<<egrid, 256, EDGE_SMEM>>>(ea, perm, sdst, Bth, Btl, biascat,
                                               S1, S2, E, ntiles);

    const int NODE_SMEM = (64 * 128 + 64 * 64) * 4;  // 49152 B
    int nblk = (N + 63) / 64;
    cudaFuncSetAttribute(node_gemm<256, true, true, false>,
                         cudaFuncAttributeMaxDynamicSharedMemorySize, NODE_SMEM);
    cudaFuncSetAttribute(node_gemm<128, false, false, true>,
                         cudaFuncAttributeMaxDynamicSharedMemorySize, NODE_SMEM);

    node_gemm<256, true, true, false><<<nblk, 256, NODE_SMEM>>>(x,  S1, B1, c1, dg, h1, N);
    node_gemm<256, true, true, false><<<nblk, 256, NODE_SMEM>>>(h1, S2, B2, c2, dg, h2, N);
    node_gemm<128, false, false, true><<<nblk, 256, NODE_SMEM>>>(h2, nullptr, B3, b3, nullptr,
                                                                 (float*)d_out, N);
}

// round 10
// speedup vs baseline: 1.4479x; 1.2229x over previous
#include <cuda_runtime.h>
#include <cuda_bf16.h>
#include <cstdint>
#include <cstdio>

// ---------------------------------------------------------------------------
// EdgeVGAE encoder, algebraically collapsed:
//   S_l = segment_sum(leaky(edge_attr @ W1_l + b1_l), dst)   (edge pass, l=1,2)
//   h1  = leaky(deg*(x @ n1Wx + c1) + S1 @ M1)
//   h2  = leaky(deg*(h1 @ n2Wh + c2) + S2 @ M2)
//   mu|lv = h2 @ [muW|lvW] + [mub|lvb]
// R10: R9 with the node_mma B-staging bug fixed (copied 32 of 64 bytes per
// (row,half) -> uninitialized SMEM -> NaN). Edge pass = R6 config.
// ---------------------------------------------------------------------------

typedef unsigned long long u64;

#define NMAX 50048

__device__ float g_S1[NMAX * 128];
__device__ float g_S2[NMAX * 128];
__device__ float g_h1[NMAX * 128];
__device__ float g_h2[NMAX * 128];
__device__ float g_deg[NMAX];
__device__ float g_B1[256 * 128];
__device__ float g_B2[256 * 128];
__device__ float g_c1[128];
__device__ float g_c2[128];
__device__ float g_B3[128 * 128];
__device__ float g_b3[128];
__device__ __nv_bfloat16 g_Bth[256 * 64];   // edge weights^T hi
__device__ __nv_bfloat16 g_Btl[256 * 64];   // edge weights^T lo
__device__ float g_biascat[256];
__device__ __nv_bfloat16 g_B1th[128 * 256], g_B1tl[128 * 256];  // node B^T splits
__device__ __nv_bfloat16 g_B2th[128 * 256], g_B2tl[128 * 256];
__device__ __nv_bfloat16 g_B3th[128 * 128], g_B3tl[128 * 128];

// ============================ helpers ======================================
__device__ __forceinline__ uint32_t smem_u32(const void* p) {
    uint32_t a;
    asm("{ .reg .u64 t; cvta.to.shared.u64 t, %1; cvt.u32.u64 %0, t; }" : "=r"(a) : "l"(p));
    return a;
}
__device__ __forceinline__ float lk(float v) { return fmaxf(v, 0.15f * v); }
__device__ __forceinline__ void red4(float* p, float a, float b, float c, float d) {
    asm volatile("red.global.add.v4.f32 [%0], {%1, %2, %3, %4};"
                 :: "l"((u64)(uintptr_t)p), "f"(a), "f"(b), "f"(c), "f"(d) : "memory");
}
// mma.sync m16n8k16 bf16 -> f32, accumulate in place
__device__ __forceinline__ void mma16816(float* c, const uint32_t* a,
                                         uint32_t b0, uint32_t b1) {
    asm volatile(
        "mma.sync.aligned.m16n8k16.row.col.f32.bf16.bf16.f32 "
        "{%0,%1,%2,%3}, {%4,%5,%6,%7}, {%8,%9}, {%0,%1,%2,%3};"
        : "+f"(c[0]), "+f"(c[1]), "+f"(c[2]), "+f"(c[3])
        : "r"(a[0]), "r"(a[1]), "r"(a[2]), "r"(a[3]), "r"(b0), "r"(b1));
}
__device__ __forceinline__ void ldsm_x4(uint32_t* r, uint32_t addr) {
    asm volatile("ldmatrix.sync.aligned.m8n8.x4.shared.b16 {%0,%1,%2,%3}, [%4];"
                 : "=r"(r[0]), "=r"(r[1]), "=r"(r[2]), "=r"(r[3]) : "r"(addr));
}
__device__ __forceinline__ void split2(float a0, float a1, uint32_t& h, uint32_t& l) {
    __nv_bfloat162 h2 = __floats2bfloat162_rn(a0, a1);
    __nv_bfloat162 l2 = __floats2bfloat162_rn(a0 - __low2float(h2), a1 - __high2float(h2));
    h = *(uint32_t*)&h2;
    l = *(uint32_t*)&l2;
}

// ======================= merged precompute =================================
__global__ void prep_all(const float* __restrict__ e1W2, const float* __restrict__ e1b2,
                         const float* __restrict__ n1W,  const float* __restrict__ n1b,
                         const float* __restrict__ e2W2, const float* __restrict__ e2b2,
                         const float* __restrict__ n2W,  const float* __restrict__ n2b,
                         const float* __restrict__ muW,  const float* __restrict__ mub,
                         const float* __restrict__ lvW,  const float* __restrict__ lvb,
                         const float* __restrict__ e1W1, const float* __restrict__ e1b1,
                         const float* __restrict__ e2W1, const float* __restrict__ e2b1,
                         float* __restrict__ B1, float* __restrict__ c1,
                         float* __restrict__ B2, float* __restrict__ c2,
                         float* __restrict__ B3, float* __restrict__ b3,
                         __nv_bfloat16* __restrict__ bth, __nv_bfloat16* __restrict__ btl,
                         float* __restrict__ bias) {
    const int task = blockIdx.y, bx = blockIdx.x, tid = threadIdx.x;
    if (task <= 1) {
        const float* eW2 = task ? e2W2 : e1W2;
        const float* eb2 = task ? e2b2 : e1b2;
        const float* nW  = task ? n2W  : n1W;
        const float* nb  = task ? n2b  : n1b;
        float* Bcat = task ? B2 : B1;
        float* c = task ? c2 : c1;
        int k = bx, j = tid;
        Bcat[k * 128 + j] = nW[k * 128 + j];
        float acc = 0.f;
        #pragma unroll 4
        for (int t = 0; t < 128; t++) acc += eW2[k * 128 + t] * nW[(128 + t) * 128 + j];
        Bcat[(128 + k) * 128 + j] = acc;
        if (k == 0) {
            float cc = nb[j];
            #pragma unroll 4
            for (int t = 0; t < 128; t++) cc += eb2[t] * nW[(128 + t) * 128 + j];
            c[j] = cc;
        }
    } else if (task == 2) {
        int k = bx, j = tid;
        B3[k * 128 + j] = (j < 64) ? muW[k * 64 + j] : lvW[k * 64 + (j - 64)];
        if (k == 0) b3[j] = (j < 64) ? mub[j] : lvb[j - 64];
    } else {
        int k = tid & 63, half = tid >> 6;
        int n = bx + half * 128;
        float w = (n < 128) ? e1W1[k * 128 + n] : e2W1[k * 128 + (n - 128)];
        __nv_bfloat16 h = __float2bfloat16(w);
        float r = w - __bfloat162float(h);
        bth[n * 64 + k] = h;
        btl[n * 64 + k] = __float2bfloat16(r);
        if (k == 0) bias[n] = (n < 128) ? e1b1[n] : e2b1[n - 128];
    }
}

// node-B transpose+split: Bt[n][k] = B[k][n], hi/lo bf16
__global__ void prep_btn(const float* __restrict__ B1, const float* __restrict__ B2,
                         const float* __restrict__ B3,
                         __nv_bfloat16* __restrict__ b1h, __nv_bfloat16* __restrict__ b1l,
                         __nv_bfloat16* __restrict__ b2h, __nv_bfloat16* __restrict__ b2l,
                         __nv_bfloat16* __restrict__ b3h, __nv_bfloat16* __restrict__ b3l) {
    const int task = blockIdx.y, n = blockIdx.x, k = threadIdx.x;
    const int KT = (task == 2) ? 128 : 256;
    if (k >= KT) return;
    const float* B = (task == 0) ? B1 : (task == 1) ? B2 : B3;
    __nv_bfloat16* bh = (task == 0) ? b1h : (task == 1) ? b2h : b3h;
    __nv_bfloat16* bl = (task == 0) ? b1l : (task == 1) ? b2l : b3l;
    float w = B[k * 128 + n];
    __nv_bfloat16 h = __float2bfloat16(w);
    bh[n * KT + k] = h;
    bl[n * KT + k] = __float2bfloat16(w - __bfloat162float(h));
}

__global__ void deg_kernel(const int* __restrict__ dst, float* __restrict__ deg, int E) {
    int e = blockIdx.x * blockDim.x + threadIdx.x;
    if (e < E) atomicAdd(&deg[dst[e]], 1.0f);
}

// ======================= mma.sync edge pass (R6 config) ====================
#define APITCH 144

__global__ __launch_bounds__(256, 1)
void edge_mma_kernel(const float* __restrict__ ea, const int* __restrict__ dstv,
                     const __nv_bfloat16* __restrict__ Bth,
                     const __nv_bfloat16* __restrict__ Btl,
                     const float* __restrict__ biascat,
                     float* __restrict__ S1, float* __restrict__ S2,
                     int E, int ntiles) {
    __shared__ __align__(16) char sA[2 * 128 * APITCH];  // hi | lo
    __shared__ float sBias[256];
    __shared__ int sDst[128];
    char* sAh = sA;
    char* sAl = sA + 128 * APITCH;

    const int tid = threadIdx.x, wid = tid >> 5, lane = tid & 31;
    const int g = lane >> 2, q = lane & 3;
    const int n0 = wid * 32;

    sBias[tid] = biascat[tid];

    uint32_t bh[4][4][2], bl[4][4][2];
    {
        const uint32_t* BH = (const uint32_t*)Bth;
        const uint32_t* BL = (const uint32_t*)Btl;
        #pragma unroll
        for (int nt = 0; nt < 4; nt++) {
            const int n = n0 + nt * 8 + g;
            #pragma unroll
            for (int kt = 0; kt < 4; kt++) {
                const int base = n * 32 + kt * 8 + q;
                bh[nt][kt][0] = BH[base];
                bh[nt][kt][1] = BH[base + 4];
                bl[nt][kt][0] = BL[base];
                bl[nt][kt][1] = BL[base + 4];
            }
        }
    }

    const int rowoff = (lane & 7) + ((lane >> 3) & 1) * 8;
    const int koff = (lane >> 4) * 16;
    const uint32_t sAh_u = smem_u32(sAh);
    const uint32_t sAl_u = smem_u32(sAl);
    const uint32_t lmBase = (uint32_t)(rowoff * APITCH + koff);

    for (int tile = blockIdx.x; tile < ntiles; tile += gridDim.x) {
        const int e0 = tile * 128;
        {
            const int row = tid >> 1, hf = tid & 1;
            const int ge = e0 + row;
            uint32_t* ah = (uint32_t*)(sAh + row * APITCH + hf * 64);
            uint32_t* al = (uint32_t*)(sAl + row * APITCH + hf * 64);
            if (ge < E) {
                const float4* src = (const float4*)(ea + (size_t)ge * 64 + hf * 32);
                #pragma unroll
                for (int j = 0; j < 8; j++) {
                    float4 v = src[j];
                    uint32_t h0, l0, h1, l1;
                    split2(v.x, v.y, h0, l0);
                    split2(v.z, v.w, h1, l1);
                    ah[j * 2] = h0; ah[j * 2 + 1] = h1;
                    al[j * 2] = l0; al[j * 2 + 1] = l1;
                }
            } else {
                #pragma unroll
                for (int j = 0; j < 16; j++) { ah[j] = 0u; al[j] = 0u; }
            }
            if (hf == 0) sDst[row] = (ge < E) ? dstv[ge] : -1;
        }
        __syncthreads();

        float acc[8][4][4];
        #pragma unroll
        for (int mt = 0; mt < 8; mt++)
            #pragma unroll
            for (int nt = 0; nt < 4; nt++)
                #pragma unroll
                for (int i = 0; i < 4; i++) acc[mt][nt][i] = 0.f;

        #pragma unroll
        for (int mt = 0; mt < 8; mt++) {
            const uint32_t mtOff = (uint32_t)(mt * 16 * APITCH) + lmBase;
            #pragma unroll
            for (int kt = 0; kt < 4; kt++) {
                uint32_t ah4[4], al4[4];
                ldsm_x4(ah4, sAh_u + mtOff + kt * 32);
                ldsm_x4(al4, sAl_u + mtOff + kt * 32);
                #pragma unroll
                for (int nt = 0; nt < 4; nt++) {
                    mma16816(acc[mt][nt], ah4, bh[nt][kt][0], bh[nt][kt][1]);
                    mma16816(acc[mt][nt], al4, bh[nt][kt][0], bh[nt][kt][1]);
                    mma16816(acc[mt][nt], ah4, bl[nt][kt][0], bl[nt][kt][1]);
                }
            }
        }

        #pragma unroll
        for (int mt = 0; mt < 8; mt++) {
            const int rowLo = mt * 16 + g;
            const int dLo = sDst[rowLo], dHi = sDst[rowLo + 8];
            #pragma unroll
            for (int nt = 0; nt < 4; nt++) {
                float* c = acc[mt][nt];
                const int col = n0 + nt * 8 + q * 2;
                const float b0 = sBias[col], b1 = sBias[col + 1];
                float v0 = lk(c[0] + b0), v1 = lk(c[1] + b1);
                float v2 = lk(c[2] + b0), v3 = lk(c[3] + b1);
                float r0 = __shfl_xor_sync(0xffffffffu, v0, 1);
                float r1 = __shfl_xor_sync(0xffffffffu, v1, 1);
                float r2 = __shfl_xor_sync(0xffffffffu, v2, 1);
                float r3 = __shfl_xor_sync(0xffffffffu, v3, 1);
                const int colb = n0 + nt * 8 + (q >> 1) * 4;
                int d;
                float w0, w1, w2, w3;
                if ((q & 1) == 0) { d = dLo; w0 = v0; w1 = v1; w2 = r0; w3 = r1; }
                else              { d = dHi; w0 = r2; w1 = r3; w2 = v2; w3 = v3; }
                if (d >= 0) {
                    float* Sp = (n0 < 128) ? (S1 + (size_t)d * 128 + colb)
                                           : (S2 + (size_t)d * 128 + (colb - 128));
                    red4(Sp, w0, w1, w2, w3);
                }
            }
        }
        __syncthreads();
    }
}

// ======================= tensor node GEMM ==================================
// Tile 128 rows (M) x 128 cols (N), K chunked by 64. Warp w: mhalf=w>>2 picks
// 64-row half, (w&3)*32 = col slice. A staged fp32->bf16 hi/lo on the fly
// (deg-scaled for the A1 part when SECOND); B pre-split, copied per chunk.
// D += Ah*Bh + Al*Bh + Ah*Bl.
#define NSM_AH 0
#define NSM_AL 18432
#define NSM_BH 36864
#define NSM_BL 55296
#define NSM_BIAS 73728
#define NSM_DEG 74304
#define NODE_SMEM 74880

template <int KTOT, bool SECOND, bool DOLEAKY, bool SPLIT>
__global__ __launch_bounds__(256, 1) void node_mma(
    const float* __restrict__ A1, const float* __restrict__ A2,
    const __nv_bfloat16* __restrict__ Bth, const __nv_bfloat16* __restrict__ Btl,
    const float* __restrict__ bias, const float* __restrict__ deg,
    float* __restrict__ out, int N) {
    extern __shared__ __align__(16) char smem[];
    char* sAh = smem + NSM_AH;
    char* sAl = smem + NSM_AL;
    char* sBh = smem + NSM_BH;
    char* sBl = smem + NSM_BL;
    float* sBias = (float*)(smem + NSM_BIAS);
    float* sDeg = (float*)(smem + NSM_DEG);

    const int tid = threadIdx.x, wid = tid >> 5, lane = tid & 31;
    const int g = lane >> 2, q = lane & 3;
    const int mhalf = wid >> 2;
    const int n0 = (wid & 3) * 32;
    const int row0 = blockIdx.x * 128;

    if (tid < 128) {
        sBias[tid] = bias[tid];
        if (SECOND) {
            int r = row0 + tid;
            sDeg[tid] = (r < N) ? deg[r] : 0.f;
        }
    }
    __syncthreads();

    // acc init: SECOND -> deg*bias (deg folded into A1 part), else bias.
    float acc[4][4][4];
    #pragma unroll
    for (int mt = 0; mt < 4; mt++) {
        const int rl = mhalf * 64 + mt * 16 + g;
        const float d0 = SECOND ? sDeg[rl] : 1.f;
        const float d1 = SECOND ? sDeg[rl + 8] : 1.f;
        #pragma unroll
        for (int nt = 0; nt < 4; nt++) {
            const int col = n0 + nt * 8 + 2 * q;
            const float b0 = sBias[col], b1 = sBias[col + 1];
            acc[mt][nt][0] = d0 * b0;
            acc[mt][nt][1] = d0 * b1;
            acc[mt][nt][2] = d1 * b0;
            acc[mt][nt][3] = d1 * b1;
        }
    }

    const int rowoff = (lane & 7) + ((lane >> 3) & 1) * 8;
    const uint32_t sAh_u = smem_u32(sAh);
    const uint32_t sAl_u = smem_u32(sAl);
    const uint32_t sBh_u = smem_u32(sBh);
    const uint32_t sBl_u = smem_u32(sBl);
    const uint32_t aBase = (uint32_t)((mhalf * 64 + rowoff) * APITCH + (lane >> 4) * 16);
    const uint32_t bBase = (uint32_t)((n0 + (lane & 7)) * APITCH + ((lane >> 3) & 3) * 16);

    for (int kc = 0; kc < KTOT; kc += 64) {
        __syncthreads();
        // ---- stage A chunk (convert + optional deg scale) ----
        {
            const int row = tid >> 1, hf = tid & 1;
            const int grow = row0 + row;
            uint32_t* ah = (uint32_t*)(sAh + row * APITCH + hf * 64);
            uint32_t* al = (uint32_t*)(sAl + row * APITCH + hf * 64);
            if (grow < N) {
                const bool a1part = (!SECOND) || (kc < 128);
                const int ksrc = (a1part ? kc : kc - 128) + hf * 32;
                const float* Arow = (a1part ? A1 : A2) + (size_t)grow * 128 + ksrc;
                const float s = (SECOND && a1part) ? sDeg[row] : 1.f;
                const float4* src = (const float4*)Arow;
                #pragma unroll
                for (int j = 0; j < 8; j++) {
                    float4 v = src[j];
                    v.x *= s; v.y *= s; v.z *= s; v.w *= s;
                    uint32_t h0, l0, h1, l1;
                    split2(v.x, v.y, h0, l0);
                    split2(v.z, v.w, h1, l1);
                    ah[j * 2] = h0; ah[j * 2 + 1] = h1;
                    al[j * 2] = l0; al[j * 2 + 1] = l1;
                }
            } else {
                #pragma unroll
                for (int j = 0; j < 16; j++) { ah[j] = 0u; al[j] = 0u; }
            }
        }
        // ---- stage B chunk (pre-split copy): 64 bytes per (n, half) ----
        {
            const int n = tid >> 1, hf = tid & 1;
            const uint4* bh4 = (const uint4*)(Bth + (size_t)n * KTOT + kc + hf * 32);
            const uint4* bl4 = (const uint4*)(Btl + (size_t)n * KTOT + kc + hf * 32);
            uint4* dh = (uint4*)(sBh + n * APITCH + hf * 64);
            uint4* dl = (uint4*)(sBl + n * APITCH + hf * 64);
            dh[0] = bh4[0]; dh[1] = bh4[1]; dh[2] = bh4[2]; dh[3] = bh4[3];
            dl[0] = bl4[0]; dl[1] = bl4[1]; dl[2] = bl4[2]; dl[3] = bl4[3];
        }
        __syncthreads();

        // ---- MMA ----
        #pragma unroll
        for (int ktp = 0; ktp < 2; ktp++) {
            uint32_t bhf[4][4], blf[4][4];
            #pragma unroll
            for (int nt = 0; nt < 4; nt++) {
                ldsm_x4(bhf[nt], sBh_u + bBase + (uint32_t)(nt * 8 * APITCH) + ktp * 64);
                ldsm_x4(blf[nt], sBl_u + bBase + (uint32_t)(nt * 8 * APITCH) + ktp * 64);
            }
            #pragma unroll
            for (int mt = 0; mt < 4; mt++) {
                #pragma unroll
                for (int kt2 = 0; kt2 < 2; kt2++) {
                    uint32_t ah4[4], al4[4];
                    const uint32_t ao = aBase + (uint32_t)(mt * 16 * APITCH) +
                                        ktp * 64 + kt2 * 32;
                    ldsm_x4(ah4, sAh_u + ao);
                    ldsm_x4(al4, sAl_u + ao);
                    #pragma unroll
                    for (int nt = 0; nt < 4; nt++) {
                        mma16816(acc[mt][nt], ah4, bhf[nt][kt2 * 2], bhf[nt][kt2 * 2 + 1]);
                        mma16816(acc[mt][nt], al4, bhf[nt][kt2 * 2], bhf[nt][kt2 * 2 + 1]);
                        mma16816(acc[mt][nt], ah4, blf[nt][kt2 * 2], blf[nt][kt2 * 2 + 1]);
                    }
                }
            }
        }
    }

    // ---- epilogue ----
    #pragma unroll
    for (int mt = 0; mt < 4; mt++) {
        const int r0g = row0 + mhalf * 64 + mt * 16 + g;
        #pragma unroll
        for (int nt = 0; nt < 4; nt++) {
            float* c = acc[mt][nt];
            const int col = n0 + nt * 8 + 2 * q;
            float v0 = c[0], v1 = c[1], v2 = c[2], v3 = c[3];
            if (DOLEAKY) { v0 = lk(v0); v1 = lk(v1); v2 = lk(v2); v3 = lk(v3); }
            if (!SPLIT) {
                if (r0g < N)     *(float2*)&out[(size_t)r0g * 128 + col] = make_float2(v0, v1);
                if (r0g + 8 < N) *(float2*)&out[(size_t)(r0g + 8) * 128 + col] = make_float2(v2, v3);
            } else {
                float* dstp = (col < 64) ? (out + (size_t)0 * 64)
                                         : (out + (size_t)N * 64 - 64);
                if (r0g < N)     *(float2*)&dstp[(size_t)r0g * 64 + col] = make_float2(v0, v1);
                if (r0g + 8 < N) *(float2*)&dstp[(size_t)(r0g + 8) * 64 + col] = make_float2(v2, v3);
            }
        }
    }
}

// ---------------------------------------------------------------------------
extern "C" void kernel_launch(void* const* d_in, const int* in_sizes, int n_in,
                              void* d_out, int out_size) {
    const float* x    = (const float*)d_in[0];
    const int*   ei   = (const int*)d_in[1];
    const float* ea   = (const float*)d_in[2];
    const float* e1W1 = (const float*)d_in[3];
    const float* e1b1 = (const float*)d_in[4];
    const float* e1W2 = (const float*)d_in[5];
    const float* e1b2 = (const float*)d_in[6];
    const float* n1W  = (const float*)d_in[7];
    const float* n1b  = (const float*)d_in[8];
    const float* e2W1 = (const float*)d_in[9];
    const float* e2b1 = (const float*)d_in[10];
    const float* e2W2 = (const float*)d_in[11];
    const float* e2b2 = (const float*)d_in[12];
    const float* n2W  = (const float*)d_in[13];
    const float* n2b  = (const float*)d_in[14];
    const float* muW  = (const float*)d_in[15];
    const float* mub  = (const float*)d_in[16];
    const float* lvW  = (const float*)d_in[17];
    const float* lvb  = (const float*)d_in[18];

    const int N = in_sizes[0] / 128;  // 50000
    const int E = in_sizes[2] / 64;   // 640000
    const int* dst = ei + E;          // edge_index row 1

    float *S1, *S2, *h1, *h2, *dg, *B1, *B2, *c1, *c2, *B3, *b3, *biascat;
    __nv_bfloat16 *Bth, *Btl, *B1th, *B1tl, *B2th, *B2tl, *B3th, *B3tl;
    cudaGetSymbolAddress((void**)&S1, g_S1);
    cudaGetSymbolAddress((void**)&S2, g_S2);
    cudaGetSymbolAddress((void**)&h1, g_h1);
    cudaGetSymbolAddress((void**)&h2, g_h2);
    cudaGetSymbolAddress((void**)&dg, g_deg);
    cudaGetSymbolAddress((void**)&B1, g_B1);
    cudaGetSymbolAddress((void**)&B2, g_B2);
    cudaGetSymbolAddress((void**)&c1, g_c1);
    cudaGetSymbolAddress((void**)&c2, g_c2);
    cudaGetSymbolAddress((void**)&B3, g_B3);
    cudaGetSymbolAddress((void**)&b3, g_b3);
    cudaGetSymbolAddress((void**)&Bth, g_Bth);
    cudaGetSymbolAddress((void**)&Btl, g_Btl);
    cudaGetSymbolAddress((void**)&biascat, g_biascat);
    cudaGetSymbolAddress((void**)&B1th, g_B1th);
    cudaGetSymbolAddress((void**)&B1tl, g_B1tl);
    cudaGetSymbolAddress((void**)&B2th, g_B2th);
    cudaGetSymbolAddress((void**)&B2tl, g_B2tl);
    cudaGetSymbolAddress((void**)&B3th, g_B3th);
    cudaGetSymbolAddress((void**)&B3tl, g_B3tl);

    cudaMemsetAsync(S1, 0, (size_t)N * 128 * sizeof(float));
    cudaMemsetAsync(S2, 0, (size_t)N * 128 * sizeof(float));
    cudaMemsetAsync(dg, 0, (size_t)N * sizeof(float));

    prep_all<<<dim3(128, 4), 128>>>(e1W2, e1b2, n1W, n1b,
                                    e2W2, e2b2, n2W, n2b,
                                    muW, mub, lvW, lvb,
                                    e1W1, e1b1, e2W1, e2b1,
                                    B1, c1, B2, c2, B3, b3, Bth, Btl, biascat);
    prep_btn<<<dim3(128, 3), 256>>>(B1, B2, B3, B1th, B1tl, B2th, B2tl, B3th, B3tl);
    deg_kernel<<<(E + 255) / 256, 256>>>(dst, dg, E);

    int ntiles = (E + 127) / 128;
    int egrid = ntiles < 148 ? ntiles : 148;
    edge_mma_kernel<<<egrid, 256>>>(ea, dst, Bth, Btl, biascat, S1, S2, E, ntiles);

    int nblk = (N + 127) / 128;  // 391
    cudaFuncSetAttribute(node_mma<256, true, true, false>,
                         cudaFuncAttributeMaxDynamicSharedMemorySize, NODE_SMEM);
    cudaFuncSetAttribute(node_mma<128, false, false, true>,
                         cudaFuncAttributeMaxDynamicSharedMemorySize, NODE_SMEM);

    node_mma<256, true, true, false><<<nblk, 256, NODE_SMEM>>>(x,  S1, B1th, B1tl, c1, dg, h1, N);
    node_mma<256, true, true, false><<<nblk, 256, NODE_SMEM>>>(h1, S2, B2th, B2tl, c2, dg, h2, N);
    node_mma<128, false, false, true><<<nblk, 256, NODE_SMEM>>>(h2, nullptr, B3th, B3tl, b3,
                                                                nullptr, (float*)d_out, N);
}

// round 11
// speedup vs baseline: 1.4875x; 1.0274x over previous
#include <cuda_runtime.h>
#include <cuda_bf16.h>
#include <cstdint>
#include <cstdio>

// ---------------------------------------------------------------------------
// EdgeVGAE encoder, algebraically collapsed:
//   S_l = segment_sum(leaky(edge_attr @ W1_l + b1_l), dst)   (edge pass, l=1,2)
//   h1  = leaky(deg*(x @ n1Wx + c1) + S1 @ M1)
//   h2  = leaky(deg*(h1 @ n2Wh + c2) + S2 @ M2)
//   mu|lv = h2 @ [muW|lvW] + [mub|lvb]
// R11: edge kernel split into 128-thread CTAs (one layer's 128 cols each)
// -> 2 CTAs/SM co-residency; stage/sync/epilogue of one CTA overlaps the
// other's MMA (R10 profile: tensor only 28.9% busy at 1 CTA/SM).
// ---------------------------------------------------------------------------

typedef unsigned long long u64;

#define NMAX 50048

__device__ float g_S1[NMAX * 128];
__device__ float g_S2[NMAX * 128];
__device__ float g_h1[NMAX * 128];
__device__ float g_h2[NMAX * 128];
__device__ float g_deg[NMAX];
__device__ float g_B1[256 * 128];
__device__ float g_B2[256 * 128];
__device__ float g_c1[128];
__device__ float g_c2[128];
__device__ float g_B3[128 * 128];
__device__ float g_b3[128];
__device__ __nv_bfloat16 g_Bth[256 * 64];   // edge weights^T hi
__device__ __nv_bfloat16 g_Btl[256 * 64];   // edge weights^T lo
__device__ float g_biascat[256];
__device__ __nv_bfloat16 g_B1th[128 * 256], g_B1tl[128 * 256];  // node B^T splits
__device__ __nv_bfloat16 g_B2th[128 * 256], g_B2tl[128 * 256];
__device__ __nv_bfloat16 g_B3th[128 * 128], g_B3tl[128 * 128];

// ============================ helpers ======================================
__device__ __forceinline__ uint32_t smem_u32(const void* p) {
    uint32_t a;
    asm("{ .reg .u64 t; cvta.to.shared.u64 t, %1; cvt.u32.u64 %0, t; }" : "=r"(a) : "l"(p));
    return a;
}
__device__ __forceinline__ float lk(float v) { return fmaxf(v, 0.15f * v); }
__device__ __forceinline__ void red4(float* p, float a, float b, float c, float d) {
    asm volatile("red.global.add.v4.f32 [%0], {%1, %2, %3, %4};"
                 :: "l"((u64)(uintptr_t)p), "f"(a), "f"(b), "f"(c), "f"(d) : "memory");
}
// mma.sync m16n8k16 bf16 -> f32, accumulate in place
__device__ __forceinline__ void mma16816(float* c, const uint32_t* a,
                                         uint32_t b0, uint32_t b1) {
    asm volatile(
        "mma.sync.aligned.m16n8k16.row.col.f32.bf16.bf16.f32 "
        "{%0,%1,%2,%3}, {%4,%5,%6,%7}, {%8,%9}, {%0,%1,%2,%3};"
        : "+f"(c[0]), "+f"(c[1]), "+f"(c[2]), "+f"(c[3])
        : "r"(a[0]), "r"(a[1]), "r"(a[2]), "r"(a[3]), "r"(b0), "r"(b1));
}
__device__ __forceinline__ void ldsm_x4(uint32_t* r, uint32_t addr) {
    asm volatile("ldmatrix.sync.aligned.m8n8.x4.shared.b16 {%0,%1,%2,%3}, [%4];"
                 : "=r"(r[0]), "=r"(r[1]), "=r"(r[2]), "=r"(r[3]) : "r"(addr));
}
__device__ __forceinline__ void split2(float a0, float a1, uint32_t& h, uint32_t& l) {
    __nv_bfloat162 h2 = __floats2bfloat162_rn(a0, a1);
    __nv_bfloat162 l2 = __floats2bfloat162_rn(a0 - __low2float(h2), a1 - __high2float(h2));
    h = *(uint32_t*)&h2;
    l = *(uint32_t*)&l2;
}

// ======================= merged precompute =================================
__global__ void prep_all(const float* __restrict__ e1W2, const float* __restrict__ e1b2,
                         const float* __restrict__ n1W,  const float* __restrict__ n1b,
                         const float* __restrict__ e2W2, const float* __restrict__ e2b2,
                         const float* __restrict__ n2W,  const float* __restrict__ n2b,
                         const float* __restrict__ muW,  const float* __restrict__ mub,
                         const float* __restrict__ lvW,  const float* __restrict__ lvb,
                         const float* __restrict__ e1W1, const float* __restrict__ e1b1,
                         const float* __restrict__ e2W1, const float* __restrict__ e2b1,
                         float* __restrict__ B1, float* __restrict__ c1,
                         float* __restrict__ B2, float* __restrict__ c2,
                         float* __restrict__ B3, float* __restrict__ b3,
                         __nv_bfloat16* __restrict__ bth, __nv_bfloat16* __restrict__ btl,
                         float* __restrict__ bias) {
    const int task = blockIdx.y, bx = blockIdx.x, tid = threadIdx.x;
    if (task <= 1) {
        const float* eW2 = task ? e2W2 : e1W2;
        const float* eb2 = task ? e2b2 : e1b2;
        const float* nW  = task ? n2W  : n1W;
        const float* nb  = task ? n2b  : n1b;
        float* Bcat = task ? B2 : B1;
        float* c = task ? c2 : c1;
        int k = bx, j = tid;
        Bcat[k * 128 + j] = nW[k * 128 + j];
        float acc = 0.f;
        #pragma unroll 4
        for (int t = 0; t < 128; t++) acc += eW2[k * 128 + t] * nW[(128 + t) * 128 + j];
        Bcat[(128 + k) * 128 + j] = acc;
        if (k == 0) {
            float cc = nb[j];
            #pragma unroll 4
            for (int t = 0; t < 128; t++) cc += eb2[t] * nW[(128 + t) * 128 + j];
            c[j] = cc;
        }
    } else if (task == 2) {
        int k = bx, j = tid;
        B3[k * 128 + j] = (j < 64) ? muW[k * 64 + j] : lvW[k * 64 + (j - 64)];
        if (k == 0) b3[j] = (j < 64) ? mub[j] : lvb[j - 64];
    } else {
        int k = tid & 63, half = tid >> 6;
        int n = bx + half * 128;
        float w = (n < 128) ? e1W1[k * 128 + n] : e2W1[k * 128 + (n - 128)];
        __nv_bfloat16 h = __float2bfloat16(w);
        float r = w - __bfloat162float(h);
        bth[n * 64 + k] = h;
        btl[n * 64 + k] = __float2bfloat16(r);
        if (k == 0) bias[n] = (n < 128) ? e1b1[n] : e2b1[n - 128];
    }
}

// node-B transpose+split: Bt[n][k] = B[k][n], hi/lo bf16
__global__ void prep_btn(const float* __restrict__ B1, const float* __restrict__ B2,
                         const float* __restrict__ B3,
                         __nv_bfloat16* __restrict__ b1h, __nv_bfloat16* __restrict__ b1l,
                         __nv_bfloat16* __restrict__ b2h, __nv_bfloat16* __restrict__ b2l,
                         __nv_bfloat16* __restrict__ b3h, __nv_bfloat16* __restrict__ b3l) {
    const int task = blockIdx.y, n = blockIdx.x, k = threadIdx.x;
    const int KT = (task == 2) ? 128 : 256;
    if (k >= KT) return;
    const float* B = (task == 0) ? B1 : (task == 1) ? B2 : B3;
    __nv_bfloat16* bh = (task == 0) ? b1h : (task == 1) ? b2h : b3h;
    __nv_bfloat16* bl = (task == 0) ? b1l : (task == 1) ? b2l : b3l;
    float w = B[k * 128 + n];
    __nv_bfloat16 h = __float2bfloat16(w);
    bh[n * KT + k] = h;
    bl[n * KT + k] = __float2bfloat16(w - __bfloat162float(h));
}

__global__ void deg_kernel(const int* __restrict__ dst, float* __restrict__ deg, int E) {
    int e = blockIdx.x * blockDim.x + threadIdx.x;
    if (e < E) atomicAdd(&deg[dst[e]], 1.0f);
}

// ======================= mma.sync edge pass ================================
// 128-thread CTA (4 warps), tile = 128 edges x ONE layer's 128 cols, K=64.
// layer = blockIdx.x & 1 (fixed per CTA -> B frags stay register-resident).
// 2 CTAs co-resident per SM overlap staging/epilogue with MMA.
#define APITCH 144

__global__ __launch_bounds__(128, 2)
void edge_mma_kernel(const float* __restrict__ ea, const int* __restrict__ dstv,
                     const __nv_bfloat16* __restrict__ Bth,
                     const __nv_bfloat16* __restrict__ Btl,
                     const float* __restrict__ biascat,
                     float* __restrict__ S1, float* __restrict__ S2,
                     int E, int ntiles) {
    __shared__ __align__(16) char sA[2 * 128 * APITCH];  // hi | lo
    __shared__ float sBias[128];
    __shared__ int sDst[128];
    char* sAh = sA;
    char* sAl = sA + 128 * APITCH;

    const int tid = threadIdx.x, wid = tid >> 5, lane = tid & 31;
    const int g = lane >> 2, q = lane & 3;
    const int layer = blockIdx.x & 1;
    const int nbase = layer * 128;
    const int n0 = wid * 32;                 // 0..96 within layer
    float* Sbase = layer ? S2 : S1;

    sBias[tid] = biascat[nbase + tid];

    // ---- B fragments in registers (once; layer fixed per CTA) ----
    uint32_t bh[4][4][2], bl[4][4][2];
    {
        const uint32_t* BH = (const uint32_t*)Bth;
        const uint32_t* BL = (const uint32_t*)Btl;
        #pragma unroll
        for (int nt = 0; nt < 4; nt++) {
            const int n = nbase + n0 + nt * 8 + g;
            #pragma unroll
            for (int kt = 0; kt < 4; kt++) {
                const int base = n * 32 + kt * 8 + q;
                bh[nt][kt][0] = BH[base];
                bh[nt][kt][1] = BH[base + 4];
                bl[nt][kt][0] = BL[base];
                bl[nt][kt][1] = BL[base + 4];
            }
        }
    }

    const int rowoff = (lane & 7) + ((lane >> 3) & 1) * 8;
    const int koff = (lane >> 4) * 16;
    const uint32_t sAh_u = smem_u32(sAh);
    const uint32_t sAl_u = smem_u32(sAl);
    const uint32_t lmBase = (uint32_t)(rowoff * APITCH + koff);

    const int cstride = gridDim.x >> 1;      // tiles stride (one per layer pair)
    for (int tile = blockIdx.x >> 1; tile < ntiles; tile += cstride) {
        const int e0 = tile * 128;
        // ---- stage A tile: thread = row, two 32-float half-batches ----
        {
            const int ge = e0 + tid;
            uint32_t* ah = (uint32_t*)(sAh + tid * APITCH);
            uint32_t* al = (uint32_t*)(sAl + tid * APITCH);
            if (ge < E) {
                const float4* src = (const float4*)(ea + (size_t)ge * 64);
                #pragma unroll 1
                for (int hb = 0; hb < 2; hb++) {
                    #pragma unroll
                    for (int j = 0; j < 8; j++) {
                        float4 v = src[hb * 8 + j];
                        uint32_t h0, l0, h1, l1;
                        split2(v.x, v.y, h0, l0);
                        split2(v.z, v.w, h1, l1);
                        ah[hb * 16 + j * 2]     = h0;
                        ah[hb * 16 + j * 2 + 1] = h1;
                        al[hb * 16 + j * 2]     = l0;
                        al[hb * 16 + j * 2 + 1] = l1;
                    }
                }
                sDst[tid] = dstv[ge];
            } else {
                #pragma unroll
                for (int j = 0; j < 32; j++) { ah[j] = 0u; al[j] = 0u; }
                sDst[tid] = -1;
            }
        }
        __syncthreads();

        // ---- mainloop: 128 rows x 32 cols per warp ----
        float acc[8][4][4];
        #pragma unroll
        for (int mt = 0; mt < 8; mt++)
            #pragma unroll
            for (int nt = 0; nt < 4; nt++)
                #pragma unroll
                for (int i = 0; i < 4; i++) acc[mt][nt][i] = 0.f;

        #pragma unroll
        for (int mt = 0; mt < 8; mt++) {
            const uint32_t mtOff = (uint32_t)(mt * 16 * APITCH) + lmBase;
            #pragma unroll
            for (int kt = 0; kt < 4; kt++) {
                uint32_t ah4[4], al4[4];
                ldsm_x4(ah4, sAh_u + mtOff + kt * 32);
                ldsm_x4(al4, sAl_u + mtOff + kt * 32);
                #pragma unroll
                for (int nt = 0; nt < 4; nt++) {
                    mma16816(acc[mt][nt], ah4, bh[nt][kt][0], bh[nt][kt][1]);
                    mma16816(acc[mt][nt], al4, bh[nt][kt][0], bh[nt][kt][1]);
                    mma16816(acc[mt][nt], ah4, bl[nt][kt][0], bl[nt][kt][1]);
                }
            }
        }

        // ---- epilogue: bias + leaky + quad-pack + red4 scatter ----
        #pragma unroll
        for (int mt = 0; mt < 8; mt++) {
            const int rowLo = mt * 16 + g;
            const int dLo = sDst[rowLo], dHi = sDst[rowLo + 8];
            #pragma unroll
            for (int nt = 0; nt < 4; nt++) {
                float* c = acc[mt][nt];
                const int col = n0 + nt * 8 + q * 2;
                const float b0 = sBias[col], b1 = sBias[col + 1];
                float v0 = lk(c[0] + b0), v1 = lk(c[1] + b1);
                float v2 = lk(c[2] + b0), v3 = lk(c[3] + b1);
                float r0 = __shfl_xor_sync(0xffffffffu, v0, 1);
                float r1 = __shfl_xor_sync(0xffffffffu, v1, 1);
                float r2 = __shfl_xor_sync(0xffffffffu, v2, 1);
                float r3 = __shfl_xor_sync(0xffffffffu, v3, 1);
                const int colb = n0 + nt * 8 + (q >> 1) * 4;
                int d;
                float w0, w1, w2, w3;
                if ((q & 1) == 0) { d = dLo; w0 = v0; w1 = v1; w2 = r0; w3 = r1; }
                else              { d = dHi; w0 = r2; w1 = r3; w2 = v2; w3 = v3; }
                if (d >= 0)
                    red4(&Sbase[(size_t)d * 128 + colb], w0, w1, w2, w3);
            }
        }
        __syncthreads();
    }
}

// ======================= tensor node GEMM (R10, known-good) ================
#define NSM_AH 0
#define NSM_AL 18432
#define NSM_BH 36864
#define NSM_BL 55296
#define NSM_BIAS 73728
#define NSM_DEG 74304
#define NODE_SMEM 74880

template <int KTOT, bool SECOND, bool DOLEAKY, bool SPLIT>
__global__ __launch_bounds__(256, 1) void node_mma(
    const float* __restrict__ A1, const float* __restrict__ A2,
    const __nv_bfloat16* __restrict__ Bth, const __nv_bfloat16* __restrict__ Btl,
    const float* __restrict__ bias, const float* __restrict__ deg,
    float* __restrict__ out, int N) {
    extern __shared__ __align__(16) char smem[];
    char* sAh = smem + NSM_AH;
    char* sAl = smem + NSM_AL;
    char* sBh = smem + NSM_BH;
    char* sBl = smem + NSM_BL;
    float* sBias = (float*)(smem + NSM_BIAS);
    float* sDeg = (float*)(smem + NSM_DEG);

    const int tid = threadIdx.x, wid = tid >> 5, lane = tid & 31;
    const int g = lane >> 2, q = lane & 3;
    const int mhalf = wid >> 2;
    const int n0 = (wid & 3) * 32;
    const int row0 = blockIdx.x * 128;

    if (tid < 128) {
        sBias[tid] = bias[tid];
        if (SECOND) {
            int r = row0 + tid;
            sDeg[tid] = (r < N) ? deg[r] : 0.f;
        }
    }
    __syncthreads();

    float acc[4][4][4];
    #pragma unroll
    for (int mt = 0; mt < 4; mt++) {
        const int rl = mhalf * 64 + mt * 16 + g;
        const float d0 = SECOND ? sDeg[rl] : 1.f;
        const float d1 = SECOND ? sDeg[rl + 8] : 1.f;
        #pragma unroll
        for (int nt = 0; nt < 4; nt++) {
            const int col = n0 + nt * 8 + 2 * q;
            const float b0 = sBias[col], b1 = sBias[col + 1];
            acc[mt][nt][0] = d0 * b0;
            acc[mt][nt][1] = d0 * b1;
            acc[mt][nt][2] = d1 * b0;
            acc[mt][nt][3] = d1 * b1;
        }
    }

    const int rowoff = (lane & 7) + ((lane >> 3) & 1) * 8;
    const uint32_t sAh_u = smem_u32(sAh);
    const uint32_t sAl_u = smem_u32(sAl);
    const uint32_t sBh_u = smem_u32(sBh);
    const uint32_t sBl_u = smem_u32(sBl);
    const uint32_t aBase = (uint32_t)((mhalf * 64 + rowoff) * APITCH + (lane >> 4) * 16);
    const uint32_t bBase = (uint32_t)((n0 + (lane & 7)) * APITCH + ((lane >> 3) & 3) * 16);

    for (int kc = 0; kc < KTOT; kc += 64) {
        __syncthreads();
        // ---- stage A chunk ----
        {
            const int row = tid >> 1, hf = tid & 1;
            const int grow = row0 + row;
            uint32_t* ah = (uint32_t*)(sAh + row * APITCH + hf * 64);
            uint32_t* al = (uint32_t*)(sAl + row * APITCH + hf * 64);
            if (grow < N) {
                const bool a1part = (!SECOND) || (kc < 128);
                const int ksrc = (a1part ? kc : kc - 128) + hf * 32;
                const float* Arow = (a1part ? A1 : A2) + (size_t)grow * 128 + ksrc;
                const float s = (SECOND && a1part) ? sDeg[row] : 1.f;
                const float4* src = (const float4*)Arow;
                #pragma unroll
                for (int j = 0; j < 8; j++) {
                    float4 v = src[j];
                    v.x *= s; v.y *= s; v.z *= s; v.w *= s;
                    uint32_t h0, l0, h1, l1;
                    split2(v.x, v.y, h0, l0);
                    split2(v.z, v.w, h1, l1);
                    ah[j * 2] = h0; ah[j * 2 + 1] = h1;
                    al[j * 2] = l0; al[j * 2 + 1] = l1;
                }
            } else {
                #pragma unroll
                for (int j = 0; j < 16; j++) { ah[j] = 0u; al[j] = 0u; }
            }
        }
        // ---- stage B chunk: 64 bytes per (n, half) ----
        {
            const int n = tid >> 1, hf = tid & 1;
            const uint4* bh4 = (const uint4*)(Bth + (size_t)n * KTOT + kc + hf * 32);
            const uint4* bl4 = (const uint4*)(Btl + (size_t)n * KTOT + kc + hf * 32);
            uint4* dh = (uint4*)(sBh + n * APITCH + hf * 64);
            uint4* dl = (uint4*)(sBl + n * APITCH + hf * 64);
            dh[0] = bh4[0]; dh[1] = bh4[1]; dh[2] = bh4[2]; dh[3] = bh4[3];
            dl[0] = bl4[0]; dl[1] = bl4[1]; dl[2] = bl4[2]; dl[3] = bl4[3];
        }
        __syncthreads();

        // ---- MMA ----
        #pragma unroll
        for (int ktp = 0; ktp < 2; ktp++) {
            uint32_t bhf[4][4], blf[4][4];
            #pragma unroll
            for (int nt = 0; nt < 4; nt++) {
                ldsm_x4(bhf[nt], sBh_u + bBase + (uint32_t)(nt * 8 * APITCH) + ktp * 64);
                ldsm_x4(blf[nt], sBl_u + bBase + (uint32_t)(nt * 8 * APITCH) + ktp * 64);
            }
            #pragma unroll
            for (int mt = 0; mt < 4; mt++) {
                #pragma unroll
                for (int kt2 = 0; kt2 < 2; kt2++) {
                    uint32_t ah4[4], al4[4];
                    const uint32_t ao = aBase + (uint32_t)(mt * 16 * APITCH) +
                                        ktp * 64 + kt2 * 32;
                    ldsm_x4(ah4, sAh_u + ao);
                    ldsm_x4(al4, sAl_u + ao);
                    #pragma unroll
                    for (int nt = 0; nt < 4; nt++) {
                        mma16816(acc[mt][nt], ah4, bhf[nt][kt2 * 2], bhf[nt][kt2 * 2 + 1]);
                        mma16816(acc[mt][nt], al4, bhf[nt][kt2 * 2], bhf[nt][kt2 * 2 + 1]);
                        mma16816(acc[mt][nt], ah4, blf[nt][kt2 * 2], blf[nt][kt2 * 2 + 1]);
                    }
                }
            }
        }
    }

    // ---- epilogue ----
    #pragma unroll
    for (int mt = 0; mt < 4; mt++) {
        const int r0g = row0 + mhalf * 64 + mt * 16 + g;
        #pragma unroll
        for (int nt = 0; nt < 4; nt++) {
            float* c = acc[mt][nt];
            const int col = n0 + nt * 8 + 2 * q;
            float v0 = c[0], v1 = c[1], v2 = c[2], v3 = c[3];
            if (DOLEAKY) { v0 = lk(v0); v1 = lk(v1); v2 = lk(v2); v3 = lk(v3); }
            if (!SPLIT) {
                if (r0g < N)     *(float2*)&out[(size_t)r0g * 128 + col] = make_float2(v0, v1);
                if (r0g + 8 < N) *(float2*)&out[(size_t)(r0g + 8) * 128 + col] = make_float2(v2, v3);
            } else {
                float* dstp = (col < 64) ? (out + (size_t)0 * 64)
                                         : (out + (size_t)N * 64 - 64);
                if (r0g < N)     *(float2*)&dstp[(size_t)r0g * 64 + col] = make_float2(v0, v1);
                if (r0g + 8 < N) *(float2*)&dstp[(size_t)(r0g + 8) * 64 + col] = make_float2(v2, v3);
            }
        }
    }
}

// ---------------------------------------------------------------------------
extern "C" void kernel_launch(void* const* d_in, const int* in_sizes, int n_in,
                              void* d_out, int out_size) {
    const float* x    = (const float*)d_in[0];
    const int*   ei   = (const int*)d_in[1];
    const float* ea   = (const float*)d_in[2];
    const float* e1W1 = (const float*)d_in[3];
    const float* e1b1 = (const float*)d_in[4];
    const float* e1W2 = (const float*)d_in[5];
    const float* e1b2 = (const float*)d_in[6];
    const float* n1W  = (const float*)d_in[7];
    const float* n1b  = (const float*)d_in[8];
    const float* e2W1 = (const float*)d_in[9];
    const float* e2b1 = (const float*)d_in[10];
    const float* e2W2 = (const float*)d_in[11];
    const float* e2b2 = (const float*)d_in[12];
    const float* n2W  = (const float*)d_in[13];
    const float* n2b  = (const float*)d_in[14];
    const float* muW  = (const float*)d_in[15];
    const float* mub  = (const float*)d_in[16];
    const float* lvW  = (const float*)d_in[17];
    const float* lvb  = (const float*)d_in[18];

    const int N = in_sizes[0] / 128;  // 50000
    const int E = in_sizes[2] / 64;   // 640000
    const int* dst = ei + E;          // edge_index row 1

    float *S1, *S2, *h1, *h2, *dg, *B1, *B2, *c1, *c2, *B3, *b3, *biascat;
    __nv_bfloat16 *Bth, *Btl, *B1th, *B1tl, *B2th, *B2tl, *B3th, *B3tl;
    cudaGetSymbolAddress((void**)&S1, g_S1);
    cudaGetSymbolAddress((void**)&S2, g_S2);
    cudaGetSymbolAddress((void**)&h1, g_h1);
    cudaGetSymbolAddress((void**)&h2, g_h2);
    cudaGetSymbolAddress((void**)&dg, g_deg);
    cudaGetSymbolAddress((void**)&B1, g_B1);
    cudaGetSymbolAddress((void**)&B2, g_B2);
    cudaGetSymbolAddress((void**)&c1, g_c1);
    cudaGetSymbolAddress((void**)&c2, g_c2);
    cudaGetSymbolAddress((void**)&B3, g_B3);
    cudaGetSymbolAddress((void**)&b3, g_b3);
    cudaGetSymbolAddress((void**)&Bth, g_Bth);
    cudaGetSymbolAddress((void**)&Btl, g_Btl);
    cudaGetSymbolAddress((void**)&biascat, g_biascat);
    cudaGetSymbolAddress((void**)&B1th, g_B1th);
    cudaGetSymbolAddress((void**)&B1tl, g_B1tl);
    cudaGetSymbolAddress((void**)&B2th, g_B2th);
    cudaGetSymbolAddress((void**)&B2tl, g_B2tl);
    cudaGetSymbolAddress((void**)&B3th, g_B3th);
    cudaGetSymbolAddress((void**)&B3tl, g_B3tl);

    cudaMemsetAsync(S1, 0, (size_t)N * 128 * sizeof(float));
    cudaMemsetAsync(S2, 0, (size_t)N * 128 * sizeof(float));
    cudaMemsetAsync(dg, 0, (size_t)N * sizeof(float));

    prep_all<<<dim3(128, 4), 128>>>(e1W2, e1b2, n1W, n1b,
                                    e2W2, e2b2, n2W, n2b,
                                    muW, mub, lvW, lvb,
                                    e1W1, e1b1, e2W1, e2b1,
                                    B1, c1, B2, c2, B3, b3, Bth, Btl, biascat);
    prep_btn<<<dim3(128, 3), 256>>>(B1, B2, B3, B1th, B1tl, B2th, B2tl, B3th, B3tl);
    deg_kernel<<<(E + 255) / 256, 256>>>(dst, dg, E);

    int ntiles = (E + 127) / 128;
    edge_mma_kernel<<<296, 128>>>(ea, dst, Bth, Btl, biascat, S1, S2, E, ntiles);

    int nblk = (N + 127) / 128;  // 391
    cudaFuncSetAttribute(node_mma<256, true, true, false>,
                         cudaFuncAttributeMaxDynamicSharedMemorySize, NODE_SMEM);
    cudaFuncSetAttribute(node_mma<128, false, false, true>,
                         cudaFuncAttributeMaxDynamicSharedMemorySize, NODE_SMEM);

    node_mma<256, true, true, false><<<nblk, 256, NODE_SMEM>>>(x,  S1, B1th, B1tl, c1, dg, h1, N);
    node_mma<256, true, true, false><<<nblk, 256, NODE_SMEM>>>(h1, S2, B2th, B2tl, c2, dg, h2, N);
    node_mma<128, false, false, true><<<nblk, 256, NODE_SMEM>>>(h2, nullptr, B3th, B3tl, b3,
                                                                nullptr, (float*)d_out, N);
}

// round 12
// speedup vs baseline: 1.5270x; 1.0265x over previous
#include <cuda_runtime.h>
#include <cuda_bf16.h>
#include <cstdint>
#include <cstdio>

// ---------------------------------------------------------------------------
// EdgeVGAE encoder, algebraically collapsed:
//   S_l = segment_sum(leaky(edge_attr @ W1_l + b1_l), dst)   (edge pass, l=1,2)
//   h1  = leaky(deg*(x @ n1Wx + c1) + S1 @ M1)
//   h2  = leaky(deg*(h1 @ n2Wh + c2) + S2 @ M2)
//   mu|lv = h2 @ [muW|lvW] + [mub|lvb]
// R12: staging stores vectorized to STS.128 (R11 profile: L1=61% — the
// STS.32 staging at 144B stride was 8-way bank-conflicted, 2048 smem
// cyc/tile; uint4 stores are conflict-free, 256 cyc). Same fix in node_mma.
// ---------------------------------------------------------------------------

typedef unsigned long long u64;

#define NMAX 50048

__device__ float g_S1[NMAX * 128];
__device__ float g_S2[NMAX * 128];
__device__ float g_h1[NMAX * 128];
__device__ float g_h2[NMAX * 128];
__device__ float g_deg[NMAX];
__device__ float g_B1[256 * 128];
__device__ float g_B2[256 * 128];
__device__ float g_c1[128];
__device__ float g_c2[128];
__device__ float g_B3[128 * 128];
__device__ float g_b3[128];
__device__ __nv_bfloat16 g_Bth[256 * 64];   // edge weights^T hi
__device__ __nv_bfloat16 g_Btl[256 * 64];   // edge weights^T lo
__device__ float g_biascat[256];
__device__ __nv_bfloat16 g_B1th[128 * 256], g_B1tl[128 * 256];  // node B^T splits
__device__ __nv_bfloat16 g_B2th[128 * 256], g_B2tl[128 * 256];
__device__ __nv_bfloat16 g_B3th[128 * 128], g_B3tl[128 * 128];

// ============================ helpers ======================================
__device__ __forceinline__ uint32_t smem_u32(const void* p) {
    uint32_t a;
    asm("{ .reg .u64 t; cvta.to.shared.u64 t, %1; cvt.u32.u64 %0, t; }" : "=r"(a) : "l"(p));
    return a;
}
__device__ __forceinline__ float lk(float v) { return fmaxf(v, 0.15f * v); }
__device__ __forceinline__ void red4(float* p, float a, float b, float c, float d) {
    asm volatile("red.global.add.v4.f32 [%0], {%1, %2, %3, %4};"
                 :: "l"((u64)(uintptr_t)p), "f"(a), "f"(b), "f"(c), "f"(d) : "memory");
}
// mma.sync m16n8k16 bf16 -> f32, accumulate in place
__device__ __forceinline__ void mma16816(float* c, const uint32_t* a,
                                         uint32_t b0, uint32_t b1) {
    asm volatile(
        "mma.sync.aligned.m16n8k16.row.col.f32.bf16.bf16.f32 "
        "{%0,%1,%2,%3}, {%4,%5,%6,%7}, {%8,%9}, {%0,%1,%2,%3};"
        : "+f"(c[0]), "+f"(c[1]), "+f"(c[2]), "+f"(c[3])
        : "r"(a[0]), "r"(a[1]), "r"(a[2]), "r"(a[3]), "r"(b0), "r"(b1));
}
__device__ __forceinline__ void ldsm_x4(uint32_t* r, uint32_t addr) {
    asm volatile("ldmatrix.sync.aligned.m8n8.x4.shared.b16 {%0,%1,%2,%3}, [%4];"
                 : "=r"(r[0]), "=r"(r[1]), "=r"(r[2]), "=r"(r[3]) : "r"(addr));
}
__device__ __forceinline__ void split2(float a0, float a1, uint32_t& h, uint32_t& l) {
    __nv_bfloat162 h2 = __floats2bfloat162_rn(a0, a1);
    __nv_bfloat162 l2 = __floats2bfloat162_rn(a0 - __low2float(h2), a1 - __high2float(h2));
    h = *(uint32_t*)&h2;
    l = *(uint32_t*)&l2;
}
// split two float4 -> one uint4 (hi) + one uint4 (lo)
__device__ __forceinline__ void split8(float4 v0, float4 v1, uint4& h, uint4& l) {
    split2(v0.x, v0.y, h.x, l.x);
    split2(v0.z, v0.w, h.y, l.y);
    split2(v1.x, v1.y, h.z, l.z);
    split2(v1.z, v1.w, h.w, l.w);
}

// ======================= merged precompute =================================
__global__ void prep_all(const float* __restrict__ e1W2, const float* __restrict__ e1b2,
                         const float* __restrict__ n1W,  const float* __restrict__ n1b,
                         const float* __restrict__ e2W2, const float* __restrict__ e2b2,
                         const float* __restrict__ n2W,  const float* __restrict__ n2b,
                         const float* __restrict__ muW,  const float* __restrict__ mub,
                         const float* __restrict__ lvW,  const float* __restrict__ lvb,
                         const float* __restrict__ e1W1, const float* __restrict__ e1b1,
                         const float* __restrict__ e2W1, const float* __restrict__ e2b1,
                         float* __restrict__ B1, float* __restrict__ c1,
                         float* __restrict__ B2, float* __restrict__ c2,
                         float* __restrict__ B3, float* __restrict__ b3,
                         __nv_bfloat16* __restrict__ bth, __nv_bfloat16* __restrict__ btl,
                         float* __restrict__ bias) {
    const int task = blockIdx.y, bx = blockIdx.x, tid = threadIdx.x;
    if (task <= 1) {
        const float* eW2 = task ? e2W2 : e1W2;
        const float* eb2 = task ? e2b2 : e1b2;
        const float* nW  = task ? n2W  : n1W;
        const float* nb  = task ? n2b  : n1b;
        float* Bcat = task ? B2 : B1;
        float* c = task ? c2 : c1;
        int k = bx, j = tid;
        Bcat[k * 128 + j] = nW[k * 128 + j];
        float acc = 0.f;
        #pragma unroll 4
        for (int t = 0; t < 128; t++) acc += eW2[k * 128 + t] * nW[(128 + t) * 128 + j];
        Bcat[(128 + k) * 128 + j] = acc;
        if (k == 0) {
            float cc = nb[j];
            #pragma unroll 4
            for (int t = 0; t < 128; t++) cc += eb2[t] * nW[(128 + t) * 128 + j];
            c[j] = cc;
        }
    } else if (task == 2) {
        int k = bx, j = tid;
        B3[k * 128 + j] = (j < 64) ? muW[k * 64 + j] : lvW[k * 64 + (j - 64)];
        if (k == 0) b3[j] = (j < 64) ? mub[j] : lvb[j - 64];
    } else {
        int k = tid & 63, half = tid >> 6;
        int n = bx + half * 128;
        float w = (n < 128) ? e1W1[k * 128 + n] : e2W1[k * 128 + (n - 128)];
        __nv_bfloat16 h = __float2bfloat16(w);
        float r = w - __bfloat162float(h);
        bth[n * 64 + k] = h;
        btl[n * 64 + k] = __float2bfloat16(r);
        if (k == 0) bias[n] = (n < 128) ? e1b1[n] : e2b1[n - 128];
    }
}

// node-B transpose+split: Bt[n][k] = B[k][n], hi/lo bf16
__global__ void prep_btn(const float* __restrict__ B1, const float* __restrict__ B2,
                         const float* __restrict__ B3,
                         __nv_bfloat16* __restrict__ b1h, __nv_bfloat16* __restrict__ b1l,
                         __nv_bfloat16* __restrict__ b2h, __nv_bfloat16* __restrict__ b2l,
                         __nv_bfloat16* __restrict__ b3h, __nv_bfloat16* __restrict__ b3l) {
    const int task = blockIdx.y, n = blockIdx.x, k = threadIdx.x;
    const int KT = (task == 2) ? 128 : 256;
    if (k >= KT) return;
    const float* B = (task == 0) ? B1 : (task == 1) ? B2 : B3;
    __nv_bfloat16* bh = (task == 0) ? b1h : (task == 1) ? b2h : b3h;
    __nv_bfloat16* bl = (task == 0) ? b1l : (task == 1) ? b2l : b3l;
    float w = B[k * 128 + n];
    __nv_bfloat16 h = __float2bfloat16(w);
    bh[n * KT + k] = h;
    bl[n * KT + k] = __float2bfloat16(w - __bfloat162float(h));
}

__global__ void deg_kernel(const int* __restrict__ dst, float* __restrict__ deg, int E) {
    int e = blockIdx.x * blockDim.x + threadIdx.x;
    if (e < E) atomicAdd(&deg[dst[e]], 1.0f);
}

// ======================= mma.sync edge pass ================================
// 128-thread CTA (4 warps), tile = 128 edges x ONE layer's 128 cols, K=64.
// layer = blockIdx.x & 1. 2 CTAs/SM. Staging via conflict-free STS.128.
#define APITCH 144

__global__ __launch_bounds__(128, 2)
void edge_mma_kernel(const float* __restrict__ ea, const int* __restrict__ dstv,
                     const __nv_bfloat16* __restrict__ Bth,
                     const __nv_bfloat16* __restrict__ Btl,
                     const float* __restrict__ biascat,
                     float* __restrict__ S1, float* __restrict__ S2,
                     int E, int ntiles) {
    __shared__ __align__(16) char sA[2 * 128 * APITCH];  // hi | lo
    __shared__ float sBias[128];
    __shared__ int sDst[128];
    char* sAh = sA;
    char* sAl = sA + 128 * APITCH;

    const int tid = threadIdx.x, wid = tid >> 5, lane = tid & 31;
    const int g = lane >> 2, q = lane & 3;
    const int layer = blockIdx.x & 1;
    const int nbase = layer * 128;
    const int n0 = wid * 32;                 // 0..96 within layer
    float* Sbase = layer ? S2 : S1;

    sBias[tid] = biascat[nbase + tid];

    // ---- B fragments in registers (once; layer fixed per CTA) ----
    uint32_t bh[4][4][2], bl[4][4][2];
    {
        const uint32_t* BH = (const uint32_t*)Bth;
        const uint32_t* BL = (const uint32_t*)Btl;
        #pragma unroll
        for (int nt = 0; nt < 4; nt++) {
            const int n = nbase + n0 + nt * 8 + g;
            #pragma unroll
            for (int kt = 0; kt < 4; kt++) {
                const int base = n * 32 + kt * 8 + q;
                bh[nt][kt][0] = BH[base];
                bh[nt][kt][1] = BH[base + 4];
                bl[nt][kt][0] = BL[base];
                bl[nt][kt][1] = BL[base + 4];
            }
        }
    }

    const int rowoff = (lane & 7) + ((lane >> 3) & 1) * 8;
    const int koff = (lane >> 4) * 16;
    const uint32_t sAh_u = smem_u32(sAh);
    const uint32_t sAl_u = smem_u32(sAl);
    const uint32_t lmBase = (uint32_t)(rowoff * APITCH + koff);

    const int cstride = gridDim.x >> 1;
    for (int tile = blockIdx.x >> 1; tile < ntiles; tile += cstride) {
        const int e0 = tile * 128;
        // ---- stage A tile: conflict-free STS.128 ----
        {
            const int ge = e0 + tid;
            uint4* ah = (uint4*)(sAh + tid * APITCH);
            uint4* al = (uint4*)(sAl + tid * APITCH);
            if (ge < E) {
                const float4* src = (const float4*)(ea + (size_t)ge * 64);
                #pragma unroll
                for (int j = 0; j < 8; j++) {
                    uint4 h, l;
                    split8(src[j * 2], src[j * 2 + 1], h, l);
                    ah[j] = h;
                    al[j] = l;
                }
                sDst[tid] = dstv[ge];
            } else {
                const uint4 z = make_uint4(0, 0, 0, 0);
                #pragma unroll
                for (int j = 0; j < 8; j++) { ah[j] = z; al[j] = z; }
                sDst[tid] = -1;
            }
        }
        __syncthreads();

        // ---- mainloop: 128 rows x 32 cols per warp ----
        float acc[8][4][4];
        #pragma unroll
        for (int mt = 0; mt < 8; mt++)
            #pragma unroll
            for (int nt = 0; nt < 4; nt++)
                #pragma unroll
                for (int i = 0; i < 4; i++) acc[mt][nt][i] = 0.f;

        #pragma unroll
        for (int mt = 0; mt < 8; mt++) {
            const uint32_t mtOff = (uint32_t)(mt * 16 * APITCH) + lmBase;
            #pragma unroll
            for (int kt = 0; kt < 4; kt++) {
                uint32_t ah4[4], al4[4];
                ldsm_x4(ah4, sAh_u + mtOff + kt * 32);
                ldsm_x4(al4, sAl_u + mtOff + kt * 32);
                #pragma unroll
                for (int nt = 0; nt < 4; nt++) {
                    mma16816(acc[mt][nt], ah4, bh[nt][kt][0], bh[nt][kt][1]);
                    mma16816(acc[mt][nt], al4, bh[nt][kt][0], bh[nt][kt][1]);
                    mma16816(acc[mt][nt], ah4, bl[nt][kt][0], bl[nt][kt][1]);
                }
            }
        }

        // ---- epilogue: bias + leaky + quad-pack + red4 scatter ----
        #pragma unroll
        for (int mt = 0; mt < 8; mt++) {
            const int rowLo = mt * 16 + g;
            const int dLo = sDst[rowLo], dHi = sDst[rowLo + 8];
            #pragma unroll
            for (int nt = 0; nt < 4; nt++) {
                float* c = acc[mt][nt];
                const int col = n0 + nt * 8 + q * 2;
                const float b0 = sBias[col], b1 = sBias[col + 1];
                float v0 = lk(c[0] + b0), v1 = lk(c[1] + b1);
                float v2 = lk(c[2] + b0), v3 = lk(c[3] + b1);
                float r0 = __shfl_xor_sync(0xffffffffu, v0, 1);
                float r1 = __shfl_xor_sync(0xffffffffu, v1, 1);
                float r2 = __shfl_xor_sync(0xffffffffu, v2, 1);
                float r3 = __shfl_xor_sync(0xffffffffu, v3, 1);
                const int colb = n0 + nt * 8 + (q >> 1) * 4;
                int d;
                float w0, w1, w2, w3;
                if ((q & 1) == 0) { d = dLo; w0 = v0; w1 = v1; w2 = r0; w3 = r1; }
                else              { d = dHi; w0 = r2; w1 = r3; w2 = v2; w3 = v3; }
                if (d >= 0)
                    red4(&Sbase[(size_t)d * 128 + colb], w0, w1, w2, w3);
            }
        }
        __syncthreads();
    }
}

// ======================= tensor node GEMM ==================================
#define NSM_AH 0
#define NSM_AL 18432
#define NSM_BH 36864
#define NSM_BL 55296
#define NSM_BIAS 73728
#define NSM_DEG 74304
#define NODE_SMEM 74880

template <int KTOT, bool SECOND, bool DOLEAKY, bool SPLIT>
__global__ __launch_bounds__(256, 1) void node_mma(
    const float* __restrict__ A1, const float* __restrict__ A2,
    const __nv_bfloat16* __restrict__ Bth, const __nv_bfloat16* __restrict__ Btl,
    const float* __restrict__ bias, const float* __restrict__ deg,
    float* __restrict__ out, int N) {
    extern __shared__ __align__(16) char smem[];
    char* sAh = smem + NSM_AH;
    char* sAl = smem + NSM_AL;
    char* sBh = smem + NSM_BH;
    char* sBl = smem + NSM_BL;
    float* sBias = (float*)(smem + NSM_BIAS);
    float* sDeg = (float*)(smem + NSM_DEG);

    const int tid = threadIdx.x, wid = tid >> 5, lane = tid & 31;
    const int g = lane >> 2, q = lane & 3;
    const int mhalf = wid >> 2;
    const int n0 = (wid & 3) * 32;
    const int row0 = blockIdx.x * 128;

    if (tid < 128) {
        sBias[tid] = bias[tid];
        if (SECOND) {
            int r = row0 + tid;
            sDeg[tid] = (r < N) ? deg[r] : 0.f;
        }
    }
    __syncthreads();

    float acc[4][4][4];
    #pragma unroll
    for (int mt = 0; mt < 4; mt++) {
        const int rl = mhalf * 64 + mt * 16 + g;
        const float d0 = SECOND ? sDeg[rl] : 1.f;
        const float d1 = SECOND ? sDeg[rl + 8] : 1.f;
        #pragma unroll
        for (int nt = 0; nt < 4; nt++) {
            const int col = n0 + nt * 8 + 2 * q;
            const float b0 = sBias[col], b1 = sBias[col + 1];
            acc[mt][nt][0] = d0 * b0;
            acc[mt][nt][1] = d0 * b1;
            acc[mt][nt][2] = d1 * b0;
            acc[mt][nt][3] = d1 * b1;
        }
    }

    const int rowoff = (lane & 7) + ((lane >> 3) & 1) * 8;
    const uint32_t sAh_u = smem_u32(sAh);
    const uint32_t sAl_u = smem_u32(sAl);
    const uint32_t sBh_u = smem_u32(sBh);
    const uint32_t sBl_u = smem_u32(sBl);
    const uint32_t aBase = (uint32_t)((mhalf * 64 + rowoff) * APITCH + (lane >> 4) * 16);
    const uint32_t bBase = (uint32_t)((n0 + (lane & 7)) * APITCH + ((lane >> 3) & 3) * 16);

    for (int kc = 0; kc < KTOT; kc += 64) {
        __syncthreads();
        // ---- stage A chunk: conflict-free STS.128 ----
        {
            const int row = tid >> 1, hf = tid & 1;
            const int grow = row0 + row;
            uint4* ah = (uint4*)(sAh + row * APITCH + hf * 64);
            uint4* al = (uint4*)(sAl + row * APITCH + hf * 64);
            if (grow < N) {
                const bool a1part = (!SECOND) || (kc < 128);
                const int ksrc = (a1part ? kc : kc - 128) + hf * 32;
                const float* Arow = (a1part ? A1 : A2) + (size_t)grow * 128 + ksrc;
                const float s = (SECOND && a1part) ? sDeg[row] : 1.f;
                const float4* src = (const float4*)Arow;
                #pragma unroll
                for (int j = 0; j < 4; j++) {
                    float4 v0 = src[j * 2], v1 = src[j * 2 + 1];
                    v0.x *= s; v0.y *= s; v0.z *= s; v0.w *= s;
                    v1.x *= s; v1.y *= s; v1.z *= s; v1.w *= s;
                    uint4 h, l;
                    split8(v0, v1, h, l);
                    ah[j] = h;
                    al[j] = l;
                }
            } else {
                const uint4 z = make_uint4(0, 0, 0, 0);
                #pragma unroll
                for (int j = 0; j < 4; j++) { ah[j] = z; al[j] = z; }
            }
        }
        // ---- stage B chunk: 64 bytes per (n, half) ----
        {
            const int n = tid >> 1, hf = tid & 1;
            const uint4* bh4 = (const uint4*)(Bth + (size_t)n * KTOT + kc + hf * 32);
            const uint4* bl4 = (const uint4*)(Btl + (size_t)n * KTOT + kc + hf * 32);
            uint4* dh = (uint4*)(sBh + n * APITCH + hf * 64);
            uint4* dl = (uint4*)(sBl + n * APITCH + hf * 64);
            dh[0] = bh4[0]; dh[1] = bh4[1]; dh[2] = bh4[2]; dh[3] = bh4[3];
            dl[0] = bl4[0]; dl[1] = bl4[1]; dl[2] = bl4[2]; dl[3] = bl4[3];
        }
        __syncthreads();

        // ---- MMA ----
        #pragma unroll
        for (int ktp = 0; ktp < 2; ktp++) {
            uint32_t bhf[4][4], blf[4][4];
            #pragma unroll
            for (int nt = 0; nt < 4; nt++) {
                ldsm_x4(bhf[nt], sBh_u + bBase + (uint32_t)(nt * 8 * APITCH) + ktp * 64);
                ldsm_x4(blf[nt], sBl_u + bBase + (uint32_t)(nt * 8 * APITCH) + ktp * 64);
            }
            #pragma unroll
            for (int mt = 0; mt < 4; mt++) {
                #pragma unroll
                for (int kt2 = 0; kt2 < 2; kt2++) {
                    uint32_t ah4[4], al4[4];
                    const uint32_t ao = aBase + (uint32_t)(mt * 16 * APITCH) +
                                        ktp * 64 + kt2 * 32;
                    ldsm_x4(ah4, sAh_u + ao);
                    ldsm_x4(al4, sAl_u + ao);
                    #pragma unroll
                    for (int nt = 0; nt < 4; nt++) {
                        mma16816(acc[mt][nt], ah4, bhf[nt][kt2 * 2], bhf[nt][kt2 * 2 + 1]);
                        mma16816(acc[mt][nt], al4, bhf[nt][kt2 * 2], bhf[nt][kt2 * 2 + 1]);
                        mma16816(acc[mt][nt], ah4, blf[nt][kt2 * 2], blf[nt][kt2 * 2 + 1]);
                    }
                }
            }
        }
    }

    // ---- epilogue ----
    #pragma unroll
    for (int mt = 0; mt < 4; mt++) {
        const int r0g = row0 + mhalf * 64 + mt * 16 + g;
        #pragma unroll
        for (int nt = 0; nt < 4; nt++) {
            float* c = acc[mt][nt];
            const int col = n0 + nt * 8 + 2 * q;
            float v0 = c[0], v1 = c[1], v2 = c[2], v3 = c[3];
            if (DOLEAKY) { v0 = lk(v0); v1 = lk(v1); v2 = lk(v2); v3 = lk(v3); }
            if (!SPLIT) {
                if (r0g < N)     *(float2*)&out[(size_t)r0g * 128 + col] = make_float2(v0, v1);
                if (r0g + 8 < N) *(float2*)&out[(size_t)(r0g + 8) * 128 + col] = make_float2(v2, v3);
            } else {
                float* dstp = (col < 64) ? (out + (size_t)0 * 64)
                                         : (out + (size_t)N * 64 - 64);
                if (r0g < N)     *(float2*)&dstp[(size_t)r0g * 64 + col] = make_float2(v0, v1);
                if (r0g + 8 < N) *(float2*)&dstp[(size_t)(r0g + 8) * 64 + col] = make_float2(v2, v3);
            }
        }
    }
}

// ---------------------------------------------------------------------------
extern "C" void kernel_launch(void* const* d_in, const int* in_sizes, int n_in,
                              void* d_out, int out_size) {
    const float* x    = (const float*)d_in[0];
    const int*   ei   = (const int*)d_in[1];
    const float* ea   = (const float*)d_in[2];
    const float* e1W1 = (const float*)d_in[3];
    const float* e1b1 = (const float*)d_in[4];
    const float* e1W2 = (const float*)d_in[5];
    const float* e1b2 = (const float*)d_in[6];
    const float* n1W  = (const float*)d_in[7];
    const float* n1b  = (const float*)d_in[8];
    const float* e2W1 = (const float*)d_in[9];
    const float* e2b1 = (const float*)d_in[10];
    const float* e2W2 = (const float*)d_in[11];
    const float* e2b2 = (const float*)d_in[12];
    const float* n2W  = (const float*)d_in[13];
    const float* n2b  = (const float*)d_in[14];
    const float* muW  = (const float*)d_in[15];
    const float* mub  = (const float*)d_in[16];
    const float* lvW  = (const float*)d_in[17];
    const float* lvb  = (const float*)d_in[18];

    const int N = in_sizes[0] / 128;  // 50000
    const int E = in_sizes[2] / 64;   // 640000
    const int* dst = ei + E;          // edge_index row 1

    float *S1, *S2, *h1, *h2, *dg, *B1, *B2, *c1, *c2, *B3, *b3, *biascat;
    __nv_bfloat16 *Bth, *Btl, *B1th, *B1tl, *B2th, *B2tl, *B3th, *B3tl;
    cudaGetSymbolAddress((void**)&S1, g_S1);
    cudaGetSymbolAddress((void**)&S2, g_S2);
    cudaGetSymbolAddress((void**)&h1, g_h1);
    cudaGetSymbolAddress((void**)&h2, g_h2);
    cudaGetSymbolAddress((void**)&dg, g_deg);
    cudaGetSymbolAddress((void**)&B1, g_B1);
    cudaGetSymbolAddress((void**)&B2, g_B2);
    cudaGetSymbolAddress((void**)&c1, g_c1);
    cudaGetSymbolAddress((void**)&c2, g_c2);
    cudaGetSymbolAddress((void**)&B3, g_B3);
    cudaGetSymbolAddress((void**)&b3, g_b3);
    cudaGetSymbolAddress((void**)&Bth, g_Bth);
    cudaGetSymbolAddress((void**)&Btl, g_Btl);
    cudaGetSymbolAddress((void**)&biascat, g_biascat);
    cudaGetSymbolAddress((void**)&B1th, g_B1th);
    cudaGetSymbolAddress((void**)&B1tl, g_B1tl);
    cudaGetSymbolAddress((void**)&B2th, g_B2th);
    cudaGetSymbolAddress((void**)&B2tl, g_B2tl);
    cudaGetSymbolAddress((void**)&B3th, g_B3th);
    cudaGetSymbolAddress((void**)&B3tl, g_B3tl);

    cudaMemsetAsync(S1, 0, (size_t)N * 128 * sizeof(float));
    cudaMemsetAsync(S2, 0, (size_t)N * 128 * sizeof(float));
    cudaMemsetAsync(dg, 0, (size_t)N * sizeof(float));

    prep_all<<<dim3(128, 4), 128>>>(e1W2, e1b2, n1W, n1b,
                                    e2W2, e2b2, n2W, n2b,
                                    muW, mub, lvW, lvb,
                                    e1W1, e1b1, e2W1, e2b1,
                                    B1, c1, B2, c2, B3, b3, Bth, Btl, biascat);
    prep_btn<<<dim3(128, 3), 256>>>(B1, B2, B3, B1th, B1tl, B2th, B2tl, B3th, B3tl);
    deg_kernel<<<(E + 255) / 256, 256>>>(dst, dg, E);

    int ntiles = (E + 127) / 128;
    edge_mma_kernel<<<296, 128>>>(ea, dst, Bth, Btl, biascat, S1, S2, E, ntiles);

    int nblk = (N + 127) / 128;  // 391
    cudaFuncSetAttribute(node_mma<256, true, true, false>,
                         cudaFuncAttributeMaxDynamicSharedMemorySize, NODE_SMEM);
    cudaFuncSetAttribute(node_mma<128, false, false, true>,
                         cudaFuncAttributeMaxDynamicSharedMemorySize, NODE_SMEM);

    node_mma<256, true, true, false><<<nblk, 256, NODE_SMEM>>>(x,  S1, B1th, B1tl, c1, dg, h1, N);
    node_mma<256, true, true, false><<<nblk, 256, NODE_SMEM>>>(h1, S2, B2th, B2tl, c2, dg, h2, N);
    node_mma<128, false, false, true><<<nblk, 256, NODE_SMEM>>>(h2, nullptr, B3th, B3tl, b3,
                                                                nullptr, (float*)d_out, N);
}

// round 13
// speedup vs baseline: 1.7830x; 1.1676x over previous
#include <cuda_runtime.h>
#include <cuda_bf16.h>
#include <cstdint>
#include <cstdio>

// ---------------------------------------------------------------------------
// EdgeVGAE encoder, algebraically collapsed:
//   S_l = segment_sum(leaky(edge_attr @ W1_l + b1_l), dst)   (edge pass, l=1,2)
//   h1  = leaky(deg*(x @ n1Wx + c1) + S1 @ M1)
//   h2  = leaky(deg*(h1 @ n2Wh + c2) + S2 @ M2)
//   mu|lv = h2 @ [muW|lvW] + [mub|lvb]
// R13: edge kernel latency-bound (issue 19%, tensor 31%, ~18K cyc/tile vs
// ~4K of work). Restructured per-mt (acc 128->16 regs live) + launch_bounds
// (128,4) -> 4 CTAs/SM (16 warps) for latency hiding; red4 interleaved.
// ---------------------------------------------------------------------------

typedef unsigned long long u64;

#define NMAX 50048

__device__ float g_S1[NMAX * 128];
__device__ float g_S2[NMAX * 128];
__device__ float g_h1[NMAX * 128];
__device__ float g_h2[NMAX * 128];
__device__ float g_deg[NMAX];
__device__ float g_B1[256 * 128];
__device__ float g_B2[256 * 128];
__device__ float g_c1[128];
__device__ float g_c2[128];
__device__ float g_B3[128 * 128];
__device__ float g_b3[128];
__device__ __nv_bfloat16 g_Bth[256 * 64];   // edge weights^T hi
__device__ __nv_bfloat16 g_Btl[256 * 64];   // edge weights^T lo
__device__ float g_biascat[256];
__device__ __nv_bfloat16 g_B1th[128 * 256], g_B1tl[128 * 256];  // node B^T splits
__device__ __nv_bfloat16 g_B2th[128 * 256], g_B2tl[128 * 256];
__device__ __nv_bfloat16 g_B3th[128 * 128], g_B3tl[128 * 128];

// ============================ helpers ======================================
__device__ __forceinline__ uint32_t smem_u32(const void* p) {
    uint32_t a;
    asm("{ .reg .u64 t; cvta.to.shared.u64 t, %1; cvt.u32.u64 %0, t; }" : "=r"(a) : "l"(p));
    return a;
}
__device__ __forceinline__ float lk(float v) { return fmaxf(v, 0.15f * v); }
__device__ __forceinline__ void red4(float* p, float a, float b, float c, float d) {
    asm volatile("red.global.add.v4.f32 [%0], {%1, %2, %3, %4};"
                 :: "l"((u64)(uintptr_t)p), "f"(a), "f"(b), "f"(c), "f"(d) : "memory");
}
// mma.sync m16n8k16 bf16 -> f32, accumulate in place
__device__ __forceinline__ void mma16816(float* c, const uint32_t* a,
                                         uint32_t b0, uint32_t b1) {
    asm volatile(
        "mma.sync.aligned.m16n8k16.row.col.f32.bf16.bf16.f32 "
        "{%0,%1,%2,%3}, {%4,%5,%6,%7}, {%8,%9}, {%0,%1,%2,%3};"
        : "+f"(c[0]), "+f"(c[1]), "+f"(c[2]), "+f"(c[3])
        : "r"(a[0]), "r"(a[1]), "r"(a[2]), "r"(a[3]), "r"(b0), "r"(b1));
}
__device__ __forceinline__ void ldsm_x4(uint32_t* r, uint32_t addr) {
    asm volatile("ldmatrix.sync.aligned.m8n8.x4.shared.b16 {%0,%1,%2,%3}, [%4];"
                 : "=r"(r[0]), "=r"(r[1]), "=r"(r[2]), "=r"(r[3]) : "r"(addr));
}
__device__ __forceinline__ void split2(float a0, float a1, uint32_t& h, uint32_t& l) {
    __nv_bfloat162 h2 = __floats2bfloat162_rn(a0, a1);
    __nv_bfloat162 l2 = __floats2bfloat162_rn(a0 - __low2float(h2), a1 - __high2float(h2));
    h = *(uint32_t*)&h2;
    l = *(uint32_t*)&l2;
}
__device__ __forceinline__ void split8(float4 v0, float4 v1, uint4& h, uint4& l) {
    split2(v0.x, v0.y, h.x, l.x);
    split2(v0.z, v0.w, h.y, l.y);
    split2(v1.x, v1.y, h.z, l.z);
    split2(v1.z, v1.w, h.w, l.w);
}

// ======================= merged precompute =================================
__global__ void prep_all(const float* __restrict__ e1W2, const float* __restrict__ e1b2,
                         const float* __restrict__ n1W,  const float* __restrict__ n1b,
                         const float* __restrict__ e2W2, const float* __restrict__ e2b2,
                         const float* __restrict__ n2W,  const float* __restrict__ n2b,
                         const float* __restrict__ muW,  const float* __restrict__ mub,
                         const float* __restrict__ lvW,  const float* __restrict__ lvb,
                         const float* __restrict__ e1W1, const float* __restrict__ e1b1,
                         const float* __restrict__ e2W1, const float* __restrict__ e2b1,
                         float* __restrict__ B1, float* __restrict__ c1,
                         float* __restrict__ B2, float* __restrict__ c2,
                         float* __restrict__ B3, float* __restrict__ b3,
                         __nv_bfloat16* __restrict__ bth, __nv_bfloat16* __restrict__ btl,
                         float* __restrict__ bias) {
    const int task = blockIdx.y, bx = blockIdx.x, tid = threadIdx.x;
    if (task <= 1) {
        const float* eW2 = task ? e2W2 : e1W2;
        const float* eb2 = task ? e2b2 : e1b2;
        const float* nW  = task ? n2W  : n1W;
        const float* nb  = task ? n2b  : n1b;
        float* Bcat = task ? B2 : B1;
        float* c = task ? c2 : c1;
        int k = bx, j = tid;
        Bcat[k * 128 + j] = nW[k * 128 + j];
        float acc = 0.f;
        #pragma unroll 4
        for (int t = 0; t < 128; t++) acc += eW2[k * 128 + t] * nW[(128 + t) * 128 + j];
        Bcat[(128 + k) * 128 + j] = acc;
        if (k == 0) {
            float cc = nb[j];
            #pragma unroll 4
            for (int t = 0; t < 128; t++) cc += eb2[t] * nW[(128 + t) * 128 + j];
            c[j] = cc;
        }
    } else if (task == 2) {
        int k = bx, j = tid;
        B3[k * 128 + j] = (j < 64) ? muW[k * 64 + j] : lvW[k * 64 + (j - 64)];
        if (k == 0) b3[j] = (j < 64) ? mub[j] : lvb[j - 64];
    } else {
        int k = tid & 63, half = tid >> 6;
        int n = bx + half * 128;
        float w = (n < 128) ? e1W1[k * 128 + n] : e2W1[k * 128 + (n - 128)];
        __nv_bfloat16 h = __float2bfloat16(w);
        float r = w - __bfloat162float(h);
        bth[n * 64 + k] = h;
        btl[n * 64 + k] = __float2bfloat16(r);
        if (k == 0) bias[n] = (n < 128) ? e1b1[n] : e2b1[n - 128];
    }
}

// node-B transpose+split: Bt[n][k] = B[k][n], hi/lo bf16
__global__ void prep_btn(const float* __restrict__ B1, const float* __restrict__ B2,
                         const float* __restrict__ B3,
                         __nv_bfloat16* __restrict__ b1h, __nv_bfloat16* __restrict__ b1l,
                         __nv_bfloat16* __restrict__ b2h, __nv_bfloat16* __restrict__ b2l,
                         __nv_bfloat16* __restrict__ b3h, __nv_bfloat16* __restrict__ b3l) {
    const int task = blockIdx.y, n = blockIdx.x, k = threadIdx.x;
    const int KT = (task == 2) ? 128 : 256;
    if (k >= KT) return;
    const float* B = (task == 0) ? B1 : (task == 1) ? B2 : B3;
    __nv_bfloat16* bh = (task == 0) ? b1h : (task == 1) ? b2h : b3h;
    __nv_bfloat16* bl = (task == 0) ? b1l : (task == 1) ? b2l : b3l;
    float w = B[k * 128 + n];
    __nv_bfloat16 h = __float2bfloat16(w);
    bh[n * KT + k] = h;
    bl[n * KT + k] = __float2bfloat16(w - __bfloat162float(h));
}

__global__ void deg_kernel(const int* __restrict__ dst, float* __restrict__ deg, int E) {
    int e = blockIdx.x * blockDim.x + threadIdx.x;
    if (e < E) atomicAdd(&deg[dst[e]], 1.0f);
}

// ======================= mma.sync edge pass ================================
// 128-thread CTA (4 warps), tile = 128 edges x ONE layer's 128 cols, K=64.
// layer = blockIdx.x & 1. Per-mt processing: acc live = 16 regs -> 4 CTAs/SM.
#define APITCH 144

__global__ __launch_bounds__(128, 4)
void edge_mma_kernel(const float* __restrict__ ea, const int* __restrict__ dstv,
                     const __nv_bfloat16* __restrict__ Bth,
                     const __nv_bfloat16* __restrict__ Btl,
                     const float* __restrict__ biascat,
                     float* __restrict__ S1, float* __restrict__ S2,
                     int E, int ntiles) {
    __shared__ __align__(16) char sA[2 * 128 * APITCH];  // hi | lo
    __shared__ float sBias[128];
    __shared__ int sDst[128];
    char* sAh = sA;
    char* sAl = sA + 128 * APITCH;

    const int tid = threadIdx.x, wid = tid >> 5, lane = tid & 31;
    const int g = lane >> 2, q = lane & 3;
    const int layer = blockIdx.x & 1;
    const int nbase = layer * 128;
    const int n0 = wid * 32;                 // 0..96 within layer
    float* Sbase = layer ? S2 : S1;

    sBias[tid] = biascat[nbase + tid];

    // ---- B fragments in registers (once; layer fixed per CTA) ----
    uint32_t bh[4][4][2], bl[4][4][2];
    {
        const uint32_t* BH = (const uint32_t*)Bth;
        const uint32_t* BL = (const uint32_t*)Btl;
        #pragma unroll
        for (int nt = 0; nt < 4; nt++) {
            const int n = nbase + n0 + nt * 8 + g;
            #pragma unroll
            for (int kt = 0; kt < 4; kt++) {
                const int base = n * 32 + kt * 8 + q;
                bh[nt][kt][0] = BH[base];
                bh[nt][kt][1] = BH[base + 4];
                bl[nt][kt][0] = BL[base];
                bl[nt][kt][1] = BL[base + 4];
            }
        }
    }

    const int rowoff = (lane & 7) + ((lane >> 3) & 1) * 8;
    const int koff = (lane >> 4) * 16;
    const uint32_t sAh_u = smem_u32(sAh);
    const uint32_t sAl_u = smem_u32(sAl);
    const uint32_t lmBase = (uint32_t)(rowoff * APITCH + koff);

    const int cstride = gridDim.x >> 1;
    for (int tile = blockIdx.x >> 1; tile < ntiles; tile += cstride) {
        const int e0 = tile * 128;
        // ---- stage A tile: conflict-free STS.128 ----
        {
            const int ge = e0 + tid;
            uint4* ah = (uint4*)(sAh + tid * APITCH);
            uint4* al = (uint4*)(sAl + tid * APITCH);
            if (ge < E) {
                const float4* src = (const float4*)(ea + (size_t)ge * 64);
                #pragma unroll
                for (int j = 0; j < 8; j++) {
                    uint4 h, l;
                    split8(src[j * 2], src[j * 2 + 1], h, l);
                    ah[j] = h;
                    al[j] = l;
                }
                sDst[tid] = dstv[ge];
            } else {
                const uint4 z = make_uint4(0, 0, 0, 0);
                #pragma unroll
                for (int j = 0; j < 8; j++) { ah[j] = z; al[j] = z; }
                sDst[tid] = -1;
            }
        }
        __syncthreads();

        // ---- per-mt: MMA + immediate epilogue (acc live = 16 regs) ----
        #pragma unroll
        for (int mt = 0; mt < 8; mt++) {
            float acc[4][4];
            #pragma unroll
            for (int nt = 0; nt < 4; nt++)
                #pragma unroll
                for (int i = 0; i < 4; i++) acc[nt][i] = 0.f;

            const uint32_t mtOff = (uint32_t)(mt * 16 * APITCH) + lmBase;
            #pragma unroll
            for (int kt = 0; kt < 4; kt++) {
                uint32_t ah4[4], al4[4];
                ldsm_x4(ah4, sAh_u + mtOff + kt * 32);
                ldsm_x4(al4, sAl_u + mtOff + kt * 32);
                #pragma unroll
                for (int nt = 0; nt < 4; nt++) {
                    mma16816(acc[nt], ah4, bh[nt][kt][0], bh[nt][kt][1]);
                    mma16816(acc[nt], al4, bh[nt][kt][0], bh[nt][kt][1]);
                    mma16816(acc[nt], ah4, bl[nt][kt][0], bl[nt][kt][1]);
                }
            }

            const int rowLo = mt * 16 + g;
            const int dLo = sDst[rowLo], dHi = sDst[rowLo + 8];
            #pragma unroll
            for (int nt = 0; nt < 4; nt++) {
                float* c = acc[nt];
                const int col = n0 + nt * 8 + q * 2;
                const float b0 = sBias[col], b1 = sBias[col + 1];
                float v0 = lk(c[0] + b0), v1 = lk(c[1] + b1);
                float v2 = lk(c[2] + b0), v3 = lk(c[3] + b1);
                float r0 = __shfl_xor_sync(0xffffffffu, v0, 1);
                float r1 = __shfl_xor_sync(0xffffffffu, v1, 1);
                float r2 = __shfl_xor_sync(0xffffffffu, v2, 1);
                float r3 = __shfl_xor_sync(0xffffffffu, v3, 1);
                const int colb = n0 + nt * 8 + (q >> 1) * 4;
                int d;
                float w0, w1, w2, w3;
                if ((q & 1) == 0) { d = dLo; w0 = v0; w1 = v1; w2 = r0; w3 = r1; }
                else              { d = dHi; w0 = r2; w1 = r3; w2 = v2; w3 = v3; }
                if (d >= 0)
                    red4(&Sbase[(size_t)d * 128 + colb], w0, w1, w2, w3);
            }
        }
        __syncthreads();
    }
}

// ======================= tensor node GEMM (R12, known-good) ================
#define NSM_AH 0
#define NSM_AL 18432
#define NSM_BH 36864
#define NSM_BL 55296
#define NSM_BIAS 73728
#define NSM_DEG 74304
#define NODE_SMEM 74880

template <int KTOT, bool SECOND, bool DOLEAKY, bool SPLIT>
__global__ __launch_bounds__(256, 1) void node_mma(
    const float* __restrict__ A1, const float* __restrict__ A2,
    const __nv_bfloat16* __restrict__ Bth, const __nv_bfloat16* __restrict__ Btl,
    const float* __restrict__ bias, const float* __restrict__ deg,
    float* __restrict__ out, int N) {
    extern __shared__ __align__(16) char smem[];
    char* sAh = smem + NSM_AH;
    char* sAl = smem + NSM_AL;
    char* sBh = smem + NSM_BH;
    char* sBl = smem + NSM_BL;
    float* sBias = (float*)(smem + NSM_BIAS);
    float* sDeg = (float*)(smem + NSM_DEG);

    const int tid = threadIdx.x, wid = tid >> 5, lane = tid & 31;
    const int g = lane >> 2, q = lane & 3;
    const int mhalf = wid >> 2;
    const int n0 = (wid & 3) * 32;
    const int row0 = blockIdx.x * 128;

    if (tid < 128) {
        sBias[tid] = bias[tid];
        if (SECOND) {
            int r = row0 + tid;
            sDeg[tid] = (r < N) ? deg[r] : 0.f;
        }
    }
    __syncthreads();

    float acc[4][4][4];
    #pragma unroll
    for (int mt = 0; mt < 4; mt++) {
        const int rl = mhalf * 64 + mt * 16 + g;
        const float d0 = SECOND ? sDeg[rl] : 1.f;
        const float d1 = SECOND ? sDeg[rl + 8] : 1.f;
        #pragma unroll
        for (int nt = 0; nt < 4; nt++) {
            const int col = n0 + nt * 8 + 2 * q;
            const float b0 = sBias[col], b1 = sBias[col + 1];
            acc[mt][nt][0] = d0 * b0;
            acc[mt][nt][1] = d0 * b1;
            acc[mt][nt][2] = d1 * b0;
            acc[mt][nt][3] = d1 * b1;
        }
    }

    const int rowoff = (lane & 7) + ((lane >> 3) & 1) * 8;
    const uint32_t sAh_u = smem_u32(sAh);
    const uint32_t sAl_u = smem_u32(sAl);
    const uint32_t sBh_u = smem_u32(sBh);
    const uint32_t sBl_u = smem_u32(sBl);
    const uint32_t aBase = (uint32_t)((mhalf * 64 + rowoff) * APITCH + (lane >> 4) * 16);
    const uint32_t bBase = (uint32_t)((n0 + (lane & 7)) * APITCH + ((lane >> 3) & 3) * 16);

    for (int kc = 0; kc < KTOT; kc += 64) {
        __syncthreads();
        // ---- stage A chunk: conflict-free STS.128 ----
        {
            const int row = tid >> 1, hf = tid & 1;
            const int grow = row0 + row;
            uint4* ah = (uint4*)(sAh + row * APITCH + hf * 64);
            uint4* al = (uint4*)(sAl + row * APITCH + hf * 64);
            if (grow < N) {
                const bool a1part = (!SECOND) || (kc < 128);
                const int ksrc = (a1part ? kc : kc - 128) + hf * 32;
                const float* Arow = (a1part ? A1 : A2) + (size_t)grow * 128 + ksrc;
                const float s = (SECOND && a1part) ? sDeg[row] : 1.f;
                const float4* src = (const float4*)Arow;
                #pragma unroll
                for (int j = 0; j < 4; j++) {
                    float4 v0 = src[j * 2], v1 = src[j * 2 + 1];
                    v0.x *= s; v0.y *= s; v0.z *= s; v0.w *= s;
                    v1.x *= s; v1.y *= s; v1.z *= s; v1.w *= s;
                    uint4 h, l;
                    split8(v0, v1, h, l);
                    ah[j] = h;
                    al[j] = l;
                }
            } else {
                const uint4 z = make_uint4(0, 0, 0, 0);
                #pragma unroll
                for (int j = 0; j < 4; j++) { ah[j] = z; al[j] = z; }
            }
        }
        // ---- stage B chunk: 64 bytes per (n, half) ----
        {
            const int n = tid >> 1, hf = tid & 1;
            const uint4* bh4 = (const uint4*)(Bth + (size_t)n * KTOT + kc + hf * 32);
            const uint4* bl4 = (const uint4*)(Btl + (size_t)n * KTOT + kc + hf * 32);
            uint4* dh = (uint4*)(sBh + n * APITCH + hf * 64);
            uint4* dl = (uint4*)(sBl + n * APITCH + hf * 64);
            dh[0] = bh4[0]; dh[1] = bh4[1]; dh[2] = bh4[2]; dh[3] = bh4[3];
            dl[0] = bl4[0]; dl[1] = bl4[1]; dl[2] = bl4[2]; dl[3] = bl4[3];
        }
        __syncthreads();

        // ---- MMA ----
        #pragma unroll
        for (int ktp = 0; ktp < 2; ktp++) {
            uint32_t bhf[4][4], blf[4][4];
            #pragma unroll
            for (int nt = 0; nt < 4; nt++) {
                ldsm_x4(bhf[nt], sBh_u + bBase + (uint32_t)(nt * 8 * APITCH) + ktp * 64);
                ldsm_x4(blf[nt], sBl_u + bBase + (uint32_t)(nt * 8 * APITCH) + ktp * 64);
            }
            #pragma unroll
            for (int mt = 0; mt < 4; mt++) {
                #pragma unroll
                for (int kt2 = 0; kt2 < 2; kt2++) {
                    uint32_t ah4[4], al4[4];
                    const uint32_t ao = aBase + (uint32_t)(mt * 16 * APITCH) +
                                        ktp * 64 + kt2 * 32;
                    ldsm_x4(ah4, sAh_u + ao);
                    ldsm_x4(al4, sAl_u + ao);
                    #pragma unroll
                    for (int nt = 0; nt < 4; nt++) {
                        mma16816(acc[mt][nt], ah4, bhf[nt][kt2 * 2], bhf[nt][kt2 * 2 + 1]);
                        mma16816(acc[mt][nt], al4, bhf[nt][kt2 * 2], bhf[nt][kt2 * 2 + 1]);
                        mma16816(acc[mt][nt], ah4, blf[nt][kt2 * 2], blf[nt][kt2 * 2 + 1]);
                    }
                }
            }
        }
    }

    // ---- epilogue ----
    #pragma unroll
    for (int mt = 0; mt < 4; mt++) {
        const int r0g = row0 + mhalf * 64 + mt * 16 + g;
        #pragma unroll
        for (int nt = 0; nt < 4; nt++) {
            float* c = acc[mt][nt];
            const int col = n0 + nt * 8 + 2 * q;
            float v0 = c[0], v1 = c[1], v2 = c[2], v3 = c[3];
            if (DOLEAKY) { v0 = lk(v0); v1 = lk(v1); v2 = lk(v2); v3 = lk(v3); }
            if (!SPLIT) {
                if (r0g < N)     *(float2*)&out[(size_t)r0g * 128 + col] = make_float2(v0, v1);
                if (r0g + 8 < N) *(float2*)&out[(size_t)(r0g + 8) * 128 + col] = make_float2(v2, v3);
            } else {
                float* dstp = (col < 64) ? (out + (size_t)0 * 64)
                                         : (out + (size_t)N * 64 - 64);
                if (r0g < N)     *(float2*)&dstp[(size_t)r0g * 64 + col] = make_float2(v0, v1);
                if (r0g + 8 < N) *(float2*)&dstp[(size_t)(r0g + 8) * 64 + col] = make_float2(v2, v3);
            }
        }
    }
}

// ---------------------------------------------------------------------------
extern "C" void kernel_launch(void* const* d_in, const int* in_sizes, int n_in,
                              void* d_out, int out_size) {
    const float* x    = (const float*)d_in[0];
    const int*   ei   = (const int*)d_in[1];
    const float* ea   = (const float*)d_in[2];
    const float* e1W1 = (const float*)d_in[3];
    const float* e1b1 = (const float*)d_in[4];
    const float* e1W2 = (const float*)d_in[5];
    const float* e1b2 = (const float*)d_in[6];
    const float* n1W  = (const float*)d_in[7];
    const float* n1b  = (const float*)d_in[8];
    const float* e2W1 = (const float*)d_in[9];
    const float* e2b1 = (const float*)d_in[10];
    const float* e2W2 = (const float*)d_in[11];
    const float* e2b2 = (const float*)d_in[12];
    const float* n2W  = (const float*)d_in[13];
    const float* n2b  = (const float*)d_in[14];
    const float* muW  = (const float*)d_in[15];
    const float* mub  = (const float*)d_in[16];
    const float* lvW  = (const float*)d_in[17];
    const float* lvb  = (const float*)d_in[18];

    const int N = in_sizes[0] / 128;  // 50000
    const int E = in_sizes[2] / 64;   // 640000
    const int* dst = ei + E;          // edge_index row 1

    float *S1, *S2, *h1, *h2, *dg, *B1, *B2, *c1, *c2, *B3, *b3, *biascat;
    __nv_bfloat16 *Bth, *Btl, *B1th, *B1tl, *B2th, *B2tl, *B3th, *B3tl;
    cudaGetSymbolAddress((void**)&S1, g_S1);
    cudaGetSymbolAddress((void**)&S2, g_S2);
    cudaGetSymbolAddress((void**)&h1, g_h1);
    cudaGetSymbolAddress((void**)&h2, g_h2);
    cudaGetSymbolAddress((void**)&dg, g_deg);
    cudaGetSymbolAddress((void**)&B1, g_B1);
    cudaGetSymbolAddress((void**)&B2, g_B2);
    cudaGetSymbolAddress((void**)&c1, g_c1);
    cudaGetSymbolAddress((void**)&c2, g_c2);
    cudaGetSymbolAddress((void**)&B3, g_B3);
    cudaGetSymbolAddress((void**)&b3, g_b3);
    cudaGetSymbolAddress((void**)&Bth, g_Bth);
    cudaGetSymbolAddress((void**)&Btl, g_Btl);
    cudaGetSymbolAddress((void**)&biascat, g_biascat);
    cudaGetSymbolAddress((void**)&B1th, g_B1th);
    cudaGetSymbolAddress((void**)&B1tl, g_B1tl);
    cudaGetSymbolAddress((void**)&B2th, g_B2th);
    cudaGetSymbolAddress((void**)&B2tl, g_B2tl);
    cudaGetSymbolAddress((void**)&B3th, g_B3th);
    cudaGetSymbolAddress((void**)&B3tl, g_B3tl);

    cudaMemsetAsync(S1, 0, (size_t)N * 128 * sizeof(float));
    cudaMemsetAsync(S2, 0, (size_t)N * 128 * sizeof(float));
    cudaMemsetAsync(dg, 0, (size_t)N * sizeof(float));

    prep_all<<<dim3(128, 4), 128>>>(e1W2, e1b2, n1W, n1b,
                                    e2W2, e2b2, n2W, n2b,
                                    muW, mub, lvW, lvb,
                                    e1W1, e1b1, e2W1, e2b1,
                                    B1, c1, B2, c2, B3, b3, Bth, Btl, biascat);
    prep_btn<<<dim3(128, 3), 256>>>(B1, B2, B3, B1th, B1tl, B2th, B2tl, B3th, B3tl);
    deg_kernel<<<(E + 255) / 256, 256>>>(dst, dg, E);

    int ntiles = (E + 127) / 128;
    edge_mma_kernel<<<592, 128>>>(ea, dst, Bth, Btl, biascat, S1, S2, E, ntiles);

    int nblk = (N + 127) / 128;  // 391
    cudaFuncSetAttribute(node_mma<256, true, true, false>,
                         cudaFuncAttributeMaxDynamicSharedMemorySize, NODE_SMEM);
    cudaFuncSetAttribute(node_mma<128, false, false, true>,
                         cudaFuncAttributeMaxDynamicSharedMemorySize, NODE_SMEM);

    node_mma<256, true, true, false><<<nblk, 256, NODE_SMEM>>>(x,  S1, B1th, B1tl, c1, dg, h1, N);
    node_mma<256, true, true, false><<<nblk, 256, NODE_SMEM>>>(h1, S2, B2th, B2tl, c2, dg, h2, N);
    node_mma<128, false, false, true><<<nblk, 256, NODE_SMEM>>>(h2, nullptr, B3th, B3tl, b3,
                                                                nullptr, (float*)d_out, N);
}

// round 14
// speedup vs baseline: 1.8381x; 1.0309x over previous
#include <cuda_runtime.h>
#include <cuda_bf16.h>
#include <cstdint>
#include <cstdio>

// ---------------------------------------------------------------------------
// EdgeVGAE encoder, algebraically collapsed:
//   S_l = segment_sum(leaky(edge_attr @ W1_l + b1_l), dst)   (edge pass, l=1,2)
//   h1  = leaky(deg*(x @ n1Wx + c1) + S1 @ M1)
//   h2  = leaky(deg*(h1 @ n2Wh + c2) + S2 @ M2)
//   mu|lv = h2 @ [muW|lvW] + [mub|lvb]
// R14: edge kernel L1TEX-bound (86%). Warp width 32->64 cols, both layers
// per CTA: A-LDSM redundancy halved, edge staging (LDG+cvt+STS) halved.
// B hi+lo frags for 8 n-groups in 128 regs; 2 CTAs/SM.
// ---------------------------------------------------------------------------

typedef unsigned long long u64;

#define NMAX 50048

__device__ float g_S1[NMAX * 128];
__device__ float g_S2[NMAX * 128];
__device__ float g_h1[NMAX * 128];
__device__ float g_h2[NMAX * 128];
__device__ float g_deg[NMAX];
__device__ float g_B1[256 * 128];
__device__ float g_B2[256 * 128];
__device__ float g_c1[128];
__device__ float g_c2[128];
__device__ float g_B3[128 * 128];
__device__ float g_b3[128];
__device__ __nv_bfloat16 g_Bth[256 * 64];   // edge weights^T hi
__device__ __nv_bfloat16 g_Btl[256 * 64];   // edge weights^T lo
__device__ float g_biascat[256];
__device__ __nv_bfloat16 g_B1th[128 * 256], g_B1tl[128 * 256];  // node B^T splits
__device__ __nv_bfloat16 g_B2th[128 * 256], g_B2tl[128 * 256];
__device__ __nv_bfloat16 g_B3th[128 * 128], g_B3tl[128 * 128];

// ============================ helpers ======================================
__device__ __forceinline__ uint32_t smem_u32(const void* p) {
    uint32_t a;
    asm("{ .reg .u64 t; cvta.to.shared.u64 t, %1; cvt.u32.u64 %0, t; }" : "=r"(a) : "l"(p));
    return a;
}
__device__ __forceinline__ float lk(float v) { return fmaxf(v, 0.15f * v); }
__device__ __forceinline__ void red4(float* p, float a, float b, float c, float d) {
    asm volatile("red.global.add.v4.f32 [%0], {%1, %2, %3, %4};"
                 :: "l"((u64)(uintptr_t)p), "f"(a), "f"(b), "f"(c), "f"(d) : "memory");
}
// mma.sync m16n8k16 bf16 -> f32, accumulate in place
__device__ __forceinline__ void mma16816(float* c, const uint32_t* a,
                                         uint32_t b0, uint32_t b1) {
    asm volatile(
        "mma.sync.aligned.m16n8k16.row.col.f32.bf16.bf16.f32 "
        "{%0,%1,%2,%3}, {%4,%5,%6,%7}, {%8,%9}, {%0,%1,%2,%3};"
        : "+f"(c[0]), "+f"(c[1]), "+f"(c[2]), "+f"(c[3])
        : "r"(a[0]), "r"(a[1]), "r"(a[2]), "r"(a[3]), "r"(b0), "r"(b1));
}
__device__ __forceinline__ void ldsm_x4(uint32_t* r, uint32_t addr) {
    asm volatile("ldmatrix.sync.aligned.m8n8.x4.shared.b16 {%0,%1,%2,%3}, [%4];"
                 : "=r"(r[0]), "=r"(r[1]), "=r"(r[2]), "=r"(r[3]) : "r"(addr));
}
__device__ __forceinline__ void split2(float a0, float a1, uint32_t& h, uint32_t& l) {
    __nv_bfloat162 h2 = __floats2bfloat162_rn(a0, a1);
    __nv_bfloat162 l2 = __floats2bfloat162_rn(a0 - __low2float(h2), a1 - __high2float(h2));
    h = *(uint32_t*)&h2;
    l = *(uint32_t*)&l2;
}
__device__ __forceinline__ void split8(float4 v0, float4 v1, uint4& h, uint4& l) {
    split2(v0.x, v0.y, h.x, l.x);
    split2(v0.z, v0.w, h.y, l.y);
    split2(v1.x, v1.y, h.z, l.z);
    split2(v1.z, v1.w, h.w, l.w);
}

// ======================= merged precompute =================================
__global__ void prep_all(const float* __restrict__ e1W2, const float* __restrict__ e1b2,
                         const float* __restrict__ n1W,  const float* __restrict__ n1b,
                         const float* __restrict__ e2W2, const float* __restrict__ e2b2,
                         const float* __restrict__ n2W,  const float* __restrict__ n2b,
                         const float* __restrict__ muW,  const float* __restrict__ mub,
                         const float* __restrict__ lvW,  const float* __restrict__ lvb,
                         const float* __restrict__ e1W1, const float* __restrict__ e1b1,
                         const float* __restrict__ e2W1, const float* __restrict__ e2b1,
                         float* __restrict__ B1, float* __restrict__ c1,
                         float* __restrict__ B2, float* __restrict__ c2,
                         float* __restrict__ B3, float* __restrict__ b3,
                         __nv_bfloat16* __restrict__ bth, __nv_bfloat16* __restrict__ btl,
                         float* __restrict__ bias) {
    const int task = blockIdx.y, bx = blockIdx.x, tid = threadIdx.x;
    if (task <= 1) {
        const float* eW2 = task ? e2W2 : e1W2;
        const float* eb2 = task ? e2b2 : e1b2;
        const float* nW  = task ? n2W  : n1W;
        const float* nb  = task ? n2b  : n1b;
        float* Bcat = task ? B2 : B1;
        float* c = task ? c2 : c1;
        int k = bx, j = tid;
        Bcat[k * 128 + j] = nW[k * 128 + j];
        float acc = 0.f;
        #pragma unroll 4
        for (int t = 0; t < 128; t++) acc += eW2[k * 128 + t] * nW[(128 + t) * 128 + j];
        Bcat[(128 + k) * 128 + j] = acc;
        if (k == 0) {
            float cc = nb[j];
            #pragma unroll 4
            for (int t = 0; t < 128; t++) cc += eb2[t] * nW[(128 + t) * 128 + j];
            c[j] = cc;
        }
    } else if (task == 2) {
        int k = bx, j = tid;
        B3[k * 128 + j] = (j < 64) ? muW[k * 64 + j] : lvW[k * 64 + (j - 64)];
        if (k == 0) b3[j] = (j < 64) ? mub[j] : lvb[j - 64];
    } else {
        int k = tid & 63, half = tid >> 6;
        int n = bx + half * 128;
        float w = (n < 128) ? e1W1[k * 128 + n] : e2W1[k * 128 + (n - 128)];
        __nv_bfloat16 h = __float2bfloat16(w);
        float r = w - __bfloat162float(h);
        bth[n * 64 + k] = h;
        btl[n * 64 + k] = __float2bfloat16(r);
        if (k == 0) bias[n] = (n < 128) ? e1b1[n] : e2b1[n - 128];
    }
}

// node-B transpose+split: Bt[n][k] = B[k][n], hi/lo bf16
__global__ void prep_btn(const float* __restrict__ B1, const float* __restrict__ B2,
                         const float* __restrict__ B3,
                         __nv_bfloat16* __restrict__ b1h, __nv_bfloat16* __restrict__ b1l,
                         __nv_bfloat16* __restrict__ b2h, __nv_bfloat16* __restrict__ b2l,
                         __nv_bfloat16* __restrict__ b3h, __nv_bfloat16* __restrict__ b3l) {
    const int task = blockIdx.y, n = blockIdx.x, k = threadIdx.x;
    const int KT = (task == 2) ? 128 : 256;
    if (k >= KT) return;
    const float* B = (task == 0) ? B1 : (task == 1) ? B2 : B3;
    __nv_bfloat16* bh = (task == 0) ? b1h : (task == 1) ? b2h : b3h;
    __nv_bfloat16* bl = (task == 0) ? b1l : (task == 1) ? b2l : b3l;
    float w = B[k * 128 + n];
    __nv_bfloat16 h = __float2bfloat16(w);
    bh[n * KT + k] = h;
    bl[n * KT + k] = __float2bfloat16(w - __bfloat162float(h));
}

__global__ void deg_kernel(const int* __restrict__ dst, float* __restrict__ deg, int E) {
    int e = blockIdx.x * blockDim.x + threadIdx.x;
    if (e < E) atomicAdd(&deg[dst[e]], 1.0f);
}

// ======================= mma.sync edge pass ================================
// 128-thread CTA (4 warps), tile = 128 edges x 256 cols (BOTH layers), K=64.
// Warp w owns concat cols [64w, 64w+64): warps 0-1 -> S1, 2-3 -> S2.
// B hi+lo frags (8 n-groups) in 128 regs. A staged once per tile. 2 CTAs/SM.
#define APITCH 144

__global__ __launch_bounds__(128, 2)
void edge_mma_kernel(const float* __restrict__ ea, const int* __restrict__ dstv,
                     const __nv_bfloat16* __restrict__ Bth,
                     const __nv_bfloat16* __restrict__ Btl,
                     const float* __restrict__ biascat,
                     float* __restrict__ S1, float* __restrict__ S2,
                     int E, int ntiles) {
    __shared__ __align__(16) char sA[2 * 128 * APITCH];  // hi | lo
    __shared__ float sBias[256];
    __shared__ int sDst[128];
    char* sAh = sA;
    char* sAl = sA + 128 * APITCH;

    const int tid = threadIdx.x, wid = tid >> 5, lane = tid & 31;
    const int g = lane >> 2, q = lane & 3;
    const int colbase = wid * 64;            // in 256-concat
    const int layer = wid >> 1;
    const int lcolbase = colbase - layer * 128;  // in-layer col base (0 or 64)
    float* Sbase = layer ? S2 : S1;

    sBias[tid] = biascat[tid];
    sBias[tid + 128] = biascat[tid + 128];

    // ---- B fragments in registers: 8 n-groups, hi+lo ----
    uint32_t bh[8][4][2], bl[8][4][2];
    {
        const uint32_t* BH = (const uint32_t*)Bth;
        const uint32_t* BL = (const uint32_t*)Btl;
        #pragma unroll
        for (int nt = 0; nt < 8; nt++) {
            const int n = colbase + nt * 8 + g;
            #pragma unroll
            for (int kt = 0; kt < 4; kt++) {
                const int base = n * 32 + kt * 8 + q;
                bh[nt][kt][0] = BH[base];
                bh[nt][kt][1] = BH[base + 4];
                bl[nt][kt][0] = BL[base];
                bl[nt][kt][1] = BL[base + 4];
            }
        }
    }

    const int rowoff = (lane & 7) + ((lane >> 3) & 1) * 8;
    const int koff = (lane >> 4) * 16;
    const uint32_t sAh_u = smem_u32(sAh);
    const uint32_t sAl_u = smem_u32(sAl);
    const uint32_t lmBase = (uint32_t)(rowoff * APITCH + koff);

    for (int tile = blockIdx.x; tile < ntiles; tile += gridDim.x) {
        const int e0 = tile * 128;
        // ---- stage A tile once (conflict-free STS.128) ----
        {
            const int ge = e0 + tid;
            uint4* ah = (uint4*)(sAh + tid * APITCH);
            uint4* al = (uint4*)(sAl + tid * APITCH);
            if (ge < E) {
                const float4* src = (const float4*)(ea + (size_t)ge * 64);
                #pragma unroll
                for (int j = 0; j < 8; j++) {
                    uint4 h, l;
                    split8(src[j * 2], src[j * 2 + 1], h, l);
                    ah[j] = h;
                    al[j] = l;
                }
                sDst[tid] = dstv[ge];
            } else {
                const uint4 z = make_uint4(0, 0, 0, 0);
                #pragma unroll
                for (int j = 0; j < 8; j++) { ah[j] = z; al[j] = z; }
                sDst[tid] = -1;
            }
        }
        __syncthreads();

        // ---- per-mt: MMA over 8 n-groups + immediate epilogue ----
        #pragma unroll
        for (int mt = 0; mt < 8; mt++) {
            float acc[8][4];
            #pragma unroll
            for (int nt = 0; nt < 8; nt++)
                #pragma unroll
                for (int i = 0; i < 4; i++) acc[nt][i] = 0.f;

            const uint32_t mtOff = (uint32_t)(mt * 16 * APITCH) + lmBase;
            #pragma unroll
            for (int kt = 0; kt < 4; kt++) {
                uint32_t ah4[4], al4[4];
                ldsm_x4(ah4, sAh_u + mtOff + kt * 32);
                ldsm_x4(al4, sAl_u + mtOff + kt * 32);
                #pragma unroll
                for (int nt = 0; nt < 8; nt++) {
                    mma16816(acc[nt], ah4, bh[nt][kt][0], bh[nt][kt][1]);
                    mma16816(acc[nt], al4, bh[nt][kt][0], bh[nt][kt][1]);
                    mma16816(acc[nt], ah4, bl[nt][kt][0], bl[nt][kt][1]);
                }
            }

            const int rowLo = mt * 16 + g;
            const int dLo = sDst[rowLo], dHi = sDst[rowLo + 8];
            #pragma unroll
            for (int nt = 0; nt < 8; nt++) {
                float* c = acc[nt];
                const int col = colbase + nt * 8 + q * 2;   // concat col (bias)
                const float b0 = sBias[col], b1 = sBias[col + 1];
                float v0 = lk(c[0] + b0), v1 = lk(c[1] + b1);
                float v2 = lk(c[2] + b0), v3 = lk(c[3] + b1);
                float r0 = __shfl_xor_sync(0xffffffffu, v0, 1);
                float r1 = __shfl_xor_sync(0xffffffffu, v1, 1);
                float r2 = __shfl_xor_sync(0xffffffffu, v2, 1);
                float r3 = __shfl_xor_sync(0xffffffffu, v3, 1);
                const int colb = lcolbase + nt * 8 + (q >> 1) * 4;  // in-layer col
                int d;
                float w0, w1, w2, w3;
                if ((q & 1) == 0) { d = dLo; w0 = v0; w1 = v1; w2 = r0; w3 = r1; }
                else              { d = dHi; w0 = r2; w1 = r3; w2 = v2; w3 = v3; }
                if (d >= 0)
                    red4(&Sbase[(size_t)d * 128 + colb], w0, w1, w2, w3);
            }
        }
        __syncthreads();
    }
}

// ======================= tensor node GEMM (R12, known-good) ================
#define NSM_AH 0
#define NSM_AL 18432
#define NSM_BH 36864
#define NSM_BL 55296
#define NSM_BIAS 73728
#define NSM_DEG 74304
#define NODE_SMEM 74880

template <int KTOT, bool SECOND, bool DOLEAKY, bool SPLIT>
__global__ __launch_bounds__(256, 1) void node_mma(
    const float* __restrict__ A1, const float* __restrict__ A2,
    const __nv_bfloat16* __restrict__ Bth, const __nv_bfloat16* __restrict__ Btl,
    const float* __restrict__ bias, const float* __restrict__ deg,
    float* __restrict__ out, int N) {
    extern __shared__ __align__(16) char smem[];
    char* sAh = smem + NSM_AH;
    char* sAl = smem + NSM_AL;
    char* sBh = smem + NSM_BH;
    char* sBl = smem + NSM_BL;
    float* sBias = (float*)(smem + NSM_BIAS);
    float* sDeg = (float*)(smem + NSM_DEG);

    const int tid = threadIdx.x, wid = tid >> 5, lane = tid & 31;
    const int g = lane >> 2, q = lane & 3;
    const int mhalf = wid >> 2;
    const int n0 = (wid & 3) * 32;
    const int row0 = blockIdx.x * 128;

    if (tid < 128) {
        sBias[tid] = bias[tid];
        if (SECOND) {
            int r = row0 + tid;
            sDeg[tid] = (r < N) ? deg[r] : 0.f;
        }
    }
    __syncthreads();

    float acc[4][4][4];
    #pragma unroll
    for (int mt = 0; mt < 4; mt++) {
        const int rl = mhalf * 64 + mt * 16 + g;
        const float d0 = SECOND ? sDeg[rl] : 1.f;
        const float d1 = SECOND ? sDeg[rl + 8] : 1.f;
        #pragma unroll
        for (int nt = 0; nt < 4; nt++) {
            const int col = n0 + nt * 8 + 2 * q;
            const float b0 = sBias[col], b1 = sBias[col + 1];
            acc[mt][nt][0] = d0 * b0;
            acc[mt][nt][1] = d0 * b1;
            acc[mt][nt][2] = d1 * b0;
            acc[mt][nt][3] = d1 * b1;
        }
    }

    const int rowoff = (lane & 7) + ((lane >> 3) & 1) * 8;
    const uint32_t sAh_u = smem_u32(sAh);
    const uint32_t sAl_u = smem_u32(sAl);
    const uint32_t sBh_u = smem_u32(sBh);
    const uint32_t sBl_u = smem_u32(sBl);
    const uint32_t aBase = (uint32_t)((mhalf * 64 + rowoff) * APITCH + (lane >> 4) * 16);
    const uint32_t bBase = (uint32_t)((n0 + (lane & 7)) * APITCH + ((lane >> 3) & 3) * 16);

    for (int kc = 0; kc < KTOT; kc += 64) {
        __syncthreads();
        // ---- stage A chunk: conflict-free STS.128 ----
        {
            const int row = tid >> 1, hf = tid & 1;
            const int grow = row0 + row;
            uint4* ah = (uint4*)(sAh + row * APITCH + hf * 64);
            uint4* al = (uint4*)(sAl + row * APITCH + hf * 64);
            if (grow < N) {
                const bool a1part = (!SECOND) || (kc < 128);
                const int ksrc = (a1part ? kc : kc - 128) + hf * 32;
                const float* Arow = (a1part ? A1 : A2) + (size_t)grow * 128 + ksrc;
                const float s = (SECOND && a1part) ? sDeg[row] : 1.f;
                const float4* src = (const float4*)Arow;
                #pragma unroll
                for (int j = 0; j < 4; j++) {
                    float4 v0 = src[j * 2], v1 = src[j * 2 + 1];
                    v0.x *= s; v0.y *= s; v0.z *= s; v0.w *= s;
                    v1.x *= s; v1.y *= s; v1.z *= s; v1.w *= s;
                    uint4 h, l;
                    split8(v0, v1, h, l);
                    ah[j] = h;
                    al[j] = l;
                }
            } else {
                const uint4 z = make_uint4(0, 0, 0, 0);
                #pragma unroll
                for (int j = 0; j < 4; j++) { ah[j] = z; al[j] = z; }
            }
        }
        // ---- stage B chunk: 64 bytes per (n, half) ----
        {
            const int n = tid >> 1, hf = tid & 1;
            const uint4* bh4 = (const uint4*)(Bth + (size_t)n * KTOT + kc + hf * 32);
            const uint4* bl4 = (const uint4*)(Btl + (size_t)n * KTOT + kc + hf * 32);
            uint4* dh = (uint4*)(sBh + n * APITCH + hf * 64);
            uint4* dl = (uint4*)(sBl + n * APITCH + hf * 64);
            dh[0] = bh4[0]; dh[1] = bh4[1]; dh[2] = bh4[2]; dh[3] = bh4[3];
            dl[0] = bl4[0]; dl[1] = bl4[1]; dl[2] = bl4[2]; dl[3] = bl4[3];
        }
        __syncthreads();

        // ---- MMA ----
        #pragma unroll
        for (int ktp = 0; ktp < 2; ktp++) {
            uint32_t bhf[4][4], blf[4][4];
            #pragma unroll
            for (int nt = 0; nt < 4; nt++) {
                ldsm_x4(bhf[nt], sBh_u + bBase + (uint32_t)(nt * 8 * APITCH) + ktp * 64);
                ldsm_x4(blf[nt], sBl_u + bBase + (uint32_t)(nt * 8 * APITCH) + ktp * 64);
            }
            #pragma unroll
            for (int mt = 0; mt < 4; mt++) {
                #pragma unroll
                for (int kt2 = 0; kt2 < 2; kt2++) {
                    uint32_t ah4[4], al4[4];
                    const uint32_t ao = aBase + (uint32_t)(mt * 16 * APITCH) +
                                        ktp * 64 + kt2 * 32;
                    ldsm_x4(ah4, sAh_u + ao);
                    ldsm_x4(al4, sAl_u + ao);
                    #pragma unroll
                    for (int nt = 0; nt < 4; nt++) {
                        mma16816(acc[mt][nt], ah4, bhf[nt][kt2 * 2], bhf[nt][kt2 * 2 + 1]);
                        mma16816(acc[mt][nt], al4, bhf[nt][kt2 * 2], bhf[nt][kt2 * 2 + 1]);
                        mma16816(acc[mt][nt], ah4, blf[nt][kt2 * 2], blf[nt][kt2 * 2 + 1]);
                    }
                }
            }
        }
    }

    // ---- epilogue ----
    #pragma unroll
    for (int mt = 0; mt < 4; mt++) {
        const int r0g = row0 + mhalf * 64 + mt * 16 + g;
        #pragma unroll
        for (int nt = 0; nt < 4; nt++) {
            float* c = acc[mt][nt];
            const int col = n0 + nt * 8 + 2 * q;
            float v0 = c[0], v1 = c[1], v2 = c[2], v3 = c[3];
            if (DOLEAKY) { v0 = lk(v0); v1 = lk(v1); v2 = lk(v2); v3 = lk(v3); }
            if (!SPLIT) {
                if (r0g < N)     *(float2*)&out[(size_t)r0g * 128 + col] = make_float2(v0, v1);
                if (r0g + 8 < N) *(float2*)&out[(size_t)(r0g + 8) * 128 + col] = make_float2(v2, v3);
            } else {
                float* dstp = (col < 64) ? (out + (size_t)0 * 64)
                                         : (out + (size_t)N * 64 - 64);
                if (r0g < N)     *(float2*)&dstp[(size_t)r0g * 64 + col] = make_float2(v0, v1);
                if (r0g + 8 < N) *(float2*)&dstp[(size_t)(r0g + 8) * 64 + col] = make_float2(v2, v3);
            }
        }
    }
}

// ---------------------------------------------------------------------------
extern "C" void kernel_launch(void* const* d_in, const int* in_sizes, int n_in,
                              void* d_out, int out_size) {
    const float* x    = (const float*)d_in[0];
    const int*   ei   = (const int*)d_in[1];
    const float* ea   = (const float*)d_in[2];
    const float* e1W1 = (const float*)d_in[3];
    const float* e1b1 = (const float*)d_in[4];
    const float* e1W2 = (const float*)d_in[5];
    const float* e1b2 = (const float*)d_in[6];
    const float* n1W  = (const float*)d_in[7];
    const float* n1b  = (const float*)d_in[8];
    const float* e2W1 = (const float*)d_in[9];
    const float* e2b1 = (const float*)d_in[10];
    const float* e2W2 = (const float*)d_in[11];
    const float* e2b2 = (const float*)d_in[12];
    const float* n2W  = (const float*)d_in[13];
    const float* n2b  = (const float*)d_in[14];
    const float* muW  = (const float*)d_in[15];
    const float* mub  = (const float*)d_in[16];
    const float* lvW  = (const float*)d_in[17];
    const float* lvb  = (const float*)d_in[18];

    const int N = in_sizes[0] / 128;  // 50000
    const int E = in_sizes[2] / 64;   // 640000
    const int* dst = ei + E;          // edge_index row 1

    float *S1, *S2, *h1, *h2, *dg, *B1, *B2, *c1, *c2, *B3, *b3, *biascat;
    __nv_bfloat16 *Bth, *Btl, *B1th, *B1tl, *B2th, *B2tl, *B3th, *B3tl;
    cudaGetSymbolAddress((void**)&S1, g_S1);
    cudaGetSymbolAddress((void**)&S2, g_S2);
    cudaGetSymbolAddress((void**)&h1, g_h1);
    cudaGetSymbolAddress((void**)&h2, g_h2);
    cudaGetSymbolAddress((void**)&dg, g_deg);
    cudaGetSymbolAddress((void**)&B1, g_B1);
    cudaGetSymbolAddress((void**)&B2, g_B2);
    cudaGetSymbolAddress((void**)&c1, g_c1);
    cudaGetSymbolAddress((void**)&c2, g_c2);
    cudaGetSymbolAddress((void**)&B3, g_B3);
    cudaGetSymbolAddress((void**)&b3, g_b3);
    cudaGetSymbolAddress((void**)&Bth, g_Bth);
    cudaGetSymbolAddress((void**)&Btl, g_Btl);
    cudaGetSymbolAddress((void**)&biascat, g_biascat);
    cudaGetSymbolAddress((void**)&B1th, g_B1th);
    cudaGetSymbolAddress((void**)&B1tl, g_B1tl);
    cudaGetSymbolAddress((void**)&B2th, g_B2th);
    cudaGetSymbolAddress((void**)&B2tl, g_B2tl);
    cudaGetSymbolAddress((void**)&B3th, g_B3th);
    cudaGetSymbolAddress((void**)&B3tl, g_B3tl);

    cudaMemsetAsync(S1, 0, (size_t)N * 128 * sizeof(float));
    cudaMemsetAsync(S2, 0, (size_t)N * 128 * sizeof(float));
    cudaMemsetAsync(dg, 0, (size_t)N * sizeof(float));

    prep_all<<<dim3(128, 4), 128>>>(e1W2, e1b2, n1W, n1b,
                                    e2W2, e2b2, n2W, n2b,
                                    muW, mub, lvW, lvb,
                                    e1W1, e1b1, e2W1, e2b1,
                                    B1, c1, B2, c2, B3, b3, Bth, Btl, biascat);
    prep_btn<<<dim3(128, 3), 256>>>(B1, B2, B3, B1th, B1tl, B2th, B2tl, B3th, B3tl);
    deg_kernel<<<(E + 255) / 256, 256>>>(dst, dg, E);

    int ntiles = (E + 127) / 128;
    edge_mma_kernel<<<296, 128>>>(ea, dst, Bth, Btl, biascat, S1, S2, E, ntiles);

    int nblk = (N + 127) / 128;  // 391
    cudaFuncSetAttribute(node_mma<256, true, true, false>,
                         cudaFuncAttributeMaxDynamicSharedMemorySize, NODE_SMEM);
    cudaFuncSetAttribute(node_mma<128, false, false, true>,
                         cudaFuncAttributeMaxDynamicSharedMemorySize, NODE_SMEM);

    node_mma<256, true, true, false><<<nblk, 256, NODE_SMEM>>>(x,  S1, B1th, B1tl, c1, dg, h1, N);
    node_mma<256, true, true, false><<<nblk, 256, NODE_SMEM>>>(h1, S2, B2th, B2tl, c2, dg, h2, N);
    node_mma<128, false, false, true><<<nblk, 256, NODE_SMEM>>>(h2, nullptr, B3th, B3tl, b3,
                                                                nullptr, (float*)d_out, N);
}

// round 17
// speedup vs baseline: 1.9987x; 1.0874x over previous
#include <cuda_runtime.h>
#include <cuda_fp16.h>
#include <cstdint>
#include <cstdio>

// ---------------------------------------------------------------------------
// EdgeVGAE encoder, algebraically collapsed:
//   S_l = segment_sum(leaky(edge_attr @ W1_l + b1_l), dst)   (edge pass, l=1,2)
//   h1  = leaky(deg*(x @ n1Wx + c1) + S1 @ M1)
//   h2  = leaky(deg*(h1 @ n2Wh + c2) + S2 @ M2)
//   mu|lv = h2 @ [muW|lvW] + [mub|lvb]
// R15: precision scheme bf16-3term -> fp16-2term (A single fp16, B hi/lo
// fp16): MMA count x2/3 (tensor floor 104->69us on edge), A staging halved.
// Error source is A's fp16 rounding 2^-11 -> predicted rel_err ~1.5e-4.
// ---------------------------------------------------------------------------

typedef unsigned long long u64;

#define NMAX 50048

__device__ float g_S1[NMAX * 128];
__device__ float g_S2[NMAX * 128];
__device__ float g_h1[NMAX * 128];
__device__ float g_h2[NMAX * 128];
__device__ float g_deg[NMAX];
__device__ float g_B1[256 * 128];
__device__ float g_B2[256 * 128];
__device__ float g_c1[128];
__device__ float g_c2[128];
__device__ float g_B3[128 * 128];
__device__ float g_b3[128];
__device__ __half g_Bth[256 * 64];   // edge weights^T hi (fp16)
__device__ __half g_Btl[256 * 64];   // edge weights^T lo (fp16)
__device__ float g_biascat[256];
__device__ __half g_B1th[128 * 256], g_B1tl[128 * 256];  // node B^T splits (fp16)
__device__ __half g_B2th[128 * 256], g_B2tl[128 * 256];
__device__ __half g_B3th[128 * 128], g_B3tl[128 * 128];

// ============================ helpers ======================================
__device__ __forceinline__ uint32_t smem_u32(const void* p) {
    uint32_t a;
    asm("{ .reg .u64 t; cvta.to.shared.u64 t, %1; cvt.u32.u64 %0, t; }" : "=r"(a) : "l"(p));
    return a;
}
__device__ __forceinline__ float lk(float v) { return fmaxf(v, 0.15f * v); }
__device__ __forceinline__ void red4(float* p, float a, float b, float c, float d) {
    asm volatile("red.global.add.v4.f32 [%0], {%1, %2, %3, %4};"
                 :: "l"((u64)(uintptr_t)p), "f"(a), "f"(b), "f"(c), "f"(d) : "memory");
}
// mma.sync m16n8k16 fp16 -> f32, accumulate in place
__device__ __forceinline__ void mma16816h(float* c, const uint32_t* a,
                                          uint32_t b0, uint32_t b1) {
    asm volatile(
        "mma.sync.aligned.m16n8k16.row.col.f32.f16.f16.f32 "
        "{%0,%1,%2,%3}, {%4,%5,%6,%7}, {%8,%9}, {%0,%1,%2,%3};"
        : "+f"(c[0]), "+f"(c[1]), "+f"(c[2]), "+f"(c[3])
        : "r"(a[0]), "r"(a[1]), "r"(a[2]), "r"(a[3]), "r"(b0), "r"(b1));
}
__device__ __forceinline__ void ldsm_x4(uint32_t* r, uint32_t addr) {
    asm volatile("ldmatrix.sync.aligned.m8n8.x4.shared.b16 {%0,%1,%2,%3}, [%4];"
                 : "=r"(r[0]), "=r"(r[1]), "=r"(r[2]), "=r"(r[3]) : "r"(addr));
}
__device__ __forceinline__ uint32_t h2pack(float a0, float a1) {
    __half2 h = __floats2half2_rn(a0, a1);
    return *(uint32_t*)&h;
}

// ======================= merged precompute =================================
__global__ void prep_all(const float* __restrict__ e1W2, const float* __restrict__ e1b2,
                         const float* __restrict__ n1W,  const float* __restrict__ n1b,
                         const float* __restrict__ e2W2, const float* __restrict__ e2b2,
                         const float* __restrict__ n2W,  const float* __restrict__ n2b,
                         const float* __restrict__ muW,  const float* __restrict__ mub,
                         const float* __restrict__ lvW,  const float* __restrict__ lvb,
                         const float* __restrict__ e1W1, const float* __restrict__ e1b1,
                         const float* __restrict__ e2W1, const float* __restrict__ e2b1,
                         float* __restrict__ B1, float* __restrict__ c1,
                         float* __restrict__ B2, float* __restrict__ c2,
                         float* __restrict__ B3, float* __restrict__ b3,
                         __half* __restrict__ bth, __half* __restrict__ btl,
                         float* __restrict__ bias) {
    const int task = blockIdx.y, bx = blockIdx.x, tid = threadIdx.x;
    if (task <= 1) {
        const float* eW2 = task ? e2W2 : e1W2;
        const float* eb2 = task ? e2b2 : e1b2;
        const float* nW  = task ? n2W  : n1W;
        const float* nb  = task ? n2b  : n1b;
        float* Bcat = task ? B2 : B1;
        float* c = task ? c2 : c1;
        int k = bx, j = tid;
        Bcat[k * 128 + j] = nW[k * 128 + j];
        float acc = 0.f;
        #pragma unroll 4
        for (int t = 0; t < 128; t++) acc += eW2[k * 128 + t] * nW[(128 + t) * 128 + j];
        Bcat[(128 + k) * 128 + j] = acc;
        if (k == 0) {
            float cc = nb[j];
            #pragma unroll 4
            for (int t = 0; t < 128; t++) cc += eb2[t] * nW[(128 + t) * 128 + j];
            c[j] = cc;
        }
    } else if (task == 2) {
        int k = bx, j = tid;
        B3[k * 128 + j] = (j < 64) ? muW[k * 64 + j] : lvW[k * 64 + (j - 64)];
        if (k == 0) b3[j] = (j < 64) ? mub[j] : lvb[j - 64];
    } else {
        int k = tid & 63, half = tid >> 6;
        int n = bx + half * 128;
        float w = (n < 128) ? e1W1[k * 128 + n] : e2W1[k * 128 + (n - 128)];
        __half h = __float2half_rn(w);
        bth[n * 64 + k] = h;
        btl[n * 64 + k] = __float2half_rn(w - __half2float(h));
        if (k == 0) bias[n] = (n < 128) ? e1b1[n] : e2b1[n - 128];
    }
}

// node-B transpose+split: Bt[n][k] = B[k][n], hi/lo fp16
__global__ void prep_btn(const float* __restrict__ B1, const float* __restrict__ B2,
                         const float* __restrict__ B3,
                         __half* __restrict__ b1h, __half* __restrict__ b1l,
                         __half* __restrict__ b2h, __half* __restrict__ b2l,
                         __half* __restrict__ b3h, __half* __restrict__ b3l) {
    const int task = blockIdx.y, n = blockIdx.x, k = threadIdx.x;
    const int KT = (task == 2) ? 128 : 256;
    if (k >= KT) return;
    const float* B = (task == 0) ? B1 : (task == 1) ? B2 : B3;
    __half* bh = (task == 0) ? b1h : (task == 1) ? b2h : b3h;
    __half* bl = (task == 0) ? b1l : (task == 1) ? b2l : b3l;
    float w = B[k * 128 + n];
    __half h = __float2half_rn(w);
    bh[n * KT + k] = h;
    bl[n * KT + k] = __float2half_rn(w - __half2float(h));
}

__global__ void deg_kernel(const int* __restrict__ dst, float* __restrict__ deg, int E) {
    int e = blockIdx.x * blockDim.x + threadIdx.x;
    if (e < E) atomicAdd(&deg[dst[e]], 1.0f);
}

// ======================= mma.sync edge pass ================================
// 128-thread CTA (4 warps), tile = 128 edges x 256 cols (BOTH layers), K=64.
// Warp w owns concat cols [64w, 64w+64): warps 0-1 -> S1, 2-3 -> S2.
// A single fp16 buffer; B hi/lo fp16 frags (8 n-groups) in 128 regs.
// D = A*(Bh) + A*(Bl): 2 MMAs per (mt,kt,nt).
#define APITCH 144

__global__ __launch_bounds__(128, 2)
void edge_mma_kernel(const float* __restrict__ ea, const int* __restrict__ dstv,
                     const __half* __restrict__ Bth,
                     const __half* __restrict__ Btl,
                     const float* __restrict__ biascat,
                     float* __restrict__ S1, float* __restrict__ S2,
                     int E, int ntiles) {
    __shared__ __align__(16) char sA[128 * APITCH];  // fp16 A tile
    __shared__ float sBias[256];
    __shared__ int sDst[128];

    const int tid = threadIdx.x, wid = tid >> 5, lane = tid & 31;
    const int g = lane >> 2, q = lane & 3;
    const int colbase = wid * 64;            // in 256-concat
    const int layer = wid >> 1;
    const int lcolbase = colbase - layer * 128;  // in-layer col base (0 or 64)
    float* Sbase = layer ? S2 : S1;

    sBias[tid] = biascat[tid];
    sBias[tid + 128] = biascat[tid + 128];

    // ---- B fragments in registers: 8 n-groups, hi+lo fp16 ----
    uint32_t bh[8][4][2], bl[8][4][2];
    {
        const uint32_t* BH = (const uint32_t*)Bth;
        const uint32_t* BL = (const uint32_t*)Btl;
        #pragma unroll
        for (int nt = 0; nt < 8; nt++) {
            const int n = colbase + nt * 8 + g;
            #pragma unroll
            for (int kt = 0; kt < 4; kt++) {
                const int base = n * 32 + kt * 8 + q;
                bh[nt][kt][0] = BH[base];
                bh[nt][kt][1] = BH[base + 4];
                bl[nt][kt][0] = BL[base];
                bl[nt][kt][1] = BL[base + 4];
            }
        }
    }

    const int rowoff = (lane & 7) + ((lane >> 3) & 1) * 8;
    const int koff = (lane >> 4) * 16;
    const uint32_t sA_u = smem_u32(sA);
    const uint32_t lmBase = (uint32_t)(rowoff * APITCH + koff);

    for (int tile = blockIdx.x; tile < ntiles; tile += gridDim.x) {
        const int e0 = tile * 128;
        // ---- stage A tile once as fp16 (conflict-free STS.128) ----
        {
            const int ge = e0 + tid;
            uint4* a4 = (uint4*)(sA + tid * APITCH);
            if (ge < E) {
                const float4* src = (const float4*)(ea + (size_t)ge * 64);
                #pragma unroll
                for (int j = 0; j < 8; j++) {
                    float4 v0 = src[j * 2], v1 = src[j * 2 + 1];
                    a4[j] = make_uint4(h2pack(v0.x, v0.y), h2pack(v0.z, v0.w),
                                       h2pack(v1.x, v1.y), h2pack(v1.z, v1.w));
                }
                sDst[tid] = dstv[ge];
            } else {
                const uint4 z = make_uint4(0, 0, 0, 0);
                #pragma unroll
                for (int j = 0; j < 8; j++) a4[j] = z;
                sDst[tid] = -1;
            }
        }
        __syncthreads();

        // ---- per-mt: 2-term MMA over 8 n-groups + immediate epilogue ----
        #pragma unroll
        for (int mt = 0; mt < 8; mt++) {
            float acc[8][4];
            #pragma unroll
            for (int nt = 0; nt < 8; nt++)
                #pragma unroll
                for (int i = 0; i < 4; i++) acc[nt][i] = 0.f;

            const uint32_t mtOff = (uint32_t)(mt * 16 * APITCH) + lmBase;
            #pragma unroll
            for (int kt = 0; kt < 4; kt++) {
                uint32_t a4[4];
                ldsm_x4(a4, sA_u + mtOff + kt * 32);
                #pragma unroll
                for (int nt = 0; nt < 8; nt++) {
                    mma16816h(acc[nt], a4, bh[nt][kt][0], bh[nt][kt][1]);
                    mma16816h(acc[nt], a4, bl[nt][kt][0], bl[nt][kt][1]);
                }
            }

            const int rowLo = mt * 16 + g;
            const int dLo = sDst[rowLo], dHi = sDst[rowLo + 8];
            #pragma unroll
            for (int nt = 0; nt < 8; nt++) {
                float* c = acc[nt];
                const int col = colbase + nt * 8 + q * 2;   // concat col (bias)
                const float b0 = sBias[col], b1 = sBias[col + 1];
                float v0 = lk(c[0] + b0), v1 = lk(c[1] + b1);
                float v2 = lk(c[2] + b0), v3 = lk(c[3] + b1);
                float r0 = __shfl_xor_sync(0xffffffffu, v0, 1);
                float r1 = __shfl_xor_sync(0xffffffffu, v1, 1);
                float r2 = __shfl_xor_sync(0xffffffffu, v2, 1);
                float r3 = __shfl_xor_sync(0xffffffffu, v3, 1);
                const int colb = lcolbase + nt * 8 + (q >> 1) * 4;  // in-layer col
                int d;
                float w0, w1, w2, w3;
                if ((q & 1) == 0) { d = dLo; w0 = v0; w1 = v1; w2 = r0; w3 = r1; }
                else              { d = dHi; w0 = r2; w1 = r3; w2 = v2; w3 = v3; }
                if (d >= 0)
                    red4(&Sbase[(size_t)d * 128 + colb], w0, w1, w2, w3);
            }
        }
        __syncthreads();
    }
}

// ======================= tensor node GEMM (fp16 2-term) ====================
// A staged fp16 single buffer; B hi/lo fp16 staged per chunk.
#define NSM_A 0
#define NSM_BH 18432
#define NSM_BL 36864
#define NSM_BIAS 55296
#define NSM_DEG 55808
#define NODE_SMEM 56320

template <int KTOT, bool SECOND, bool DOLEAKY, bool SPLIT>
__global__ __launch_bounds__(256, 1) void node_mma(
    const float* __restrict__ A1, const float* __restrict__ A2,
    const __half* __restrict__ Bth, const __half* __restrict__ Btl,
    const float* __restrict__ bias, const float* __restrict__ deg,
    float* __restrict__ out, int N) {
    extern __shared__ __align__(16) char smem[];
    char* sA = smem + NSM_A;
    char* sBh = smem + NSM_BH;
    char* sBl = smem + NSM_BL;
    float* sBias = (float*)(smem + NSM_BIAS);
    float* sDeg = (float*)(smem + NSM_DEG);

    const int tid = threadIdx.x, wid = tid >> 5, lane = tid & 31;
    const int g = lane >> 2, q = lane & 3;
    const int mhalf = wid >> 2;
    const int n0 = (wid & 3) * 32;
    const int row0 = blockIdx.x * 128;

    if (tid < 128) {
        sBias[tid] = bias[tid];
        if (SECOND) {
            int r = row0 + tid;
            sDeg[tid] = (r < N) ? deg[r] : 0.f;
        }
    }
    __syncthreads();

    float acc[4][4][4];
    #pragma unroll
    for (int mt = 0; mt < 4; mt++) {
        const int rl = mhalf * 64 + mt * 16 + g;
        const float d0 = SECOND ? sDeg[rl] : 1.f;
        const float d1 = SECOND ? sDeg[rl + 8] : 1.f;
        #pragma unroll
        for (int nt = 0; nt < 4; nt++) {
            const int col = n0 + nt * 8 + 2 * q;
            const float b0 = sBias[col], b1 = sBias[col + 1];
            acc[mt][nt][0] = d0 * b0;
            acc[mt][nt][1] = d0 * b1;
            acc[mt][nt][2] = d1 * b0;
            acc[mt][nt][3] = d1 * b1;
        }
    }

    const int rowoff = (lane & 7) + ((lane >> 3) & 1) * 8;
    const uint32_t sA_u = smem_u32(sA);
    const uint32_t sBh_u = smem_u32(sBh);
    const uint32_t sBl_u = smem_u32(sBl);
    const uint32_t aBase = (uint32_t)((mhalf * 64 + rowoff) * APITCH + (lane >> 4) * 16);
    const uint32_t bBase = (uint32_t)((n0 + (lane & 7)) * APITCH + ((lane >> 3) & 3) * 16);

    for (int kc = 0; kc < KTOT; kc += 64) {
        __syncthreads();
        // ---- stage A chunk as fp16 (conflict-free STS.128) ----
        {
            const int row = tid >> 1, hf = tid & 1;
            const int grow = row0 + row;
            uint4* a4 = (uint4*)(sA + row * APITCH + hf * 64);
            if (grow < N) {
                const bool a1part = (!SECOND) || (kc < 128);
                const int ksrc = (a1part ? kc : kc - 128) + hf * 32;
                const float* Arow = (a1part ? A1 : A2) + (size_t)grow * 128 + ksrc;
                const float s = (SECOND && a1part) ? sDeg[row] : 1.f;
                const float4* src = (const float4*)Arow;
                #pragma unroll
                for (int j = 0; j < 4; j++) {
                    float4 v0 = src[j * 2], v1 = src[j * 2 + 1];
                    v0.x *= s; v0.y *= s; v0.z *= s; v0.w *= s;
                    v1.x *= s; v1.y *= s; v1.z *= s; v1.w *= s;
                    a4[j] = make_uint4(h2pack(v0.x, v0.y), h2pack(v0.z, v0.w),
                                       h2pack(v1.x, v1.y), h2pack(v1.z, v1.w));
                }
            } else {
                const uint4 z = make_uint4(0, 0, 0, 0);
                #pragma unroll
                for (int j = 0; j < 4; j++) a4[j] = z;
            }
        }
        // ---- stage B chunk (pre-split fp16): 64 bytes per (n, half) ----
        {
            const int n = tid >> 1, hf = tid & 1;
            const uint4* bh4 = (const uint4*)(Bth + (size_t)n * KTOT + kc + hf * 32);
            const uint4* bl4 = (const uint4*)(Btl + (size_t)n * KTOT + kc + hf * 32);
            uint4* dh = (uint4*)(sBh + n * APITCH + hf * 64);
            uint4* dl = (uint4*)(sBl + n * APITCH + hf * 64);
            dh[0] = bh4[0]; dh[1] = bh4[1]; dh[2] = bh4[2]; dh[3] = bh4[3];
            dl[0] = bl4[0]; dl[1] = bl4[1]; dl[2] = bl4[2]; dl[3] = bl4[3];
        }
        __syncthreads();

        // ---- MMA: 2 terms ----
        #pragma unroll
        for (int ktp = 0; ktp < 2; ktp++) {
            uint32_t bhf[4][4], blf[4][4];
            #pragma unroll
            for (int nt = 0; nt < 4; nt++) {
                ldsm_x4(bhf[nt], sBh_u + bBase + (uint32_t)(nt * 8 * APITCH) + ktp * 64);
                ldsm_x4(blf[nt], sBl_u + bBase + (uint32_t)(nt * 8 * APITCH) + ktp * 64);
            }
            #pragma unroll
            for (int mt = 0; mt < 4; mt++) {
                #pragma unroll
                for (int kt2 = 0; kt2 < 2; kt2++) {
                    uint32_t a4[4];
                    const uint32_t ao = aBase + (uint32_t)(mt * 16 * APITCH) +
                                        ktp * 64 + kt2 * 32;
                    ldsm_x4(a4, sA_u + ao);
                    #pragma unroll
                    for (int nt = 0; nt < 4; nt++) {
                        mma16816h(acc[mt][nt], a4, bhf[nt][kt2 * 2], bhf[nt][kt2 * 2 + 1]);
                        mma16816h(acc[mt][nt], a4, blf[nt][kt2 * 2], blf[nt][kt2 * 2 + 1]);
                    }
                }
            }
        }
    }

    // ---- epilogue ----
    #pragma unroll
    for (int mt = 0; mt < 4; mt++) {
        const int r0g = row0 + mhalf * 64 + mt * 16 + g;
        #pragma unroll
        for (int nt = 0; nt < 4; nt++) {
            float* c = acc[mt][nt];
            const int col = n0 + nt * 8 + 2 * q;
            float v0 = c[0], v1 = c[1], v2 = c[2], v3 = c[3];
            if (DOLEAKY) { v0 = lk(v0); v1 = lk(v1); v2 = lk(v2); v3 = lk(v3); }
            if (!SPLIT) {
                if (r0g < N)     *(float2*)&out[(size_t)r0g * 128 + col] = make_float2(v0, v1);
                if (r0g + 8 < N) *(float2*)&out[(size_t)(r0g + 8) * 128 + col] = make_float2(v2, v3);
            } else {
                float* dstp = (col < 64) ? (out + (size_t)0 * 64)
                                         : (out + (size_t)N * 64 - 64);
                if (r0g < N)     *(float2*)&dstp[(size_t)r0g * 64 + col] = make_float2(v0, v1);
                if (r0g + 8 < N) *(float2*)&dstp[(size_t)(r0g + 8) * 64 + col] = make_float2(v2, v3);
            }
        }
    }
}

// ---------------------------------------------------------------------------
extern "C" void kernel_launch(void* const* d_in, const int* in_sizes, int n_in,
                              void* d_out, int out_size) {
    const float* x    = (const float*)d_in[0];
    const int*   ei   = (const int*)d_in[1];
    const float* ea   = (const float*)d_in[2];
    const float* e1W1 = (const float*)d_in[3];
    const float* e1b1 = (const float*)d_in[4];
    const float* e1W2 = (const float*)d_in[5];
    const float* e1b2 = (const float*)d_in[6];
    const float* n1W  = (const float*)d_in[7];
    const float* n1b  = (const float*)d_in[8];
    const float* e2W1 = (const float*)d_in[9];
    const float* e2b1 = (const float*)d_in[10];
    const float* e2W2 = (const float*)d_in[11];
    const float* e2b2 = (const float*)d_in[12];
    const float* n2W  = (const float*)d_in[13];
    const float* n2b  = (const float*)d_in[14];
    const float* muW  = (const float*)d_in[15];
    const float* mub  = (const float*)d_in[16];
    const float* lvW  = (const float*)d_in[17];
    const float* lvb  = (const float*)d_in[18];

    const int N = in_sizes[0] / 128;  // 50000
    const int E = in_sizes[2] / 64;   // 640000
    const int* dst = ei + E;          // edge_index row 1

    float *S1, *S2, *h1, *h2, *dg, *B1, *B2, *c1, *c2, *B3, *b3, *biascat;
    __half *Bth, *Btl, *B1th, *B1tl, *B2th, *B2tl, *B3th, *B3tl;
    cudaGetSymbolAddress((void**)&S1, g_S1);
    cudaGetSymbolAddress((void**)&S2, g_S2);
    cudaGetSymbolAddress((void**)&h1, g_h1);
    cudaGetSymbolAddress((void**)&h2, g_h2);
    cudaGetSymbolAddress((void**)&dg, g_deg);
    cudaGetSymbolAddress((void**)&B1, g_B1);
    cudaGetSymbolAddress((void**)&B2, g_B2);
    cudaGetSymbolAddress((void**)&c1, g_c1);
    cudaGetSymbolAddress((void**)&c2, g_c2);
    cudaGetSymbolAddress((void**)&B3, g_B3);
    cudaGetSymbolAddress((void**)&b3, g_b3);
    cudaGetSymbolAddress((void**)&Bth, g_Bth);
    cudaGetSymbolAddress((void**)&Btl, g_Btl);
    cudaGetSymbolAddress((void**)&biascat, g_biascat);
    cudaGetSymbolAddress((void**)&B1th, g_B1th);
    cudaGetSymbolAddress((void**)&B1tl, g_B1tl);
    cudaGetSymbolAddress((void**)&B2th, g_B2th);
    cudaGetSymbolAddress((void**)&B2tl, g_B2tl);
    cudaGetSymbolAddress((void**)&B3th, g_B3th);
    cudaGetSymbolAddress((void**)&B3tl, g_B3tl);

    cudaMemsetAsync(S1, 0, (size_t)N * 128 * sizeof(float));
    cudaMemsetAsync(S2, 0, (size_t)N * 128 * sizeof(float));
    cudaMemsetAsync(dg, 0, (size_t)N * sizeof(float));

    prep_all<<<dim3(128, 4), 128>>>(e1W2, e1b2, n1W, n1b,
                                    e2W2, e2b2, n2W, n2b,
                                    muW, mub, lvW, lvb,
                                    e1W1, e1b1, e2W1, e2b1,
                                    B1, c1, B2, c2, B3, b3, Bth, Btl, biascat);
    prep_btn<<<dim3(128, 3), 256>>>(B1, B2, B3, B1th, B1tl, B2th, B2tl, B3th, B3tl);
    deg_kernel<<<(E + 255) / 256, 256>>>(dst, dg, E);

    int ntiles = (E + 127) / 128;
    edge_mma_kernel<<<296, 128>>>(ea, dst, Bth, Btl, biascat, S1, S2, E, ntiles);

    int nblk = (N + 127) / 128;  // 391
    cudaFuncSetAttribute(node_mma<256, true, true, false>,
                         cudaFuncAttributeMaxDynamicSharedMemorySize, NODE_SMEM);
    cudaFuncSetAttribute(node_mma<128, false, false, true>,
                         cudaFuncAttributeMaxDynamicSharedMemorySize, NODE_SMEM);

    node_mma<256, true, true, false><<<nblk, 256, NODE_SMEM>>>(x,  S1, B1th, B1tl, c1, dg, h1, N);
    node_mma<256, true, true, false><<<nblk, 256, NODE_SMEM>>>(h1, S2, B2th, B2tl, c2, dg, h2, N);
    node_mma<128, false, false, true><<<nblk, 256, NODE_SMEM>>>(h2, nullptr, B3th, B3tl, b3,
                                                                nullptr, (float*)d_out, N);
}